// round 10
// baseline (speedup 1.0000x reference)
#include <cuda_runtime.h>
#include <cuda_fp16.h>
#include <stdint.h>

#define D 128
#define DPAD 132

static __device__ float g_A [46792704];
static __device__ float g_B [46792704];
static __device__ float g_C [46792704];
static __device__ float g_A2[ 2752512];
static __device__ float g_B2[ 2752512];
static __device__ float g_C2[ 2752512];
static __device__ float g_acc [18*256];
static __device__ float g_fold[19*256];
static __device__ float g_wT  [884736];
static __device__ uint2 g_wf  [98304];

__global__ void init_kernel(float* acc, float* foldId) {
    int t = blockIdx.x * blockDim.x + threadIdx.x;
    if (t < 18*256) acc[t] = 0.f;
    if (t < 128) { foldId[t] = 1.f; foldId[128 + t] = 0.f; }
}

__global__ void transpose_kernel(const float* __restrict__ src, float* __restrict__ dst,
                                 int R, int C, int total) {
    int idx = blockIdx.x * blockDim.x + threadIdx.x;
    if (idx >= total) return;
    int m = idx / (R * C), rc = idx - m * (R * C), cc = rc / R, r = rc - cc * R;
    dst[idx] = src[m * R * C + r * C + cc];
}

__global__ void prep_frag(const float* __restrict__ W, uint2* __restrict__ out,
                          int NT, int K, int total) {
    int idx = blockIdx.x * blockDim.x + threadIdx.x;
    if (idx >= total) return;
    int lane = idx & 31, tile = idx >> 5;
    int nt = tile % NT, kt = tile / NT;
    int g = lane >> 2, t = lane & 3;
    const float* w = W + (size_t)(nt * 8 + g) * K + kt * 16 + 2 * t;
    __half2 b0 = __floats2half2_rn(w[0], w[1]);
    __half2 b1 = __floats2half2_rn(w[8], w[9]);
    uint2 o; o.x = *(uint32_t*)&b0; o.y = *(uint32_t*)&b1;
    out[idx] = o;
}

__global__ void embed_kernel(const float* __restrict__ poses, const float* __restrict__ ew,
                             const float* __restrict__ eb, float* __restrict__ out, int total) {
    int idx = blockIdx.x * blockDim.x + threadIdx.x;
    if (idx >= total) return;
    int row = idx >> 7, c = idx & 127;
    float v = fmaf(poses[row*2], ew[2*c], fmaf(poses[row*2+1], ew[2*c+1], eb[c]));
    out[idx] = v > 0.f ? v : 0.01f * v;
}

__global__ void finalize_kernel(const float* __restrict__ acc, float invN,
                                const float* g0, const float* b0, float* f0,
                                const float* g1, const float* b1, float* f1) {
    int set = blockIdx.x, c = threadIdx.x;
    const float* a  = acc + set * 256;
    const float* gg = set ? g1 : g0;
    const float* bb = set ? b1 : b0;
    float* ff = set ? f1 : f0;
    float m = a[c] * invN;
    float v = fmaxf(a[128 + c] * invN - m * m, 0.f);
    float sc = rsqrtf(v + 1e-5f) * gg[c];
    ff[c] = sc;
    ff[128 + c] = fmaf(-m, sc, bb[c]);
}

__global__ void pool1_kernel(const float* __restrict__ hin, const float* __restrict__ fold,
                             float* __restrict__ out, int total) {
    int idx = blockIdx.x * blockDim.x + threadIdx.x;
    if (idx >= total) return;
    int orow = idx >> 7, c = idx & 127;
    const float* base = hin + (size_t)orow * 17 * D + c;
    float s = 0.f;
    #pragma unroll
    for (int j = 0; j < 17; ++j) s += base[j * D];
    out[idx] = fmaf(s * (1.f / 17.f), fold[c], fold[128 + c]);
}

__global__ void pool2_cls_kernel(const float* __restrict__ hin, const float* __restrict__ fold,
                                 const float* __restrict__ cw, const float* __restrict__ cb,
                                 float* __restrict__ out) {
    __shared__ float p_s[D];
    int b = blockIdx.x, c = threadIdx.x;
    const float* base = hin + (size_t)b * 84 * D + c;
    float s = 0.f;
    #pragma unroll 4
    for (int r = 0; r < 84; ++r) s += base[r * D];
    p_s[c] = fmaf(s * (1.f / 84.f), fold[c], fold[128 + c]);
    __syncthreads();
    if (c < 8) {
        float acc = cb[c];
        #pragma unroll 4
        for (int k = 0; k < D; ++k) acc = fmaf(p_s[k], cw[c * D + k], acc);
        out[b * 8 + c] = acc;
    }
}

__device__ __forceinline__ void mma16816(float* c, uint32_t a0, uint32_t a1,
                                         uint32_t a2, uint32_t a3, uint32_t b0, uint32_t b1) {
    asm("mma.sync.aligned.m16n8k16.row.col.f32.f16.f16.f32 "
        "{%0,%1,%2,%3},{%4,%5,%6,%7},{%8,%9},{%0,%1,%2,%3};"
        : "+f"(c[0]), "+f"(c[1]), "+f"(c[2]), "+f"(c[3])
        : "r"(a0), "r"(a1), "r"(a2), "r"(a3), "r"(b0), "r"(b1));
}

template<int KT, int NT>
__device__ __forceinline__ void mtile(const __half* a0p, int lda, const uint2* __restrict__ wf,
                                      int ng, int lane, float acc[4][4]) {
    const __half* a1p = a0p + 8 * lda;
    #pragma unroll
    for (int kt = 0; kt < KT; ++kt) {
        uint32_t a0 = *(const uint32_t*)(a0p + kt*16);
        uint32_t a1 = *(const uint32_t*)(a1p + kt*16);
        uint32_t a2 = *(const uint32_t*)(a0p + kt*16 + 8);
        uint32_t a3 = *(const uint32_t*)(a1p + kt*16 + 8);
        #pragma unroll
        for (int j = 0; j < 4; ++j) {
            uint2 b = wf[(kt*NT + ng*4 + j)*32 + lane];
            mma16816(acc[j], a0, a1, a2, a3, b.x, b.y);
        }
    }
}

// ---------------- stage-1 tensor kernels: 1 graph (17 rows), 3 CTAs/SM -----
#define O_H16 0
#define O_Q16 8704
#define O_K16 17408
#define O_VT  26112
#define O_P   34816
#define O_SC  43520
#define O_MB  50320
#define O_H32 52368
#define SM1   61344

__global__ __launch_bounds__(256, 3)
void k1_s1(const float* __restrict__ hin, const float* __restrict__ foldIn,
           float* __restrict__ gcnb, float* __restrict__ t2, float* __restrict__ accL,
           const float* __restrict__ gwT, const float* __restrict__ gb,
           const float* __restrict__ qb, const float* __restrict__ ob,
           const uint2* __restrict__ qkvf, const uint2* __restrict__ owf) {
    extern __shared__ char sm[];
    __half (*h16)[136] = (__half(*)[136])(sm + O_H16);   // [32][136]
    __half (*q16)[136] = (__half(*)[136])(sm + O_Q16);   // [32][136]
    __half (*k16)[136] = (__half(*)[136])(sm + O_K16);   // [32][136]
    __half (*vT )[34]  = (__half(*)[34]) (sm + O_VT);    // [128][34]
    __half (*pp )[34]  = (__half(*)[34]) (sm + O_P);     // [4*32][34]
    float  (*sc )[25]  = (float(*)[25])  (sm + O_SC);    // [68][25]
    float*  mbuf       = (float*)(sm + O_MB);            // 512 floats
    float  (*h32)[132] = (float(*)[132]) (sm + O_H32);   // [17][132]

    const int tid = threadIdx.x, warp = tid >> 5, lane = tid & 31;
    const int g = lane >> 2, t = lane & 3;
    const int colj = tid & 127;
    const float* hg = hin + (size_t)blockIdx.x * 2176;
    float* t2g = t2 + (size_t)blockIdx.x * 2176;
    const float scIn = foldIn[colj], shIn = foldIn[128 + colj];

    { // zero vT+pp (contiguous 17408B) + h16 pad rows 17-31; load h32+h16
        uint32_t* z = (uint32_t*)(sm + O_VT);
        for (int i = tid; i < 4352; i += 256) z[i] = 0;
        uint32_t* zh = (uint32_t*)&h16[17][0];
        for (int i = tid; i < 1020; i += 256) zh[i] = 0;
        for (int i = tid; i < 2176; i += 256) {
            int rr = i >> 7;
            float v = fmaf(hg[i], scIn, shIn);
            h32[rr][colj] = v;
            h16[rr][colj] = __float2half_rn(v);
        }
    }
    __syncthreads();
    if (tid < 128) { // node mean over 17 rows
        float s = 0.f;
        #pragma unroll
        for (int r = 0; r < 17; ++r) s += h32[r][tid];
        mbuf[tid] = s * (1.f / 17.f);
    }
    __syncthreads();
    if (tid < 128) { // GCN rank-1 -> smem + tiny global buffer
        float a = gb[tid];
        #pragma unroll 4
        for (int k = 0; k < 128; ++k) a = fmaf(mbuf[k], gwT[k*128 + tid], a);
        mbuf[128 + tid] = a;
        gcnb[(size_t)blockIdx.x * 128 + tid] = a;
    }
    __syncthreads();
    { // t1 stats (t1 never materialized; column-aligned)
        float s1 = 0.f, q1 = 0.f;
        for (int i = tid; i < 2176; i += 256) {
            float v = mbuf[128 + colj] + h32[i >> 7][colj];
            s1 += v; q1 = fmaf(v, v, q1);
        }
        float* red = (float*)sc;
        red[tid] = s1; red[256 + tid] = q1;
    }
    __syncthreads();
    if (tid < 128) {
        float* red = (float*)sc;
        atomicAdd(&accL[tid],       red[tid] + red[tid + 128]);
        atomicAdd(&accL[128 + tid], red[256 + tid] + red[384 + tid]);
    }
    // qkv: M=32, N=384, K=128 -> 24 items
    for (int item = warp; item < 24; item += 8) {
        int mt = item / 12, ng = item % 12, m0 = mt * 16;
        float acc[4][4] = {};
        mtile<8,48>(&h16[m0 + g][2*t], 136, qkvf, ng, lane, acc);
        int r0 = m0 + g, r1 = r0 + 8;
        #pragma unroll
        for (int j = 0; j < 4; ++j) {
            int nc = ng*32 + j*8 + 2*t;
            float b0 = qb[nc], b1 = qb[nc+1];
            float v00 = acc[j][0]+b0, v01 = acc[j][1]+b1, v10 = acc[j][2]+b0, v11 = acc[j][3]+b1;
            if (nc < 128) {
                *(__half2*)&q16[r0][nc] = __floats2half2_rn(v00, v01);
                *(__half2*)&q16[r1][nc] = __floats2half2_rn(v10, v11);
            } else if (nc < 256) {
                *(__half2*)&k16[r0][nc-128] = __floats2half2_rn(v00, v01);
                *(__half2*)&k16[r1][nc-128] = __floats2half2_rn(v10, v11);
            } else {
                int d = nc - 256;
                if (r0 < 17) { vT[d][r0] = __float2half_rn(v00); vT[d+1][r0] = __float2half_rn(v01); }
                if (r1 < 17) { vT[d][r1] = __float2half_rn(v10); vT[d+1][r1] = __float2half_rn(v11); }
            }
        }
    }
    __syncthreads();
    // scores: 4 heads x 2 mt x 3 nt = 24 items
    for (int item = warp; item < 24; item += 8) {
        int hh = item / 6, r2 = item % 6, mt = r2 / 3, nt = r2 % 3;
        float acc[4] = {};
        const __half* a0p = &q16[mt*16 + g][hh*32 + 2*t];
        const __half* a1p = a0p + 8*136;
        const __half* br  = &k16[nt*8 + g][hh*32 + 2*t];
        #pragma unroll
        for (int kt = 0; kt < 2; ++kt) {
            mma16816(acc, *(const uint32_t*)(a0p+kt*16), *(const uint32_t*)(a1p+kt*16),
                     *(const uint32_t*)(a0p+kt*16+8), *(const uint32_t*)(a1p+kt*16+8),
                     *(const uint32_t*)(br+kt*16), *(const uint32_t*)(br+kt*16+8));
        }
        const float invs = 0.17677669529663687f;
        int q0 = mt*16 + g, ss = nt*8 + 2*t, row = hh*17;
        if (q0 < 17)     { sc[row+q0][ss]   = acc[0]*invs; sc[row+q0][ss+1]   = acc[1]*invs; }
        if (q0 + 8 < 17) { sc[row+q0+8][ss] = acc[2]*invs; sc[row+q0+8][ss+1] = acc[3]*invs; }
    }
    __syncthreads();
    for (int idx = tid; idx < 68; idx += 256) { // softmax -> fp16 probs
        int hh = idx / 17, q = idx - hh*17;
        float e[17], mx = -1e30f;
        #pragma unroll
        for (int s = 0; s < 17; ++s) mx = fmaxf(mx, sc[hh*17+q][s]);
        float sum = 0.f;
        #pragma unroll
        for (int s = 0; s < 17; ++s) { e[s] = __expf(sc[hh*17+q][s] - mx); sum += e[s]; }
        float inv = 1.f / sum;
        #pragma unroll
        for (int s = 0; s < 17; ++s) pp[hh*32 + q][s] = __float2half_rn(e[s] * inv);
    }
    __syncthreads();
    // attn @ V -> q16 (reuse): 4 heads x 2 mt = 8 items
    for (int item = warp; item < 8; item += 8) {
        int hh = item / 2, mt = item % 2;
        float acc[4][4] = {};
        const __half* a0p = &pp[hh*32 + mt*16 + g][2*t];
        const __half* a1p = a0p + 8*34;
        #pragma unroll
        for (int kt = 0; kt < 2; ++kt) {
            uint32_t a0 = *(const uint32_t*)(a0p+kt*16), a1 = *(const uint32_t*)(a1p+kt*16);
            uint32_t a2 = *(const uint32_t*)(a0p+kt*16+8), a3 = *(const uint32_t*)(a1p+kt*16+8);
            #pragma unroll
            for (int j = 0; j < 4; ++j) {
                const __half* bp = &vT[hh*32 + j*8 + g][kt*16 + 2*t];
                mma16816(acc[j], a0, a1, a2, a3, *(const uint32_t*)bp, *(const uint32_t*)(bp+8));
            }
        }
        int q0 = mt*16 + g;
        #pragma unroll
        for (int j = 0; j < 4; ++j) {
            int col = hh*32 + j*8 + 2*t;
            if (q0 < 17)     *(__half2*)&q16[q0][col]   = __floats2half2_rn(acc[j][0], acc[j][1]);
            if (q0 + 8 < 17) *(__half2*)&q16[q0+8][col] = __floats2half2_rn(acc[j][2], acc[j][3]);
        }
    }
    __syncthreads();
    // out-proj + residual -> t2 (global) AND back into h32 (stats): 8 items
    for (int item = warp; item < 8; item += 8) {
        int mt = item / 4, ng = item % 4, m0 = mt * 16;
        float acc[4][4] = {};
        mtile<8,16>(&q16[m0 + g][2*t], 136, owf, ng, lane, acc);
        int r0 = m0 + g, r1 = r0 + 8;
        #pragma unroll
        for (int j = 0; j < 4; ++j) {
            int nc = ng*32 + j*8 + 2*t;
            float b0 = ob[nc], b1 = ob[nc+1];
            if (r0 < 17) {
                float v0 = acc[j][0] + b0 + h32[r0][nc];
                float v1 = acc[j][1] + b1 + h32[r0][nc+1];
                t2g[r0*128+nc] = v0; t2g[r0*128+nc+1] = v1;
                h32[r0][nc] = v0; h32[r0][nc+1] = v1;
            }
            if (r1 < 17) {
                float v0 = acc[j][2] + b0 + h32[r1][nc];
                float v1 = acc[j][3] + b1 + h32[r1][nc+1];
                t2g[r1*128+nc] = v0; t2g[r1*128+nc+1] = v1;
                h32[r1][nc] = v0; h32[r1][nc+1] = v1;
            }
        }
    }
    __syncthreads();
    { // t2 stats, column-aligned from smem
        float s2 = 0.f, q2 = 0.f;
        for (int i = tid; i < 2176; i += 256) {
            float v = h32[i >> 7][colj];
            s2 += v; q2 = fmaf(v, v, q2);
        }
        mbuf[tid] = s2; mbuf[256 + tid] = q2;
        __syncthreads();
        if (tid < 128) {
            atomicAdd(&accL[256 + tid], mbuf[tid] + mbuf[tid + 128]);
            atomicAdd(&accL[384 + tid], mbuf[256 + tid] + mbuf[384 + tid]);
        }
    }
}

// 2 graphs (34 rows) per block, 3 CTAs/SM
#define P_O16 0
#define P_U16 13056
#define P_O32 38400
#define P_GB  56352
#define SM2   57376

__global__ __launch_bounds__(256, 3)
void k2_s1(const float* __restrict__ hg0, const float* __restrict__ gcnb,
           const float* __restrict__ t2, const float* __restrict__ foldIn,
           const float* __restrict__ fold1, const float* __restrict__ fold2,
           float* __restrict__ hout, float* __restrict__ accL,
           const uint2* __restrict__ w1f, const float* __restrict__ b1v,
           const uint2* __restrict__ w2f, const float* __restrict__ b2v) {
    extern __shared__ char sm[];
    __half (*o16)[136] = (__half(*)[136])(sm + P_O16);   // [48][136]
    __half (*u16)[264] = (__half(*)[264])(sm + P_U16);   // [48][264]
    float  (*o32)[132] = (float(*)[132]) (sm + P_O32);   // [34][132]
    float*  gbuf       = (float*)(sm + P_GB);            // 256 floats
    const int tid = threadIdx.x, warp = tid >> 5, lane = tid & 31;
    const int g = lane >> 2, t = lane & 3;
    const int colj = tid & 127;
    const float* hgA = hg0 + (size_t)blockIdx.x * 4352;
    const float* t2g = t2  + (size_t)blockIdx.x * 4352;
    float* og = hout + (size_t)blockIdx.x * 4352;
    const float scIn = foldIn[colj], shIn = foldIn[128 + colj];
    const float sc1 = fold1[colj], sh1 = fold1[128 + colj];
    const float sc2 = fold2[colj], sh2 = fold2[128 + colj];

    if (tid < 256) gbuf[tid] = gcnb[(size_t)blockIdx.x * 256 + tid];
    { // zero o16 pad rows 34-47
        uint32_t* zz = (uint32_t*)&o16[34][0];
        for (int i = tid; i < 952; i += 256) zz[i] = 0;
    }
    __syncthreads();
    // o = BN1(gcn + BN_in(h)) + BN2(t2)  -> o32 (fp32) + o16
    for (int i = tid; i < 4352; i += 256) {
        int rr = i >> 7;
        float t1v = gbuf[(rr/17)*128 + colj] + fmaf(hgA[i], scIn, shIn);
        float o = fmaf(t1v, sc1, sh1) + fmaf(t2g[i], sc2, sh2);
        o32[rr][colj] = o;
        o16[rr][colj] = __float2half_rn(o);
    }
    __syncthreads();
    // mlp1: M=48, N=256, K=128 (+ReLU): 3 x 8 = 24 items
    for (int item = warp; item < 24; item += 8) {
        int mt = item / 8, ng = item % 8, m0 = mt * 16;
        float acc[4][4] = {};
        mtile<8,32>(&o16[m0 + g][2*t], 136, w1f, ng, lane, acc);
        int r0 = m0 + g, r1 = r0 + 8;
        #pragma unroll
        for (int j = 0; j < 4; ++j) {
            int nc = ng*32 + j*8 + 2*t;
            float b0 = b1v[nc], b1 = b1v[nc+1];
            *(__half2*)&u16[r0][nc] = __floats2half2_rn(fmaxf(acc[j][0]+b0, 0.f), fmaxf(acc[j][1]+b1, 0.f));
            *(__half2*)&u16[r1][nc] = __floats2half2_rn(fmaxf(acc[j][2]+b0, 0.f), fmaxf(acc[j][3]+b1, 0.f));
        }
    }
    __syncthreads();
    // mlp2: M=48, N=128, K=256 + residual -> og AND o32 (stats): 3 x 4 = 12 items
    for (int item = warp; item < 12; item += 8) {
        int mt = item / 4, ng = item % 4, m0 = mt * 16;
        float acc[4][4] = {};
        mtile<16,16>(&u16[m0 + g][2*t], 264, w2f, ng, lane, acc);
        int r0 = m0 + g, r1 = r0 + 8;
        #pragma unroll
        for (int j = 0; j < 4; ++j) {
            int nc = ng*32 + j*8 + 2*t;
            float b0 = b2v[nc], b1 = b2v[nc+1];
            if (r0 < 34) {
                float v0 = acc[j][0] + b0 + o32[r0][nc];
                float v1 = acc[j][1] + b1 + o32[r0][nc+1];
                og[r0*128+nc] = v0; og[r0*128+nc+1] = v1;
                o32[r0][nc] = v0; o32[r0][nc+1] = v1;
            }
            if (r1 < 34) {
                float v0 = acc[j][2] + b0 + o32[r1][nc];
                float v1 = acc[j][3] + b1 + o32[r1][nc+1];
                og[r1*128+nc] = v0; og[r1*128+nc+1] = v1;
                o32[r1][nc] = v0; o32[r1][nc+1] = v1;
            }
        }
    }
    __syncthreads();
    { // output stats, column-aligned from smem
        float s3 = 0.f, q3 = 0.f;
        for (int i = tid; i < 4352; i += 256) {
            float v = o32[i >> 7][colj];
            s3 += v; q3 = fmaf(v, v, q3);
        }
        float* red = (float*)u16;
        red[tid] = s3; red[256 + tid] = q3;
        __syncthreads();
        if (tid < 128) {
            atomicAdd(&accL[tid],       red[tid] + red[tid + 128]);
            atomicAdd(&accL[128 + tid], red[256 + tid] + red[384 + tid]);
        }
    }
}

// ---------------- stage-2 scalar path (proven) -----------------------------
template<int N>
__device__ __forceinline__ void gemm128(const float (*hs)[DPAD], const float* __restrict__ wT,
                                        int ldw, int cidx, float bias, float* out) {
    #pragma unroll
    for (int r = 0; r < N; ++r) out[r] = bias;
    #pragma unroll 2
    for (int k = 0; k < D; k += 4) {
        float w0 = wT[(k+0)*ldw + cidx], w1 = wT[(k+1)*ldw + cidx];
        float w2 = wT[(k+2)*ldw + cidx], w3 = wT[(k+3)*ldw + cidx];
        #pragma unroll
        for (int r = 0; r < N; ++r) {
            float4 hv = *reinterpret_cast<const float4*>(&hs[r][k]);
            out[r] = fmaf(hv.x, w0, out[r]); out[r] = fmaf(hv.y, w1, out[r]);
            out[r] = fmaf(hv.z, w2, out[r]); out[r] = fmaf(hv.w, w3, out[r]);
        }
    }
}

template<int N, int GPB>
__global__ __launch_bounds__(128)
void k1_kernel(const float* __restrict__ hin, const float* __restrict__ foldIn,
               float* __restrict__ t1, float* __restrict__ t2, float* __restrict__ acc,
               const float* __restrict__ gwT, const float* __restrict__ gb,
               const float* __restrict__ qwT, const float* __restrict__ qb,
               const float* __restrict__ owT, const float* __restrict__ ob) {
    __shared__ float h_s[N][DPAD], q_s[N][DPAD], k_s[N][DPAD], v_s[N][DPAD];
    __shared__ float sc_s[4][N][N + 1], m_s[D];
    const int c = threadIdx.x, wp = c >> 5, lane = c & 31;
    const float scIn = foldIn[c], shIn = foldIn[D + c];
    const float gbv = gb[c], obv = ob[c];
    const float qbq = qb[c], qbk = qb[D + c], qbv = qb[2*D + c];
    float s1 = 0.f, sq1 = 0.f, s2 = 0.f, sq2 = 0.f;
    for (int gi = 0; gi < GPB; ++gi) {
        const int g = blockIdx.x * GPB + gi;
        const float* hg = hin + (size_t)g * (N * D);
        float mv = 0.f;
        #pragma unroll
        for (int r = 0; r < N; ++r) {
            float v = fmaf(hg[r*D + c], scIn, shIn);
            h_s[r][c] = v; mv += v;
        }
        m_s[c] = mv * (1.f / N);
        __syncthreads();
        float gcnv = gbv;
        #pragma unroll 4
        for (int k = 0; k < D; ++k) gcnv = fmaf(m_s[k], gwT[k*D + c], gcnv);
        {
            float* t1g = t1 + (size_t)g * (N * D);
            #pragma unroll
            for (int r = 0; r < N; ++r) {
                float v = gcnv + h_s[r][c];
                t1g[r*D + c] = v; s1 += v; sq1 = fmaf(v, v, sq1);
            }
        }
        {
            float a[N];
            gemm128<N>(h_s, qwT, 384, c, qbq, a);
            #pragma unroll
            for (int r = 0; r < N; ++r) q_s[r][c] = a[r];
            gemm128<N>(h_s, qwT, 384, c + 128, qbk, a);
            #pragma unroll
            for (int r = 0; r < N; ++r) k_s[r][c] = a[r];
            gemm128<N>(h_s, qwT, 384, c + 256, qbv, a);
            #pragma unroll
            for (int r = 0; r < N; ++r) v_s[r][c] = a[r];
        }
        __syncthreads();
        {
            const float invs = 0.17677669529663687f;
            for (int p = lane; p < N * N; p += 32) {
                int r = p / N, s = p - r * N;
                float d0 = 0.f;
                #pragma unroll
                for (int d = 0; d < 32; d += 4) {
                    float4 qq = *reinterpret_cast<const float4*>(&q_s[r][wp*32 + d]);
                    float4 kk = *reinterpret_cast<const float4*>(&k_s[s][wp*32 + d]);
                    d0 = fmaf(qq.x, kk.x, d0); d0 = fmaf(qq.y, kk.y, d0);
                    d0 = fmaf(qq.z, kk.z, d0); d0 = fmaf(qq.w, kk.w, d0);
                }
                sc_s[wp][r][s] = d0 * invs;
            }
            __syncwarp();
            if (lane < N) {
                float mx = -1e30f;
                #pragma unroll
                for (int s = 0; s < N; ++s) mx = fmaxf(mx, sc_s[wp][lane][s]);
                float sum = 0.f;
                #pragma unroll
                for (int s = 0; s < N; ++s) { float e = __expf(sc_s[wp][lane][s] - mx); sc_s[wp][lane][s] = e; sum += e; }
                float inv = 1.f / sum;
                #pragma unroll
                for (int s = 0; s < N; ++s) sc_s[wp][lane][s] *= inv;
            }
            __syncwarp();
            #pragma unroll
            for (int r = 0; r < N; ++r) {
                float o = 0.f;
                #pragma unroll
                for (int s = 0; s < N; ++s) o = fmaf(sc_s[wp][r][s], v_s[s][wp*32 + lane], o);
                q_s[r][wp*32 + lane] = o;
            }
        }
        __syncthreads();
        {
            float a[N];
            gemm128<N>(q_s, owT, 128, c, obv, a);
            float* t2g = t2 + (size_t)g * (N * D);
            #pragma unroll
            for (int r = 0; r < N; ++r) {
                float v = a[r] + h_s[r][c];
                t2g[r*D + c] = v; s2 += v; sq2 = fmaf(v, v, sq2);
            }
        }
        __syncthreads();
    }
    atomicAdd(&acc[c], s1); atomicAdd(&acc[128 + c], sq1);
    atomicAdd(&acc[256 + c], s2); atomicAdd(&acc[384 + c], sq2);
}

template<int N, int GPB>
__global__ __launch_bounds__(128)
void k2_kernel(const float* __restrict__ t1, const float* __restrict__ t2,
               const float* __restrict__ fold1, const float* __restrict__ fold2,
               float* __restrict__ hout, float* __restrict__ acc,
               const float* __restrict__ w1T, const float* __restrict__ b1,
               const float* __restrict__ w2T, const float* __restrict__ b2) {
    __shared__ float o_s[N][DPAD], u_s[N][260];
    const int c = threadIdx.x;
    const float sc1 = fold1[c], sh1 = fold1[128 + c];
    const float sc2 = fold2[c], sh2 = fold2[128 + c];
    const float b1a = b1[c], b1b = b1[128 + c], b2a = b2[c];
    float s3 = 0.f, q3 = 0.f;
    for (int gi = 0; gi < GPB; ++gi) {
        const int g = blockIdx.x * GPB + gi;
        const float* t1g = t1 + (size_t)g * (N * D);
        const float* t2g = t2 + (size_t)g * (N * D);
        #pragma unroll
        for (int r = 0; r < N; ++r)
            o_s[r][c] = fmaf(t1g[r*D + c], sc1, sh1) + fmaf(t2g[r*D + c], sc2, sh2);
        __syncthreads();
        {
            float a0[N], a1[N];
            #pragma unroll
            for (int r = 0; r < N; ++r) { a0[r] = b1a; a1[r] = b1b; }
            #pragma unroll 2
            for (int k = 0; k < D; k += 4) {
                float wa0 = w1T[(k+0)*256 + c], wb0 = w1T[(k+0)*256 + 128 + c];
                float wa1 = w1T[(k+1)*256 + c], wb1 = w1T[(k+1)*256 + 128 + c];
                float wa2 = w1T[(k+2)*256 + c], wb2 = w1T[(k+2)*256 + 128 + c];
                float wa3 = w1T[(k+3)*256 + c], wb3 = w1T[(k+3)*256 + 128 + c];
                #pragma unroll
                for (int r = 0; r < N; ++r) {
                    float4 hv = *reinterpret_cast<const float4*>(&o_s[r][k]);
                    a0[r] = fmaf(hv.x, wa0, a0[r]);  a1[r] = fmaf(hv.x, wb0, a1[r]);
                    a0[r] = fmaf(hv.y, wa1, a0[r]);  a1[r] = fmaf(hv.y, wb1, a1[r]);
                    a0[r] = fmaf(hv.z, wa2, a0[r]);  a1[r] = fmaf(hv.z, wb2, a1[r]);
                    a0[r] = fmaf(hv.w, wa3, a0[r]);  a1[r] = fmaf(hv.w, wb3, a1[r]);
                }
            }
            #pragma unroll
            for (int r = 0; r < N; ++r) {
                u_s[r][c] = fmaxf(a0[r], 0.f); u_s[r][128 + c] = fmaxf(a1[r], 0.f);
            }
        }
        __syncthreads();
        {
            float a0[N];
            #pragma unroll
            for (int r = 0; r < N; ++r) a0[r] = b2a;
            #pragma unroll 2
            for (int j = 0; j < 256; j += 4) {
                float w0 = w2T[(j+0)*D + c], w1v = w2T[(j+1)*D + c];
                float w2v = w2T[(j+2)*D + c], w3 = w2T[(j+3)*D + c];
                #pragma unroll
                for (int r = 0; r < N; ++r) {
                    float4 uv = *reinterpret_cast<const float4*>(&u_s[r][j]);
                    a0[r] = fmaf(uv.x, w0, a0[r]); a0[r] = fmaf(uv.y, w1v, a0[r]);
                    a0[r] = fmaf(uv.z, w2v, a0[r]); a0[r] = fmaf(uv.w, w3, a0[r]);
                }
            }
            float* og = hout + (size_t)g * (N * D);
            #pragma unroll
            for (int r = 0; r < N; ++r) {
                float v = o_s[r][c] + a0[r];
                og[r*D + c] = v; s3 += v; q3 = fmaf(v, v, q3);
            }
        }
        __syncthreads();
    }
    atomicAdd(&acc[c], s3); atomicAdd(&acc[128 + c], q3);
}

extern "C" void kernel_launch(void* const* d_in, const int* in_sizes, int n_in,
                              void* d_out, int out_size) {
    const float* poses = (const float*)d_in[0];
    const float* emb_w = (const float*)d_in[1];
    const float* emb_b = (const float*)d_in[2];
    const float* cls_w = (const float*)d_in[3];
    const float* cls_b = (const float*)d_in[4];
    const float* PPj[12]; const float* PPi[12];
    for (int i = 0; i < 12; ++i) { PPj[i] = (const float*)d_in[5+i]; PPi[i] = (const float*)d_in[17+i]; }

    float *A, *Bb, *Cc, *A2, *B2, *C2, *acc, *fold, *wT; uint2* wf;
    cudaGetSymbolAddress((void**)&A,    g_A);
    cudaGetSymbolAddress((void**)&Bb,   g_B);
    cudaGetSymbolAddress((void**)&Cc,   g_C);
    cudaGetSymbolAddress((void**)&A2,   g_A2);
    cudaGetSymbolAddress((void**)&B2,   g_B2);
    cudaGetSymbolAddress((void**)&C2,   g_C2);
    cudaGetSymbolAddress((void**)&acc,  g_acc);
    cudaGetSymbolAddress((void**)&fold, g_fold);
    cudaGetSymbolAddress((void**)&wT,   g_wT);
    cudaGetSymbolAddress((void**)&wf,   g_wf);
    const float* foldId = fold + 18 * 256;

    cudaFuncSetAttribute(k1_s1, cudaFuncAttributeMaxDynamicSharedMemorySize, SM1);
    cudaFuncSetAttribute(k2_s1, cudaFuncAttributeMaxDynamicSharedMemorySize, SM2);

    init_kernel<<<18, 256>>>(acc, fold + 18 * 256);

    transpose_kernel<<<192, 256>>>(PPj[0], wT, 128, 128, 49152);
    for (int l = 0; l < 3; ++l) {
        prep_frag<<<48, 256>>>(PPj[2]  + l*49152, wf + l*32768,          48, 128, 12288);
        prep_frag<<<16, 256>>>(PPj[4]  + l*16384, wf + l*32768 + 12288,  16, 128, 4096);
        prep_frag<<<32, 256>>>(PPj[8]  + l*32768, wf + l*32768 + 16384,  32, 128, 8192);
        prep_frag<<<32, 256>>>(PPj[10] + l*32768, wf + l*32768 + 24576,  16, 256, 8192);
    }
    {
        float* wTs = wT + 442368;
        transpose_kernel<<<192, 256>>>(PPi[0],  wTs + 0,      128, 128, 49152);
        transpose_kernel<<<576, 256>>>(PPi[2],  wTs + 49152,  384, 128, 147456);
        transpose_kernel<<<192, 256>>>(PPi[4],  wTs + 196608, 128, 128, 49152);
        transpose_kernel<<<384, 256>>>(PPi[8],  wTs + 245760, 256, 128, 98304);
        transpose_kernel<<<384, 256>>>(PPi[10], wTs + 344064, 128, 256, 98304);
    }

    embed_kernel<<<182784, 256>>>(poses, emb_w, emb_b, A, 46792704);

    // stage 1 (tensor-core, 3 CTAs/SM)
    const float* foldPrev = foldId;
    for (int l = 0; l < 3; ++l) {
        float* accL = acc + l * 768;
        float* foldL = fold + l * 768;
        k1_s1<<<21504, 256, SM1>>>(A, foldPrev, Bb, Cc, accL,
                                   wT + l*16384, PPj[1] + l*128, PPj[3] + l*384, PPj[5] + l*128,
                                   wf + l*32768, wf + l*32768 + 12288);
        finalize_kernel<<<2, 128>>>(accL, 1.f/365568.f, PPj[6] + l*384, PPj[7] + l*384, foldL,
                                    PPj[6] + l*384 + 128, PPj[7] + l*384 + 128, foldL + 256);
        k2_s1<<<10752, 256, SM2>>>(A, Bb, Cc, foldPrev, foldL, foldL + 256, A, accL + 512,
                                   wf + l*32768 + 16384, PPj[9] + l*256,
                                   wf + l*32768 + 24576, PPj[11] + l*128);
        finalize_kernel<<<1, 128>>>(accL + 512, 1.f/365568.f, PPj[6] + l*384 + 256,
                                    PPj[7] + l*384 + 256, foldL + 512, nullptr, nullptr, nullptr);
        foldPrev = foldL + 512;
    }

    pool1_kernel<<<10752, 256>>>(A, foldPrev, A2, 2752512);

    // stage 2 (scalar)
    foldPrev = foldId;
    float* wTs = wT + 442368;
    for (int l = 0; l < 3; ++l) {
        float* accL = acc + 2304 + l * 768;
        float* foldL = fold + 2304 + l * 768;
        k1_kernel<12, 2><<<896, 128>>>(A2, foldPrev, B2, C2, accL,
                                       wTs + l*16384, PPi[1] + l*128, wTs + 49152 + l*49152,
                                       PPi[3] + l*384, wTs + 196608 + l*16384, PPi[5] + l*128);
        finalize_kernel<<<2, 128>>>(accL, 1.f/21504.f, PPi[6] + l*384, PPi[7] + l*384, foldL,
                                    PPi[6] + l*384 + 128, PPi[7] + l*384 + 128, foldL + 256);
        k2_kernel<12, 2><<<896, 128>>>(B2, C2, foldL, foldL + 256, A2, accL + 512,
                                       wTs + 245760 + l*32768, PPi[9] + l*256,
                                       wTs + 344064 + l*32768, PPi[11] + l*128);
        finalize_kernel<<<1, 128>>>(accL + 512, 1.f/21504.f, PPi[6] + l*384 + 256,
                                    PPi[7] + l*384 + 256, foldL + 512, nullptr, nullptr, nullptr);
        foldPrev = foldL + 512;
    }

    pool2_cls_kernel<<<256, 128>>>(A2, foldPrev, cls_w, cls_b, (float*)d_out);
}

// round 11
// speedup vs baseline: 1.1493x; 1.1493x over previous
#include <cuda_runtime.h>
#include <cuda_fp16.h>
#include <stdint.h>

#define D 128
#define DPAD 132

static __device__ float g_A [46792704];
static __device__ float g_B [46792704];
static __device__ float g_C [46792704];
static __device__ float g_A2[ 2752512];
static __device__ float g_B2[ 2752512];
static __device__ float g_C2[ 2752512];
static __device__ float g_acc [18*256];
static __device__ float g_fold[19*256];
static __device__ float g_wT  [884736];
static __device__ uint2 g_wf  [98304];

__global__ void init_kernel(float* acc, float* foldId) {
    int t = blockIdx.x * blockDim.x + threadIdx.x;
    if (t < 18*256) acc[t] = 0.f;
    if (t < 128) { foldId[t] = 1.f; foldId[128 + t] = 0.f; }
}

__global__ void transpose_kernel(const float* __restrict__ src, float* __restrict__ dst,
                                 int R, int C, int total) {
    int idx = blockIdx.x * blockDim.x + threadIdx.x;
    if (idx >= total) return;
    int m = idx / (R * C), rc = idx - m * (R * C), cc = rc / R, r = rc - cc * R;
    dst[idx] = src[m * R * C + r * C + cc];
}

__global__ void prep_frag(const float* __restrict__ W, uint2* __restrict__ out,
                          int NT, int K, int total) {
    int idx = blockIdx.x * blockDim.x + threadIdx.x;
    if (idx >= total) return;
    int lane = idx & 31, tile = idx >> 5;
    int nt = tile % NT, kt = tile / NT;
    int g = lane >> 2, t = lane & 3;
    const float* w = W + (size_t)(nt * 8 + g) * K + kt * 16 + 2 * t;
    __half2 b0 = __floats2half2_rn(w[0], w[1]);
    __half2 b1 = __floats2half2_rn(w[8], w[9]);
    uint2 o; o.x = *(uint32_t*)&b0; o.y = *(uint32_t*)&b1;
    out[idx] = o;
}

__global__ void embed_kernel(const float* __restrict__ poses, const float* __restrict__ ew,
                             const float* __restrict__ eb, float* __restrict__ out, int total) {
    int idx = blockIdx.x * blockDim.x + threadIdx.x;
    if (idx >= total) return;
    int row = idx >> 7, c = idx & 127;
    float v = fmaf(poses[row*2], ew[2*c], fmaf(poses[row*2+1], ew[2*c+1], eb[c]));
    out[idx] = v > 0.f ? v : 0.01f * v;
}

__global__ void finalize_kernel(const float* __restrict__ acc, float invN,
                                const float* g0, const float* b0, float* f0,
                                const float* g1, const float* b1, float* f1) {
    int set = blockIdx.x, c = threadIdx.x;
    const float* a  = acc + set * 256;
    const float* gg = set ? g1 : g0;
    const float* bb = set ? b1 : b0;
    float* ff = set ? f1 : f0;
    float m = a[c] * invN;
    float v = fmaxf(a[128 + c] * invN - m * m, 0.f);
    float sc = rsqrtf(v + 1e-5f) * gg[c];
    ff[c] = sc;
    ff[128 + c] = fmaf(-m, sc, bb[c]);
}

__global__ void pool1_kernel(const float* __restrict__ hin, const float* __restrict__ fold,
                             float* __restrict__ out, int total) {
    int idx = blockIdx.x * blockDim.x + threadIdx.x;
    if (idx >= total) return;
    int orow = idx >> 7, c = idx & 127;
    const float* base = hin + (size_t)orow * 17 * D + c;
    float s = 0.f;
    #pragma unroll
    for (int j = 0; j < 17; ++j) s += base[j * D];
    out[idx] = fmaf(s * (1.f / 17.f), fold[c], fold[128 + c]);
}

__global__ void pool2_cls_kernel(const float* __restrict__ hin, const float* __restrict__ fold,
                                 const float* __restrict__ cw, const float* __restrict__ cb,
                                 float* __restrict__ out) {
    __shared__ float p_s[D];
    int b = blockIdx.x, c = threadIdx.x;
    const float* base = hin + (size_t)b * 84 * D + c;
    float s = 0.f;
    #pragma unroll 4
    for (int r = 0; r < 84; ++r) s += base[r * D];
    p_s[c] = fmaf(s * (1.f / 84.f), fold[c], fold[128 + c]);
    __syncthreads();
    if (c < 8) {
        float acc = cb[c];
        #pragma unroll 4
        for (int k = 0; k < D; ++k) acc = fmaf(p_s[k], cw[c * D + k], acc);
        out[b * 8 + c] = acc;
    }
}

__device__ __forceinline__ void mma16816(float* c, uint32_t a0, uint32_t a1,
                                         uint32_t a2, uint32_t a3, uint32_t b0, uint32_t b1) {
    asm("mma.sync.aligned.m16n8k16.row.col.f32.f16.f16.f32 "
        "{%0,%1,%2,%3},{%4,%5,%6,%7},{%8,%9},{%0,%1,%2,%3};"
        : "+f"(c[0]), "+f"(c[1]), "+f"(c[2]), "+f"(c[3])
        : "r"(a0), "r"(a1), "r"(a2), "r"(a3), "r"(b0), "r"(b1));
}

template<int KT, int NT>
__device__ __forceinline__ void mtile(const __half* a0p, int lda, const uint2* __restrict__ wf,
                                      int ng, int lane, float acc[4][4]) {
    const __half* a1p = a0p + 8 * lda;
    #pragma unroll
    for (int kt = 0; kt < KT; ++kt) {
        uint32_t a0 = *(const uint32_t*)(a0p + kt*16);
        uint32_t a1 = *(const uint32_t*)(a1p + kt*16);
        uint32_t a2 = *(const uint32_t*)(a0p + kt*16 + 8);
        uint32_t a3 = *(const uint32_t*)(a1p + kt*16 + 8);
        #pragma unroll
        for (int j = 0; j < 4; ++j) {
            uint2 b = wf[(kt*NT + ng*4 + j)*32 + lane];
            mma16816(acc[j], a0, a1, a2, a3, b.x, b.y);
        }
    }
}

// ---------------- stage-1 tensor kernels: 2 graphs (34 rows), 2 CTAs/SM ----
#define O_H16 0
#define O_Q16 13056
#define O_K16 26112
#define O_VT  39168
#define O_P   56576
#define O_SC  73984
#define O_MB  87584
#define O_H32 91680
#define SM1   109632

__global__ __launch_bounds__(256, 2)
void k1_s1(const float* __restrict__ hin, const float* __restrict__ foldIn,
           float* __restrict__ gcnb, float* __restrict__ t2, float* __restrict__ accL,
           const float* __restrict__ gwT, const float* __restrict__ gb,
           const float* __restrict__ qb, const float* __restrict__ ob,
           const uint2* __restrict__ qkvf, const uint2* __restrict__ owf) {
    extern __shared__ char sm[];
    __half (*h16)[136] = (__half(*)[136])(sm + O_H16);   // [48][136]
    __half (*q16)[136] = (__half(*)[136])(sm + O_Q16);   // [48][136]
    __half (*k16)[136] = (__half(*)[136])(sm + O_K16);   // [48][136]
    __half (*vT )[34]  = (__half(*)[34]) (sm + O_VT);    // [2*128][34]
    __half (*pp )[34]  = (__half(*)[34]) (sm + O_P);     // [2*4*32][34]
    float  (*sc )[25]  = (float(*)[25])  (sm + O_SC);    // [136][25]
    float*  mbuf       = (float*)(sm + O_MB);            // 1024 floats
    float  (*h32)[132] = (float(*)[132]) (sm + O_H32);   // [34][132]

    const int tid = threadIdx.x, warp = tid >> 5, lane = tid & 31;
    const int g = lane >> 2, t = lane & 3;
    const int colj = tid & 127;
    const float* hg = hin + (size_t)blockIdx.x * 4352;
    float* t2g = t2 + (size_t)blockIdx.x * 4352;
    const float scIn = foldIn[colj], shIn = foldIn[128 + colj];

    { // zero vT+pp (contiguous 34816B = 2176 uint4) + h16 pad rows (uint4)
        uint4 zz = make_uint4(0,0,0,0);
        uint4* z = (uint4*)(sm + O_VT);
        for (int i = tid; i < 2176; i += 256) z[i] = zz;
        uint4* zh = (uint4*)&h16[34][0];   // 14 rows x 272B = 3808B = 238 uint4
        for (int i = tid; i < 238; i += 256) zh[i] = zz;
        for (int i = tid; i < 4352; i += 256) {
            int rr = i >> 7;
            float v = fmaf(hg[i], scIn, shIn);
            h32[rr][colj] = v;
            h16[rr][colj] = __float2half_rn(v);
        }
    }
    __syncthreads();
    { // per-graph mean + Sh + Sq (2 graphs x 128 channels)
        int gi = tid >> 7, cc = tid & 127;
        float s = 0.f, q = 0.f;
        #pragma unroll
        for (int r = 0; r < 17; ++r) {
            float v = h32[gi*17 + r][cc];
            s += v; q = fmaf(v, v, q);
        }
        mbuf[tid] = s * (1.f / 17.f);
        float* scr = (float*)sc;
        scr[tid] = q;          // Sq
        scr[256 + tid] = s;    // Sh
    }
    __syncthreads();
    { // GCN rank-1 -> smem + tiny global buffer
        int gi = tid >> 7, cc = tid & 127;
        float a = gb[cc];
        const float* mrow = mbuf + gi * 128;
        #pragma unroll 4
        for (int k = 0; k < 128; ++k) a = fmaf(mrow[k], gwT[k*128 + cc], a);
        mbuf[256 + tid] = a;
        gcnb[(size_t)blockIdx.x * 256 + tid] = a;
    }
    __syncthreads();
    { // t1 stats via algebra: sum = 17*gcn + Sh ; sumsq = 17*gcn^2 + 2*gcn*Sh + Sq
        float* scr = (float*)sc;
        float gcnv = mbuf[256 + tid];
        float Sh = scr[256 + tid], Sq = scr[tid];
        float s1 = fmaf(17.f, gcnv, Sh);
        float q1 = fmaf(17.f * gcnv, gcnv, fmaf(2.f * gcnv, Sh, Sq));
        mbuf[tid] = s1;       // means no longer needed
        scr[tid] = q1;
    }
    __syncthreads();
    if (tid < 128) {
        float* scr = (float*)sc;
        atomicAdd(&accL[tid],       mbuf[tid] + mbuf[tid + 128]);
        atomicAdd(&accL[128 + tid], scr[tid] + scr[tid + 128]);
    }
    // qkv: M=48, N=384, K=128
    for (int item = warp; item < 36; item += 8) {
        int mt = item / 12, ng = item % 12, m0 = mt * 16;
        float acc[4][4] = {};
        mtile<8,48>(&h16[m0 + g][2*t], 136, qkvf, ng, lane, acc);
        int r0 = m0 + g, r1 = r0 + 8;
        #pragma unroll
        for (int j = 0; j < 4; ++j) {
            int nc = ng*32 + j*8 + 2*t;
            float b0 = qb[nc], b1 = qb[nc+1];
            float v00 = acc[j][0]+b0, v01 = acc[j][1]+b1, v10 = acc[j][2]+b0, v11 = acc[j][3]+b1;
            if (nc < 128) {
                *(__half2*)&q16[r0][nc] = __floats2half2_rn(v00, v01);
                *(__half2*)&q16[r1][nc] = __floats2half2_rn(v10, v11);
            } else if (nc < 256) {
                *(__half2*)&k16[r0][nc-128] = __floats2half2_rn(v00, v01);
                *(__half2*)&k16[r1][nc-128] = __floats2half2_rn(v10, v11);
            } else {
                int d = nc - 256;
                if (r0 < 34) { int gi = r0/17, sl = r0 - gi*17;
                    vT[gi*128+d][sl] = __float2half_rn(v00); vT[gi*128+d+1][sl] = __float2half_rn(v01); }
                if (r1 < 34) { int gi = r1/17, sl = r1 - gi*17;
                    vT[gi*128+d][sl] = __float2half_rn(v10); vT[gi*128+d+1][sl] = __float2half_rn(v11); }
            }
        }
    }
    __syncthreads();
    // scores: 2 graphs x 4 heads x (2 mt x 3 nt)
    for (int item = warp; item < 48; item += 8) {
        int gi = item / 24, r = item % 24, hh = r / 6, r2 = r % 6, mt = r2 / 3, nt = r2 % 3;
        int base = gi * 17;
        float acc[4] = {};
        const __half* a0p = &q16[base + mt*16 + g][hh*32 + 2*t];
        const __half* a1p = a0p + 8*136;
        const __half* br  = &k16[base + nt*8 + g][hh*32 + 2*t];
        #pragma unroll
        for (int kt = 0; kt < 2; ++kt) {
            mma16816(acc, *(const uint32_t*)(a0p+kt*16), *(const uint32_t*)(a1p+kt*16),
                     *(const uint32_t*)(a0p+kt*16+8), *(const uint32_t*)(a1p+kt*16+8),
                     *(const uint32_t*)(br+kt*16), *(const uint32_t*)(br+kt*16+8));
        }
        const float invs = 0.17677669529663687f;
        int q0 = mt*16 + g, ss = nt*8 + 2*t, row = (gi*4 + hh)*17;
        if (q0 < 17)     { sc[row+q0][ss]   = acc[0]*invs; sc[row+q0][ss+1]   = acc[1]*invs; }
        if (q0 + 8 < 17) { sc[row+q0+8][ss] = acc[2]*invs; sc[row+q0+8][ss+1] = acc[3]*invs; }
    }
    __syncthreads();
    for (int idx = tid; idx < 136; idx += 256) { // softmax -> fp16 probs
        int gh = idx / 17, q = idx - gh*17;
        float e[17], mx = -1e30f;
        #pragma unroll
        for (int s = 0; s < 17; ++s) mx = fmaxf(mx, sc[gh*17+q][s]);
        float sum = 0.f;
        #pragma unroll
        for (int s = 0; s < 17; ++s) { e[s] = __expf(sc[gh*17+q][s] - mx); sum += e[s]; }
        float inv = 1.f / sum;
        #pragma unroll
        for (int s = 0; s < 17; ++s) pp[gh*32 + q][s] = __float2half_rn(e[s] * inv);
    }
    __syncthreads();
    // attn @ V -> q16 (reuse): 2 x 4 x 2 = 16 items
    for (int item = warp; item < 16; item += 8) {
        int gi = item / 8, r = item % 8, hh = r / 2, mt = r % 2;
        float acc[4][4] = {};
        const __half* a0p = &pp[(gi*4+hh)*32 + mt*16 + g][2*t];
        const __half* a1p = a0p + 8*34;
        #pragma unroll
        for (int kt = 0; kt < 2; ++kt) {
            uint32_t a0 = *(const uint32_t*)(a0p+kt*16), a1 = *(const uint32_t*)(a1p+kt*16);
            uint32_t a2 = *(const uint32_t*)(a0p+kt*16+8), a3 = *(const uint32_t*)(a1p+kt*16+8);
            #pragma unroll
            for (int j = 0; j < 4; ++j) {
                const __half* bp = &vT[gi*128 + hh*32 + j*8 + g][kt*16 + 2*t];
                mma16816(acc[j], a0, a1, a2, a3, *(const uint32_t*)bp, *(const uint32_t*)(bp+8));
            }
        }
        int q0 = mt*16 + g;
        #pragma unroll
        for (int j = 0; j < 4; ++j) {
            int col = hh*32 + j*8 + 2*t;
            if (q0 < 17)     *(__half2*)&q16[gi*17+q0][col]   = __floats2half2_rn(acc[j][0], acc[j][1]);
            if (q0 + 8 < 17) *(__half2*)&q16[gi*17+q0+8][col] = __floats2half2_rn(acc[j][2], acc[j][3]);
        }
    }
    __syncthreads();
    // out-proj + residual -> t2 (global) AND back into h32 (stats)
    for (int item = warp; item < 12; item += 8) {
        int mt = item / 4, ng = item % 4, m0 = mt * 16;
        float acc[4][4] = {};
        mtile<8,16>(&q16[m0 + g][2*t], 136, owf, ng, lane, acc);
        int r0 = m0 + g, r1 = r0 + 8;
        #pragma unroll
        for (int j = 0; j < 4; ++j) {
            int nc = ng*32 + j*8 + 2*t;
            float b0 = ob[nc], b1 = ob[nc+1];
            if (r0 < 34) {
                float v0 = acc[j][0] + b0 + h32[r0][nc];
                float v1 = acc[j][1] + b1 + h32[r0][nc+1];
                t2g[r0*128+nc] = v0; t2g[r0*128+nc+1] = v1;
                h32[r0][nc] = v0; h32[r0][nc+1] = v1;
            }
            if (r1 < 34) {
                float v0 = acc[j][2] + b0 + h32[r1][nc];
                float v1 = acc[j][3] + b1 + h32[r1][nc+1];
                t2g[r1*128+nc] = v0; t2g[r1*128+nc+1] = v1;
                h32[r1][nc] = v0; h32[r1][nc+1] = v1;
            }
        }
    }
    __syncthreads();
    { // t2 stats, column-aligned from smem
        float s2 = 0.f, q2 = 0.f;
        for (int i = tid; i < 4352; i += 256) {
            float v = h32[i >> 7][colj];
            s2 += v; q2 = fmaf(v, v, q2);
        }
        mbuf[tid] = s2; mbuf[256 + tid] = q2;
        __syncthreads();
        if (tid < 128) {
            atomicAdd(&accL[256 + tid], mbuf[tid] + mbuf[tid + 128]);
            atomicAdd(&accL[384 + tid], mbuf[256 + tid] + mbuf[384 + tid]);
        }
    }
}

// 4 graphs (68 rows) per block, 2 CTAs/SM
#define P_O16 0
#define P_U16 21760
#define P_O32 64000
#define P_GB  99904
#define SM2   101952

__global__ __launch_bounds__(256, 2)
void k2_s1(const float* __restrict__ hg0, const float* __restrict__ gcnb,
           const float* __restrict__ t2, const float* __restrict__ foldIn,
           const float* __restrict__ fold1, const float* __restrict__ fold2,
           float* __restrict__ hout, float* __restrict__ accL,
           const uint2* __restrict__ w1f, const float* __restrict__ b1v,
           const uint2* __restrict__ w2f, const float* __restrict__ b2v) {
    extern __shared__ char sm[];
    __half (*o16)[136] = (__half(*)[136])(sm + P_O16);   // [80][136]
    __half (*u16)[264] = (__half(*)[264])(sm + P_U16);   // [80][264]
    float  (*o32)[132] = (float(*)[132]) (sm + P_O32);   // [68][132]
    float*  gbuf       = (float*)(sm + P_GB);            // 512 floats
    const int tid = threadIdx.x, warp = tid >> 5, lane = tid & 31;
    const int g = lane >> 2, t = lane & 3;
    const int colj = tid & 127;
    const float* hgA = hg0 + (size_t)blockIdx.x * 8704;
    const float* t2g = t2  + (size_t)blockIdx.x * 8704;
    float* og = hout + (size_t)blockIdx.x * 8704;
    const float scIn = foldIn[colj], shIn = foldIn[128 + colj];
    const float sc1 = fold1[colj], sh1 = fold1[128 + colj];
    const float sc2 = fold2[colj], sh2 = fold2[128 + colj];

    for (int j = tid; j < 512; j += 256)
        gbuf[j] = gcnb[(size_t)blockIdx.x * 512 + j];
    { // zero o16 pad rows 68-79 (12 rows x 272B = 3264B = 204 uint4)
        uint4 zz = make_uint4(0,0,0,0);
        uint4* z = (uint4*)&o16[68][0];
        for (int i = tid; i < 204; i += 256) z[i] = zz;
    }
    __syncthreads();
    // o = BN1(gcn + BN_in(h)) + BN2(t2)  -> o32 (fp32) + o16
    for (int i = tid; i < 8704; i += 256) {
        int rr = i >> 7;
        float t1v = gbuf[(rr/17)*128 + colj] + fmaf(hgA[i], scIn, shIn);
        float o = fmaf(t1v, sc1, sh1) + fmaf(t2g[i], sc2, sh2);
        o32[rr][colj] = o;
        o16[rr][colj] = __float2half_rn(o);
    }
    __syncthreads();
    // mlp1: M=80, N=256, K=128 (+ReLU): 40 items
    for (int item = warp; item < 40; item += 8) {
        int mt = item / 8, ng = item % 8, m0 = mt * 16;
        float acc[4][4] = {};
        mtile<8,32>(&o16[m0 + g][2*t], 136, w1f, ng, lane, acc);
        int r0 = m0 + g, r1 = r0 + 8;
        #pragma unroll
        for (int j = 0; j < 4; ++j) {
            int nc = ng*32 + j*8 + 2*t;
            float b0 = b1v[nc], b1 = b1v[nc+1];
            *(__half2*)&u16[r0][nc] = __floats2half2_rn(fmaxf(acc[j][0]+b0, 0.f), fmaxf(acc[j][1]+b1, 0.f));
            *(__half2*)&u16[r1][nc] = __floats2half2_rn(fmaxf(acc[j][2]+b0, 0.f), fmaxf(acc[j][3]+b1, 0.f));
        }
    }
    __syncthreads();
    // mlp2: M=80, N=128, K=256 + residual -> og AND o32 (stats): 20 items
    for (int item = warp; item < 20; item += 8) {
        int mt = item / 4, ng = item % 4, m0 = mt * 16;
        float acc[4][4] = {};
        mtile<16,16>(&u16[m0 + g][2*t], 264, w2f, ng, lane, acc);
        int r0 = m0 + g, r1 = r0 + 8;
        #pragma unroll
        for (int j = 0; j < 4; ++j) {
            int nc = ng*32 + j*8 + 2*t;
            float b0 = b2v[nc], b1 = b2v[nc+1];
            if (r0 < 68) {
                float v0 = acc[j][0] + b0 + o32[r0][nc];
                float v1 = acc[j][1] + b1 + o32[r0][nc+1];
                og[r0*128+nc] = v0; og[r0*128+nc+1] = v1;
                o32[r0][nc] = v0; o32[r0][nc+1] = v1;
            }
            if (r1 < 68) {
                float v0 = acc[j][2] + b0 + o32[r1][nc];
                float v1 = acc[j][3] + b1 + o32[r1][nc+1];
                og[r1*128+nc] = v0; og[r1*128+nc+1] = v1;
                o32[r1][nc] = v0; o32[r1][nc+1] = v1;
            }
        }
    }
    __syncthreads();
    { // output stats, column-aligned from smem
        float s3 = 0.f, q3 = 0.f;
        for (int i = tid; i < 8704; i += 256) {
            float v = o32[i >> 7][colj];
            s3 += v; q3 = fmaf(v, v, q3);
        }
        float* red = (float*)u16;
        red[tid] = s3; red[256 + tid] = q3;
        __syncthreads();
        if (tid < 128) {
            atomicAdd(&accL[tid],       red[tid] + red[tid + 128]);
            atomicAdd(&accL[128 + tid], red[256 + tid] + red[384 + tid]);
        }
    }
}

// ---------------- stage-2 scalar path (proven) -----------------------------
template<int N>
__device__ __forceinline__ void gemm128(const float (*hs)[DPAD], const float* __restrict__ wT,
                                        int ldw, int cidx, float bias, float* out) {
    #pragma unroll
    for (int r = 0; r < N; ++r) out[r] = bias;
    #pragma unroll 2
    for (int k = 0; k < D; k += 4) {
        float w0 = wT[(k+0)*ldw + cidx], w1 = wT[(k+1)*ldw + cidx];
        float w2 = wT[(k+2)*ldw + cidx], w3 = wT[(k+3)*ldw + cidx];
        #pragma unroll
        for (int r = 0; r < N; ++r) {
            float4 hv = *reinterpret_cast<const float4*>(&hs[r][k]);
            out[r] = fmaf(hv.x, w0, out[r]); out[r] = fmaf(hv.y, w1, out[r]);
            out[r] = fmaf(hv.z, w2, out[r]); out[r] = fmaf(hv.w, w3, out[r]);
        }
    }
}

template<int N, int GPB>
__global__ __launch_bounds__(128)
void k1_kernel(const float* __restrict__ hin, const float* __restrict__ foldIn,
               float* __restrict__ t1, float* __restrict__ t2, float* __restrict__ acc,
               const float* __restrict__ gwT, const float* __restrict__ gb,
               const float* __restrict__ qwT, const float* __restrict__ qb,
               const float* __restrict__ owT, const float* __restrict__ ob) {
    __shared__ float h_s[N][DPAD], q_s[N][DPAD], k_s[N][DPAD], v_s[N][DPAD];
    __shared__ float sc_s[4][N][N + 1], m_s[D];
    const int c = threadIdx.x, wp = c >> 5, lane = c & 31;
    const float scIn = foldIn[c], shIn = foldIn[D + c];
    const float gbv = gb[c], obv = ob[c];
    const float qbq = qb[c], qbk = qb[D + c], qbv = qb[2*D + c];
    float s1 = 0.f, sq1 = 0.f, s2 = 0.f, sq2 = 0.f;
    for (int gi = 0; gi < GPB; ++gi) {
        const int g = blockIdx.x * GPB + gi;
        const float* hg = hin + (size_t)g * (N * D);
        float mv = 0.f;
        #pragma unroll
        for (int r = 0; r < N; ++r) {
            float v = fmaf(hg[r*D + c], scIn, shIn);
            h_s[r][c] = v; mv += v;
        }
        m_s[c] = mv * (1.f / N);
        __syncthreads();
        float gcnv = gbv;
        #pragma unroll 4
        for (int k = 0; k < D; ++k) gcnv = fmaf(m_s[k], gwT[k*D + c], gcnv);
        {
            float* t1g = t1 + (size_t)g * (N * D);
            #pragma unroll
            for (int r = 0; r < N; ++r) {
                float v = gcnv + h_s[r][c];
                t1g[r*D + c] = v; s1 += v; sq1 = fmaf(v, v, sq1);
            }
        }
        {
            float a[N];
            gemm128<N>(h_s, qwT, 384, c, qbq, a);
            #pragma unroll
            for (int r = 0; r < N; ++r) q_s[r][c] = a[r];
            gemm128<N>(h_s, qwT, 384, c + 128, qbk, a);
            #pragma unroll
            for (int r = 0; r < N; ++r) k_s[r][c] = a[r];
            gemm128<N>(h_s, qwT, 384, c + 256, qbv, a);
            #pragma unroll
            for (int r = 0; r < N; ++r) v_s[r][c] = a[r];
        }
        __syncthreads();
        {
            const float invs = 0.17677669529663687f;
            for (int p = lane; p < N * N; p += 32) {
                int r = p / N, s = p - r * N;
                float d0 = 0.f;
                #pragma unroll
                for (int d = 0; d < 32; d += 4) {
                    float4 qq = *reinterpret_cast<const float4*>(&q_s[r][wp*32 + d]);
                    float4 kk = *reinterpret_cast<const float4*>(&k_s[s][wp*32 + d]);
                    d0 = fmaf(qq.x, kk.x, d0); d0 = fmaf(qq.y, kk.y, d0);
                    d0 = fmaf(qq.z, kk.z, d0); d0 = fmaf(qq.w, kk.w, d0);
                }
                sc_s[wp][r][s] = d0 * invs;
            }
            __syncwarp();
            if (lane < N) {
                float mx = -1e30f;
                #pragma unroll
                for (int s = 0; s < N; ++s) mx = fmaxf(mx, sc_s[wp][lane][s]);
                float sum = 0.f;
                #pragma unroll
                for (int s = 0; s < N; ++s) { float e = __expf(sc_s[wp][lane][s] - mx); sc_s[wp][lane][s] = e; sum += e; }
                float inv = 1.f / sum;
                #pragma unroll
                for (int s = 0; s < N; ++s) sc_s[wp][lane][s] *= inv;
            }
            __syncwarp();
            #pragma unroll
            for (int r = 0; r < N; ++r) {
                float o = 0.f;
                #pragma unroll
                for (int s = 0; s < N; ++s) o = fmaf(sc_s[wp][r][s], v_s[s][wp*32 + lane], o);
                q_s[r][wp*32 + lane] = o;
            }
        }
        __syncthreads();
        {
            float a[N];
            gemm128<N>(q_s, owT, 128, c, obv, a);
            float* t2g = t2 + (size_t)g * (N * D);
            #pragma unroll
            for (int r = 0; r < N; ++r) {
                float v = a[r] + h_s[r][c];
                t2g[r*D + c] = v; s2 += v; sq2 = fmaf(v, v, sq2);
            }
        }
        __syncthreads();
    }
    atomicAdd(&acc[c], s1); atomicAdd(&acc[128 + c], sq1);
    atomicAdd(&acc[256 + c], s2); atomicAdd(&acc[384 + c], sq2);
}

template<int N, int GPB>
__global__ __launch_bounds__(128)
void k2_kernel(const float* __restrict__ t1, const float* __restrict__ t2,
               const float* __restrict__ fold1, const float* __restrict__ fold2,
               float* __restrict__ hout, float* __restrict__ acc,
               const float* __restrict__ w1T, const float* __restrict__ b1,
               const float* __restrict__ w2T, const float* __restrict__ b2) {
    __shared__ float o_s[N][DPAD], u_s[N][260];
    const int c = threadIdx.x;
    const float sc1 = fold1[c], sh1 = fold1[128 + c];
    const float sc2 = fold2[c], sh2 = fold2[128 + c];
    const float b1a = b1[c], b1b = b1[128 + c], b2a = b2[c];
    float s3 = 0.f, q3 = 0.f;
    for (int gi = 0; gi < GPB; ++gi) {
        const int g = blockIdx.x * GPB + gi;
        const float* t1g = t1 + (size_t)g * (N * D);
        const float* t2g = t2 + (size_t)g * (N * D);
        #pragma unroll
        for (int r = 0; r < N; ++r)
            o_s[r][c] = fmaf(t1g[r*D + c], sc1, sh1) + fmaf(t2g[r*D + c], sc2, sh2);
        __syncthreads();
        {
            float a0[N], a1[N];
            #pragma unroll
            for (int r = 0; r < N; ++r) { a0[r] = b1a; a1[r] = b1b; }
            #pragma unroll 2
            for (int k = 0; k < D; k += 4) {
                float wa0 = w1T[(k+0)*256 + c], wb0 = w1T[(k+0)*256 + 128 + c];
                float wa1 = w1T[(k+1)*256 + c], wb1 = w1T[(k+1)*256 + 128 + c];
                float wa2 = w1T[(k+2)*256 + c], wb2 = w1T[(k+2)*256 + 128 + c];
                float wa3 = w1T[(k+3)*256 + c], wb3 = w1T[(k+3)*256 + 128 + c];
                #pragma unroll
                for (int r = 0; r < N; ++r) {
                    float4 hv = *reinterpret_cast<const float4*>(&o_s[r][k]);
                    a0[r] = fmaf(hv.x, wa0, a0[r]);  a1[r] = fmaf(hv.x, wb0, a1[r]);
                    a0[r] = fmaf(hv.y, wa1, a0[r]);  a1[r] = fmaf(hv.y, wb1, a1[r]);
                    a0[r] = fmaf(hv.z, wa2, a0[r]);  a1[r] = fmaf(hv.z, wb2, a1[r]);
                    a0[r] = fmaf(hv.w, wa3, a0[r]);  a1[r] = fmaf(hv.w, wb3, a1[r]);
                }
            }
            #pragma unroll
            for (int r = 0; r < N; ++r) {
                u_s[r][c] = fmaxf(a0[r], 0.f); u_s[r][128 + c] = fmaxf(a1[r], 0.f);
            }
        }
        __syncthreads();
        {
            float a0[N];
            #pragma unroll
            for (int r = 0; r < N; ++r) a0[r] = b2a;
            #pragma unroll 2
            for (int j = 0; j < 256; j += 4) {
                float w0 = w2T[(j+0)*D + c], w1v = w2T[(j+1)*D + c];
                float w2v = w2T[(j+2)*D + c], w3 = w2T[(j+3)*D + c];
                #pragma unroll
                for (int r = 0; r < N; ++r) {
                    float4 uv = *reinterpret_cast<const float4*>(&u_s[r][j]);
                    a0[r] = fmaf(uv.x, w0, a0[r]); a0[r] = fmaf(uv.y, w1v, a0[r]);
                    a0[r] = fmaf(uv.z, w2v, a0[r]); a0[r] = fmaf(uv.w, w3, a0[r]);
                }
            }
            float* og = hout + (size_t)g * (N * D);
            #pragma unroll
            for (int r = 0; r < N; ++r) {
                float v = o_s[r][c] + a0[r];
                og[r*D + c] = v; s3 += v; q3 = fmaf(v, v, q3);
            }
        }
        __syncthreads();
    }
    atomicAdd(&acc[c], s3); atomicAdd(&acc[128 + c], q3);
}

extern "C" void kernel_launch(void* const* d_in, const int* in_sizes, int n_in,
                              void* d_out, int out_size) {
    const float* poses = (const float*)d_in[0];
    const float* emb_w = (const float*)d_in[1];
    const float* emb_b = (const float*)d_in[2];
    const float* cls_w = (const float*)d_in[3];
    const float* cls_b = (const float*)d_in[4];
    const float* PPj[12]; const float* PPi[12];
    for (int i = 0; i < 12; ++i) { PPj[i] = (const float*)d_in[5+i]; PPi[i] = (const float*)d_in[17+i]; }

    float *A, *Bb, *Cc, *A2, *B2, *C2, *acc, *fold, *wT; uint2* wf;
    cudaGetSymbolAddress((void**)&A,    g_A);
    cudaGetSymbolAddress((void**)&Bb,   g_B);
    cudaGetSymbolAddress((void**)&Cc,   g_C);
    cudaGetSymbolAddress((void**)&A2,   g_A2);
    cudaGetSymbolAddress((void**)&B2,   g_B2);
    cudaGetSymbolAddress((void**)&C2,   g_C2);
    cudaGetSymbolAddress((void**)&acc,  g_acc);
    cudaGetSymbolAddress((void**)&fold, g_fold);
    cudaGetSymbolAddress((void**)&wT,   g_wT);
    cudaGetSymbolAddress((void**)&wf,   g_wf);
    const float* foldId = fold + 18 * 256;

    cudaFuncSetAttribute(k1_s1, cudaFuncAttributeMaxDynamicSharedMemorySize, SM1);
    cudaFuncSetAttribute(k2_s1, cudaFuncAttributeMaxDynamicSharedMemorySize, SM2);

    init_kernel<<<18, 256>>>(acc, fold + 18 * 256);

    transpose_kernel<<<192, 256>>>(PPj[0], wT, 128, 128, 49152);
    for (int l = 0; l < 3; ++l) {
        prep_frag<<<48, 256>>>(PPj[2]  + l*49152, wf + l*32768,          48, 128, 12288);
        prep_frag<<<16, 256>>>(PPj[4]  + l*16384, wf + l*32768 + 12288,  16, 128, 4096);
        prep_frag<<<32, 256>>>(PPj[8]  + l*32768, wf + l*32768 + 16384,  32, 128, 8192);
        prep_frag<<<32, 256>>>(PPj[10] + l*32768, wf + l*32768 + 24576,  16, 256, 8192);
    }
    {
        float* wTs = wT + 442368;
        transpose_kernel<<<192, 256>>>(PPi[0],  wTs + 0,      128, 128, 49152);
        transpose_kernel<<<576, 256>>>(PPi[2],  wTs + 49152,  384, 128, 147456);
        transpose_kernel<<<192, 256>>>(PPi[4],  wTs + 196608, 128, 128, 49152);
        transpose_kernel<<<384, 256>>>(PPi[8],  wTs + 245760, 256, 128, 98304);
        transpose_kernel<<<384, 256>>>(PPi[10], wTs + 344064, 128, 256, 98304);
    }

    embed_kernel<<<182784, 256>>>(poses, emb_w, emb_b, A, 46792704);

    // stage 1 (tensor-core, 2 CTAs/SM — proven R9 config)
    const float* foldPrev = foldId;
    for (int l = 0; l < 3; ++l) {
        float* accL = acc + l * 768;
        float* foldL = fold + l * 768;
        k1_s1<<<10752, 256, SM1>>>(A, foldPrev, Bb, Cc, accL,
                                   wT + l*16384, PPj[1] + l*128, PPj[3] + l*384, PPj[5] + l*128,
                                   wf + l*32768, wf + l*32768 + 12288);
        finalize_kernel<<<2, 128>>>(accL, 1.f/365568.f, PPj[6] + l*384, PPj[7] + l*384, foldL,
                                    PPj[6] + l*384 + 128, PPj[7] + l*384 + 128, foldL + 256);
        k2_s1<<<5376, 256, SM2>>>(A, Bb, Cc, foldPrev, foldL, foldL + 256, A, accL + 512,
                                  wf + l*32768 + 16384, PPj[9] + l*256,
                                  wf + l*32768 + 24576, PPj[11] + l*128);
        finalize_kernel<<<1, 128>>>(accL + 512, 1.f/365568.f, PPj[6] + l*384 + 256,
                                    PPj[7] + l*384 + 256, foldL + 512, nullptr, nullptr, nullptr);
        foldPrev = foldL + 512;
    }

    pool1_kernel<<<10752, 256>>>(A, foldPrev, A2, 2752512);

    // stage 2 (scalar)
    foldPrev = foldId;
    float* wTs = wT + 442368;
    for (int l = 0; l < 3; ++l) {
        float* accL = acc + 2304 + l * 768;
        float* foldL = fold + 2304 + l * 768;
        k1_kernel<12, 2><<<896, 128>>>(A2, foldPrev, B2, C2, accL,
                                       wTs + l*16384, PPi[1] + l*128, wTs + 49152 + l*49152,
                                       PPi[3] + l*384, wTs + 196608 + l*16384, PPi[5] + l*128);
        finalize_kernel<<<2, 128>>>(accL, 1.f/21504.f, PPi[6] + l*384, PPi[7] + l*384, foldL,
                                    PPi[6] + l*384 + 128, PPi[7] + l*384 + 128, foldL + 256);
        k2_kernel<12, 2><<<896, 128>>>(B2, C2, foldL, foldL + 256, A2, accL + 512,
                                       wTs + 245760 + l*32768, PPi[9] + l*256,
                                       wTs + 344064 + l*32768, PPi[11] + l*128);
        finalize_kernel<<<1, 128>>>(accL + 512, 1.f/21504.f, PPi[6] + l*384 + 256,
                                    PPi[7] + l*384 + 256, foldL + 512, nullptr, nullptr, nullptr);
        foldPrev = foldL + 512;
    }

    pool2_cls_kernel<<<256, 128>>>(A2, foldPrev, cls_w, cls_b, (float*)d_out);
}

// round 12
// speedup vs baseline: 1.2732x; 1.1078x over previous
#include <cuda_runtime.h>
#include <cuda_fp16.h>
#include <stdint.h>

#define D 128

static __device__ float g_A [46792704];
static __device__ float g_B [46792704];
static __device__ float g_C [46792704];
static __device__ float g_A2[ 2752512];
static __device__ float g_B2[ 2752512];
static __device__ float g_C2[ 2752512];
static __device__ float g_acc [18*256];
static __device__ float g_fold[19*256];
static __device__ float g_wT  [98304];
static __device__ uint2 g_wf  [196608];

__global__ void init_kernel(float* acc, float* foldId) {
    int t = blockIdx.x * blockDim.x + threadIdx.x;
    if (t < 18*256) acc[t] = 0.f;
    if (t < 128) { foldId[t] = 1.f; foldId[128 + t] = 0.f; }
}

__global__ void transpose_kernel(const float* __restrict__ src, float* __restrict__ dst,
                                 int R, int C, int total) {
    int idx = blockIdx.x * blockDim.x + threadIdx.x;
    if (idx >= total) return;
    int m = idx / (R * C), rc = idx - m * (R * C), cc = rc / R, r = rc - cc * R;
    dst[idx] = src[m * R * C + r * C + cc];
}

__global__ void prep_frag(const float* __restrict__ W, uint2* __restrict__ out,
                          int NT, int K, int total) {
    int idx = blockIdx.x * blockDim.x + threadIdx.x;
    if (idx >= total) return;
    int lane = idx & 31, tile = idx >> 5;
    int nt = tile % NT, kt = tile / NT;
    int g = lane >> 2, t = lane & 3;
    const float* w = W + (size_t)(nt * 8 + g) * K + kt * 16 + 2 * t;
    __half2 b0 = __floats2half2_rn(w[0], w[1]);
    __half2 b1 = __floats2half2_rn(w[8], w[9]);
    uint2 o; o.x = *(uint32_t*)&b0; o.y = *(uint32_t*)&b1;
    out[idx] = o;
}

__global__ void embed_kernel(const float* __restrict__ poses, const float* __restrict__ ew,
                             const float* __restrict__ eb, float* __restrict__ out, int total) {
    int idx = blockIdx.x * blockDim.x + threadIdx.x;
    if (idx >= total) return;
    int row = idx >> 7, c = idx & 127;
    float v = fmaf(poses[row*2], ew[2*c], fmaf(poses[row*2+1], ew[2*c+1], eb[c]));
    out[idx] = v > 0.f ? v : 0.01f * v;
}

__global__ void finalize_kernel(const float* __restrict__ acc, float invN,
                                const float* g0, const float* b0, float* f0,
                                const float* g1, const float* b1, float* f1) {
    int set = blockIdx.x, c = threadIdx.x;
    const float* a  = acc + set * 256;
    const float* gg = set ? g1 : g0;
    const float* bb = set ? b1 : b0;
    float* ff = set ? f1 : f0;
    float m = a[c] * invN;
    float v = fmaxf(a[128 + c] * invN - m * m, 0.f);
    float sc = rsqrtf(v + 1e-5f) * gg[c];
    ff[c] = sc;
    ff[128 + c] = fmaf(-m, sc, bb[c]);
}

__global__ void pool1_kernel(const float* __restrict__ hin, const float* __restrict__ fold,
                             float* __restrict__ out, int total) {
    int idx = blockIdx.x * blockDim.x + threadIdx.x;
    if (idx >= total) return;
    int orow = idx >> 7, c = idx & 127;
    const float* base = hin + (size_t)orow * 17 * D + c;
    float s = 0.f;
    #pragma unroll
    for (int j = 0; j < 17; ++j) s += base[j * D];
    out[idx] = fmaf(s * (1.f / 17.f), fold[c], fold[128 + c]);
}

__global__ void pool2_cls_kernel(const float* __restrict__ hin, const float* __restrict__ fold,
                                 const float* __restrict__ cw, const float* __restrict__ cb,
                                 float* __restrict__ out) {
    __shared__ float p_s[D];
    int b = blockIdx.x, c = threadIdx.x;
    const float* base = hin + (size_t)b * 84 * D + c;
    float s = 0.f;
    #pragma unroll 4
    for (int r = 0; r < 84; ++r) s += base[r * D];
    p_s[c] = fmaf(s * (1.f / 84.f), fold[c], fold[128 + c]);
    __syncthreads();
    if (c < 8) {
        float acc = cb[c];
        #pragma unroll 4
        for (int k = 0; k < D; ++k) acc = fmaf(p_s[k], cw[c * D + k], acc);
        out[b * 8 + c] = acc;
    }
}

__device__ __forceinline__ void mma16816(float* c, uint32_t a0, uint32_t a1,
                                         uint32_t a2, uint32_t a3, uint32_t b0, uint32_t b1) {
    asm("mma.sync.aligned.m16n8k16.row.col.f32.f16.f16.f32 "
        "{%0,%1,%2,%3},{%4,%5,%6,%7},{%8,%9},{%0,%1,%2,%3};"
        : "+f"(c[0]), "+f"(c[1]), "+f"(c[2]), "+f"(c[3])
        : "r"(a0), "r"(a1), "r"(a2), "r"(a3), "r"(b0), "r"(b1));
}

template<int KT, int NT>
__device__ __forceinline__ void mtile(const __half* a0p, int lda, const uint2* __restrict__ wf,
                                      int ng, int lane, float acc[4][4]) {
    const __half* a1p = a0p + 8 * lda;
    #pragma unroll
    for (int kt = 0; kt < KT; ++kt) {
        uint32_t a0 = *(const uint32_t*)(a0p + kt*16);
        uint32_t a1 = *(const uint32_t*)(a1p + kt*16);
        uint32_t a2 = *(const uint32_t*)(a0p + kt*16 + 8);
        uint32_t a3 = *(const uint32_t*)(a1p + kt*16 + 8);
        #pragma unroll
        for (int j = 0; j < 4; ++j) {
            uint2 b = wf[(kt*NT + ng*4 + j)*32 + lane];
            mma16816(acc[j], a0, a1, a2, a3, b.x, b.y);
        }
    }
}

// ---------------- stage-1 tensor kernels: 2 graphs (34 rows), 2 CTAs/SM ----
#define O_H16 0
#define O_Q16 13056
#define O_K16 26112
#define O_VT  39168
#define O_P   56576
#define O_SC  73984
#define O_MB  87584
#define O_H32 91680
#define SM1   109632

__global__ __launch_bounds__(256, 2)
void k1_s1(const float* __restrict__ hin, const float* __restrict__ foldIn,
           float* __restrict__ gcnb, float* __restrict__ t2, float* __restrict__ accL,
           const float* __restrict__ gwT, const float* __restrict__ gb,
           const float* __restrict__ qb, const float* __restrict__ ob,
           const uint2* __restrict__ qkvf, const uint2* __restrict__ owf) {
    extern __shared__ char sm[];
    __half (*h16)[136] = (__half(*)[136])(sm + O_H16);
    __half (*q16)[136] = (__half(*)[136])(sm + O_Q16);
    __half (*k16)[136] = (__half(*)[136])(sm + O_K16);
    __half (*vT )[34]  = (__half(*)[34]) (sm + O_VT);
    __half (*pp )[34]  = (__half(*)[34]) (sm + O_P);
    float  (*sc )[25]  = (float(*)[25])  (sm + O_SC);
    float*  mbuf       = (float*)(sm + O_MB);
    float  (*h32)[132] = (float(*)[132]) (sm + O_H32);

    const int tid = threadIdx.x, warp = tid >> 5, lane = tid & 31;
    const int g = lane >> 2, t = lane & 3;
    const int colj = tid & 127;
    const float* hg = hin + (size_t)blockIdx.x * 4352;
    float* t2g = t2 + (size_t)blockIdx.x * 4352;
    const float scIn = foldIn[colj], shIn = foldIn[128 + colj];

    {
        uint4 zz = make_uint4(0,0,0,0);
        uint4* z = (uint4*)(sm + O_VT);
        for (int i = tid; i < 2176; i += 256) z[i] = zz;
        uint4* zh = (uint4*)&h16[34][0];
        for (int i = tid; i < 238; i += 256) zh[i] = zz;
        for (int i = tid; i < 4352; i += 256) {
            int rr = i >> 7;
            float v = fmaf(hg[i], scIn, shIn);
            h32[rr][colj] = v;
            h16[rr][colj] = __float2half_rn(v);
        }
    }
    __syncthreads();
    {
        int gi = tid >> 7, cc = tid & 127;
        float s = 0.f, q = 0.f;
        #pragma unroll
        for (int r = 0; r < 17; ++r) {
            float v = h32[gi*17 + r][cc];
            s += v; q = fmaf(v, v, q);
        }
        mbuf[tid] = s * (1.f / 17.f);
        float* scr = (float*)sc;
        scr[tid] = q;
        scr[256 + tid] = s;
    }
    __syncthreads();
    {
        int gi = tid >> 7, cc = tid & 127;
        float a = gb[cc];
        const float* mrow = mbuf + gi * 128;
        #pragma unroll 4
        for (int k = 0; k < 128; ++k) a = fmaf(mrow[k], gwT[k*128 + cc], a);
        gcnb[(size_t)blockIdx.x * 256 + tid] = a;
        float* scr = (float*)sc;
        float Sh = scr[256 + tid], Sq = scr[tid];
        scr[256 + tid] = fmaf(17.f, a, Sh);
        scr[tid] = fmaf(17.f * a, a, fmaf(2.f * a, Sh, Sq));
    }
    __syncthreads();
    if (tid < 128) {
        float* scr = (float*)sc;
        atomicAdd(&accL[tid],       scr[256 + tid] + scr[384 + tid]);
        atomicAdd(&accL[128 + tid], scr[tid] + scr[tid + 128]);
    }
    // qkv: M=48, N=384, K=128
    for (int item = warp; item < 36; item += 8) {
        int mt = item / 12, ng = item % 12, m0 = mt * 16;
        float acc[4][4] = {};
        mtile<8,48>(&h16[m0 + g][2*t], 136, qkvf, ng, lane, acc);
        int r0 = m0 + g, r1 = r0 + 8;
        #pragma unroll
        for (int j = 0; j < 4; ++j) {
            int nc = ng*32 + j*8 + 2*t;
            float b0 = qb[nc], b1 = qb[nc+1];
            float v00 = acc[j][0]+b0, v01 = acc[j][1]+b1, v10 = acc[j][2]+b0, v11 = acc[j][3]+b1;
            if (nc < 128) {
                *(__half2*)&q16[r0][nc] = __floats2half2_rn(v00, v01);
                *(__half2*)&q16[r1][nc] = __floats2half2_rn(v10, v11);
            } else if (nc < 256) {
                *(__half2*)&k16[r0][nc-128] = __floats2half2_rn(v00, v01);
                *(__half2*)&k16[r1][nc-128] = __floats2half2_rn(v10, v11);
            } else {
                int d = nc - 256;
                if (r0 < 34) { int gi = r0/17, sl = r0 - gi*17;
                    vT[gi*128+d][sl] = __float2half_rn(v00); vT[gi*128+d+1][sl] = __float2half_rn(v01); }
                if (r1 < 34) { int gi = r1/17, sl = r1 - gi*17;
                    vT[gi*128+d][sl] = __float2half_rn(v10); vT[gi*128+d+1][sl] = __float2half_rn(v11); }
            }
        }
    }
    __syncthreads();
    // scores
    for (int item = warp; item < 48; item += 8) {
        int gi = item / 24, r = item % 24, hh = r / 6, r2 = r % 6, mt = r2 / 3, nt = r2 % 3;
        int base = gi * 17;
        float acc[4] = {};
        const __half* a0p = &q16[base + mt*16 + g][hh*32 + 2*t];
        const __half* a1p = a0p + 8*136;
        const __half* br  = &k16[base + nt*8 + g][hh*32 + 2*t];
        #pragma unroll
        for (int kt = 0; kt < 2; ++kt) {
            mma16816(acc, *(const uint32_t*)(a0p+kt*16), *(const uint32_t*)(a1p+kt*16),
                     *(const uint32_t*)(a0p+kt*16+8), *(const uint32_t*)(a1p+kt*16+8),
                     *(const uint32_t*)(br+kt*16), *(const uint32_t*)(br+kt*16+8));
        }
        const float invs = 0.17677669529663687f;
        int q0 = mt*16 + g, ss = nt*8 + 2*t, row = (gi*4 + hh)*17;
        if (q0 < 17)     { sc[row+q0][ss]   = acc[0]*invs; sc[row+q0][ss+1]   = acc[1]*invs; }
        if (q0 + 8 < 17) { sc[row+q0+8][ss] = acc[2]*invs; sc[row+q0+8][ss+1] = acc[3]*invs; }
    }
    __syncthreads();
    for (int idx = tid; idx < 136; idx += 256) {
        int gh = idx / 17, q = idx - gh*17;
        float e[17], mx = -1e30f;
        #pragma unroll
        for (int s = 0; s < 17; ++s) mx = fmaxf(mx, sc[gh*17+q][s]);
        float sum = 0.f;
        #pragma unroll
        for (int s = 0; s < 17; ++s) { e[s] = __expf(sc[gh*17+q][s] - mx); sum += e[s]; }
        float inv = 1.f / sum;
        #pragma unroll
        for (int s = 0; s < 17; ++s) pp[gh*32 + q][s] = __float2half_rn(e[s] * inv);
    }
    __syncthreads();
    // attn @ V -> q16
    for (int item = warp; item < 16; item += 8) {
        int gi = item / 8, r = item % 8, hh = r / 2, mt = r % 2;
        float acc[4][4] = {};
        const __half* a0p = &pp[(gi*4+hh)*32 + mt*16 + g][2*t];
        const __half* a1p = a0p + 8*34;
        #pragma unroll
        for (int kt = 0; kt < 2; ++kt) {
            uint32_t a0 = *(const uint32_t*)(a0p+kt*16), a1 = *(const uint32_t*)(a1p+kt*16);
            uint32_t a2 = *(const uint32_t*)(a0p+kt*16+8), a3 = *(const uint32_t*)(a1p+kt*16+8);
            #pragma unroll
            for (int j = 0; j < 4; ++j) {
                const __half* bp = &vT[gi*128 + hh*32 + j*8 + g][kt*16 + 2*t];
                mma16816(acc[j], a0, a1, a2, a3, *(const uint32_t*)bp, *(const uint32_t*)(bp+8));
            }
        }
        int q0 = mt*16 + g;
        #pragma unroll
        for (int j = 0; j < 4; ++j) {
            int col = hh*32 + j*8 + 2*t;
            if (q0 < 17)     *(__half2*)&q16[gi*17+q0][col]   = __floats2half2_rn(acc[j][0], acc[j][1]);
            if (q0 + 8 < 17) *(__half2*)&q16[gi*17+q0+8][col] = __floats2half2_rn(acc[j][2], acc[j][3]);
        }
    }
    __syncthreads();
    // out-proj + residual -> t2 AND h32
    for (int item = warp; item < 12; item += 8) {
        int mt = item / 4, ng = item % 4, m0 = mt * 16;
        float acc[4][4] = {};
        mtile<8,16>(&q16[m0 + g][2*t], 136, owf, ng, lane, acc);
        int r0 = m0 + g, r1 = r0 + 8;
        #pragma unroll
        for (int j = 0; j < 4; ++j) {
            int nc = ng*32 + j*8 + 2*t;
            float b0 = ob[nc], b1 = ob[nc+1];
            if (r0 < 34) {
                float v0 = acc[j][0] + b0 + h32[r0][nc];
                float v1 = acc[j][1] + b1 + h32[r0][nc+1];
                t2g[r0*128+nc] = v0; t2g[r0*128+nc+1] = v1;
                h32[r0][nc] = v0; h32[r0][nc+1] = v1;
            }
            if (r1 < 34) {
                float v0 = acc[j][2] + b0 + h32[r1][nc];
                float v1 = acc[j][3] + b1 + h32[r1][nc+1];
                t2g[r1*128+nc] = v0; t2g[r1*128+nc+1] = v1;
                h32[r1][nc] = v0; h32[r1][nc+1] = v1;
            }
        }
    }
    __syncthreads();
    {
        float s2 = 0.f, q2 = 0.f;
        for (int i = tid; i < 4352; i += 256) {
            float v = h32[i >> 7][colj];
            s2 += v; q2 = fmaf(v, v, q2);
        }
        mbuf[tid] = s2; mbuf[256 + tid] = q2;
        __syncthreads();
        if (tid < 128) {
            atomicAdd(&accL[256 + tid], mbuf[tid] + mbuf[tid + 128]);
            atomicAdd(&accL[384 + tid], mbuf[256 + tid] + mbuf[384 + tid]);
        }
    }
}

// 4 graphs (68 rows) per block, 2 CTAs/SM
#define P_O16 0
#define P_U16 21760
#define P_O32 64000
#define P_GB  99904
#define SM2   101952

__global__ __launch_bounds__(256, 2)
void k2_s1(const float* __restrict__ hg0, const float* __restrict__ gcnb,
           const float* __restrict__ t2, const float* __restrict__ foldIn,
           const float* __restrict__ fold1, const float* __restrict__ fold2,
           float* __restrict__ hout, float* __restrict__ accL,
           const uint2* __restrict__ w1f, const float* __restrict__ b1v,
           const uint2* __restrict__ w2f, const float* __restrict__ b2v) {
    extern __shared__ char sm[];
    __half (*o16)[136] = (__half(*)[136])(sm + P_O16);
    __half (*u16)[264] = (__half(*)[264])(sm + P_U16);
    float  (*o32)[132] = (float(*)[132]) (sm + P_O32);
    float*  gbuf       = (float*)(sm + P_GB);
    const int tid = threadIdx.x, warp = tid >> 5, lane = tid & 31;
    const int g = lane >> 2, t = lane & 3;
    const int colj = tid & 127;
    const float* hgA = hg0 + (size_t)blockIdx.x * 8704;
    const float* t2g = t2  + (size_t)blockIdx.x * 8704;
    float* og = hout + (size_t)blockIdx.x * 8704;
    const float scIn = foldIn[colj], shIn = foldIn[128 + colj];
    const float sc1 = fold1[colj], sh1 = fold1[128 + colj];
    const float sc2 = fold2[colj], sh2 = fold2[128 + colj];

    for (int j = tid; j < 512; j += 256)
        gbuf[j] = gcnb[(size_t)blockIdx.x * 512 + j];
    {
        uint4 zz = make_uint4(0,0,0,0);
        uint4* z = (uint4*)&o16[68][0];
        for (int i = tid; i < 204; i += 256) z[i] = zz;
    }
    __syncthreads();
    for (int i = tid; i < 8704; i += 256) {
        int rr = i >> 7;
        float t1v = gbuf[(rr/17)*128 + colj] + fmaf(hgA[i], scIn, shIn);
        float o = fmaf(t1v, sc1, sh1) + fmaf(t2g[i], sc2, sh2);
        o32[rr][colj] = o;
        o16[rr][colj] = __float2half_rn(o);
    }
    __syncthreads();
    for (int item = warp; item < 40; item += 8) {
        int mt = item / 8, ng = item % 8, m0 = mt * 16;
        float acc[4][4] = {};
        mtile<8,32>(&o16[m0 + g][2*t], 136, w1f, ng, lane, acc);
        int r0 = m0 + g, r1 = r0 + 8;
        #pragma unroll
        for (int j = 0; j < 4; ++j) {
            int nc = ng*32 + j*8 + 2*t;
            float b0 = b1v[nc], b1 = b1v[nc+1];
            *(__half2*)&u16[r0][nc] = __floats2half2_rn(fmaxf(acc[j][0]+b0, 0.f), fmaxf(acc[j][1]+b1, 0.f));
            *(__half2*)&u16[r1][nc] = __floats2half2_rn(fmaxf(acc[j][2]+b0, 0.f), fmaxf(acc[j][3]+b1, 0.f));
        }
    }
    __syncthreads();
    for (int item = warp; item < 20; item += 8) {
        int mt = item / 4, ng = item % 4, m0 = mt * 16;
        float acc[4][4] = {};
        mtile<16,16>(&u16[m0 + g][2*t], 264, w2f, ng, lane, acc);
        int r0 = m0 + g, r1 = r0 + 8;
        #pragma unroll
        for (int j = 0; j < 4; ++j) {
            int nc = ng*32 + j*8 + 2*t;
            float b0 = b2v[nc], b1 = b2v[nc+1];
            if (r0 < 68) {
                float v0 = acc[j][0] + b0 + o32[r0][nc];
                float v1 = acc[j][1] + b1 + o32[r0][nc+1];
                og[r0*128+nc] = v0; og[r0*128+nc+1] = v1;
                o32[r0][nc] = v0; o32[r0][nc+1] = v1;
            }
            if (r1 < 68) {
                float v0 = acc[j][2] + b0 + o32[r1][nc];
                float v1 = acc[j][3] + b1 + o32[r1][nc+1];
                og[r1*128+nc] = v0; og[r1*128+nc+1] = v1;
                o32[r1][nc] = v0; o32[r1][nc+1] = v1;
            }
        }
    }
    __syncthreads();
    {
        float s3 = 0.f, q3 = 0.f;
        for (int i = tid; i < 8704; i += 256) {
            float v = o32[i >> 7][colj];
            s3 += v; q3 = fmaf(v, v, q3);
        }
        float* red = (float*)u16;
        red[tid] = s3; red[256 + tid] = q3;
        __syncthreads();
        if (tid < 128) {
            atomicAdd(&accL[tid],       red[tid] + red[tid + 128]);
            atomicAdd(&accL[128 + tid], red[256 + tid] + red[384 + tid]);
        }
    }
}

// ========== stage-2 tensor kernels: 4 graphs x 12 nodes = 48 rows ==========
#define B_H16 0
#define B_Q16 13056
#define B_K16 27200
#define B_VT  41344
#define B_P   57728
#define B_SC  65920
#define B_MB  78976
#define B_H32 83072
#define SM1B  108416

__global__ __launch_bounds__(256, 2)
void k1_s2(const float* __restrict__ hin, const float* __restrict__ foldIn,
           float* __restrict__ gcnb, float* __restrict__ t2, float* __restrict__ accL,
           const float* __restrict__ gwT, const float* __restrict__ gb,
           const float* __restrict__ qb, const float* __restrict__ ob,
           const uint2* __restrict__ qkvf, const uint2* __restrict__ owf) {
    extern __shared__ char sm[];
    __half (*h16)[136] = (__half(*)[136])(sm + B_H16);   // [48][136]
    __half (*q16)[136] = (__half(*)[136])(sm + B_Q16);   // [52][136]
    __half (*k16)[136] = (__half(*)[136])(sm + B_K16);   // [52][136]
    __half (*vT )[16]  = (__half(*)[16]) (sm + B_VT);    // [512][16]
    __half (*pp )[16]  = (__half(*)[16]) (sm + B_P);     // [256][16]
    float  (*sc )[17]  = (float(*)[17])  (sm + B_SC);    // [192][17]
    float*  mbuf       = (float*)(sm + B_MB);            // 1024 floats
    float  (*h32)[132] = (float(*)[132]) (sm + B_H32);   // [48][132]

    const int tid = threadIdx.x, warp = tid >> 5, lane = tid & 31;
    const int g = lane >> 2, t = lane & 3;
    const int colj = tid & 127;
    const float* hg = hin + (size_t)blockIdx.x * 6144;
    float* t2g = t2 + (size_t)blockIdx.x * 6144;
    const float scIn = foldIn[colj], shIn = foldIn[128 + colj];

    { // zero vT+pp (24576B) and q16/k16 garbage rows 48-51
        uint4 zz = make_uint4(0,0,0,0);
        uint4* z = (uint4*)(sm + B_VT);
        for (int i = tid; i < 1536; i += 256) z[i] = zz;
        uint4* zq = (uint4*)&q16[48][0];
        for (int i = tid; i < 68; i += 256) zq[i] = zz;
        uint4* zk = (uint4*)&k16[48][0];
        for (int i = tid; i < 68; i += 256) zk[i] = zz;
        for (int i = tid; i < 6144; i += 256) {
            int rr = i >> 7;
            float v = fmaf(hg[i], scIn, shIn);
            h32[rr][colj] = v;
            h16[rr][colj] = __float2half_rn(v);
        }
    }
    __syncthreads();
    { // mean + Sh/Sq (4 graphs x 128 channels)
        float* scr = (float*)sc;
        for (int j = tid; j < 512; j += 256) {
            int gi = j >> 7, cc = j & 127;
            float s = 0.f, q = 0.f;
            #pragma unroll
            for (int r = 0; r < 12; ++r) {
                float v = h32[gi*12 + r][cc];
                s += v; q = fmaf(v, v, q);
            }
            mbuf[j] = s * (1.f / 12.f);
            scr[j] = q; scr[512 + j] = s;
        }
    }
    __syncthreads();
    { // gcn + t1-stats algebra
        float* scr = (float*)sc;
        for (int j = tid; j < 512; j += 256) {
            int gi = j >> 7, cc = j & 127;
            float a = gb[cc];
            const float* mrow = mbuf + gi * 128;
            #pragma unroll 4
            for (int k = 0; k < 128; ++k) a = fmaf(mrow[k], gwT[k*128 + cc], a);
            gcnb[(size_t)blockIdx.x * 512 + j] = a;
            float Sh = scr[512 + j], Sq = scr[j];
            scr[512 + j] = fmaf(12.f, a, Sh);
            scr[j] = fmaf(12.f * a, a, fmaf(2.f * a, Sh, Sq));
        }
    }
    __syncthreads();
    if (tid < 128) {
        float* scr = (float*)sc;
        atomicAdd(&accL[tid],       scr[512+tid] + scr[640+tid] + scr[768+tid] + scr[896+tid]);
        atomicAdd(&accL[128 + tid], scr[tid] + scr[128+tid] + scr[256+tid] + scr[384+tid]);
    }
    // qkv: M=48 (all valid), N=384, K=128: 36 items
    for (int item = warp; item < 36; item += 8) {
        int mt = item / 12, ng = item % 12, m0 = mt * 16;
        float acc[4][4] = {};
        mtile<8,48>(&h16[m0 + g][2*t], 136, qkvf, ng, lane, acc);
        int r0 = m0 + g, r1 = r0 + 8;
        #pragma unroll
        for (int j = 0; j < 4; ++j) {
            int nc = ng*32 + j*8 + 2*t;
            float b0 = qb[nc], b1 = qb[nc+1];
            float v00 = acc[j][0]+b0, v01 = acc[j][1]+b1, v10 = acc[j][2]+b0, v11 = acc[j][3]+b1;
            if (nc < 128) {
                *(__half2*)&q16[r0][nc] = __floats2half2_rn(v00, v01);
                *(__half2*)&q16[r1][nc] = __floats2half2_rn(v10, v11);
            } else if (nc < 256) {
                *(__half2*)&k16[r0][nc-128] = __floats2half2_rn(v00, v01);
                *(__half2*)&k16[r1][nc-128] = __floats2half2_rn(v10, v11);
            } else {
                int d = nc - 256;
                { int gi = r0/12, sl = r0 - gi*12;
                  vT[gi*128+d][sl] = __float2half_rn(v00); vT[gi*128+d+1][sl] = __float2half_rn(v01); }
                { int gi = r1/12, sl = r1 - gi*12;
                  vT[gi*128+d][sl] = __float2half_rn(v10); vT[gi*128+d+1][sl] = __float2half_rn(v11); }
            }
        }
    }
    __syncthreads();
    // scores: 4 graphs x 4 heads x 1 mt x 2 nt = 32 items
    for (int item = warp; item < 32; item += 8) {
        int gi = item / 8, r = item % 8, hh = r / 2, nt = r % 2;
        int base = gi * 12;
        float acc[4] = {};
        const __half* a0p = &q16[base + g][hh*32 + 2*t];
        const __half* a1p = a0p + 8*136;
        const __half* br  = &k16[base + nt*8 + g][hh*32 + 2*t];
        #pragma unroll
        for (int kt = 0; kt < 2; ++kt) {
            mma16816(acc, *(const uint32_t*)(a0p+kt*16), *(const uint32_t*)(a1p+kt*16),
                     *(const uint32_t*)(a0p+kt*16+8), *(const uint32_t*)(a1p+kt*16+8),
                     *(const uint32_t*)(br+kt*16), *(const uint32_t*)(br+kt*16+8));
        }
        const float invs = 0.17677669529663687f;
        int ss = nt*8 + 2*t, row = (gi*4 + hh)*12;
        { sc[row+g][ss] = acc[0]*invs; sc[row+g][ss+1] = acc[1]*invs; }
        if (g + 8 < 12) { sc[row+g+8][ss] = acc[2]*invs; sc[row+g+8][ss+1] = acc[3]*invs; }
    }
    __syncthreads();
    if (tid < 192) { // softmax -> fp16 probs
        int gh = tid / 12, q = tid - gh*12;
        float e[12], mx = -1e30f;
        #pragma unroll
        for (int s = 0; s < 12; ++s) mx = fmaxf(mx, sc[gh*12+q][s]);
        float sum = 0.f;
        #pragma unroll
        for (int s = 0; s < 12; ++s) { e[s] = __expf(sc[gh*12+q][s] - mx); sum += e[s]; }
        float inv = 1.f / sum;
        #pragma unroll
        for (int s = 0; s < 12; ++s) pp[gh*16 + q][s] = __float2half_rn(e[s] * inv);
    }
    __syncthreads();
    // attn @ V -> q16: 4 graphs x 4 heads = 16 items (kt=1 since 12<=16)
    for (int item = warp; item < 16; item += 8) {
        int gi = item / 4, hh = item % 4;
        float acc[4][4] = {};
        const __half* a0p = &pp[(gi*4+hh)*16 + g][2*t];
        const __half* a1p = a0p + 8*16;
        uint32_t a0 = *(const uint32_t*)a0p,       a1 = *(const uint32_t*)a1p;
        uint32_t a2 = *(const uint32_t*)(a0p + 8), a3 = *(const uint32_t*)(a1p + 8);
        #pragma unroll
        for (int j = 0; j < 4; ++j) {
            const __half* bp = &vT[gi*128 + hh*32 + j*8 + g][2*t];
            mma16816(acc[j], a0, a1, a2, a3, *(const uint32_t*)bp, *(const uint32_t*)(bp+8));
        }
        #pragma unroll
        for (int j = 0; j < 4; ++j) {
            int col = hh*32 + j*8 + 2*t;
            *(__half2*)&q16[gi*12+g][col] = __floats2half2_rn(acc[j][0], acc[j][1]);
            if (g + 8 < 12) *(__half2*)&q16[gi*12+g+8][col] = __floats2half2_rn(acc[j][2], acc[j][3]);
        }
    }
    __syncthreads();
    // out-proj + residual -> t2 AND h32: 12 items
    for (int item = warp; item < 12; item += 8) {
        int mt = item / 4, ng = item % 4, m0 = mt * 16;
        float acc[4][4] = {};
        mtile<8,16>(&q16[m0 + g][2*t], 136, owf, ng, lane, acc);
        int r0 = m0 + g, r1 = r0 + 8;
        #pragma unroll
        for (int j = 0; j < 4; ++j) {
            int nc = ng*32 + j*8 + 2*t;
            float b0 = ob[nc], b1 = ob[nc+1];
            {
                float v0 = acc[j][0] + b0 + h32[r0][nc];
                float v1 = acc[j][1] + b1 + h32[r0][nc+1];
                t2g[r0*128+nc] = v0; t2g[r0*128+nc+1] = v1;
                h32[r0][nc] = v0; h32[r0][nc+1] = v1;
            }
            {
                float v0 = acc[j][2] + b0 + h32[r1][nc];
                float v1 = acc[j][3] + b1 + h32[r1][nc+1];
                t2g[r1*128+nc] = v0; t2g[r1*128+nc+1] = v1;
                h32[r1][nc] = v0; h32[r1][nc+1] = v1;
            }
        }
    }
    __syncthreads();
    { // t2 stats
        float s2 = 0.f, q2 = 0.f;
        for (int i = tid; i < 6144; i += 256) {
            float v = h32[i >> 7][colj];
            s2 += v; q2 = fmaf(v, v, q2);
        }
        mbuf[tid] = s2; mbuf[256 + tid] = q2;
        __syncthreads();
        if (tid < 128) {
            atomicAdd(&accL[256 + tid], mbuf[tid] + mbuf[tid + 128]);
            atomicAdd(&accL[384 + tid], mbuf[256 + tid] + mbuf[384 + tid]);
        }
    }
}

#define C_O16 0
#define C_U16 13056
#define C_O32 38400
#define C_GB  63744
#define SM2B  65792

__global__ __launch_bounds__(256, 2)
void k2_s2(const float* __restrict__ hg0, const float* __restrict__ gcnb,
           const float* __restrict__ t2, const float* __restrict__ foldIn,
           const float* __restrict__ fold1, const float* __restrict__ fold2,
           float* __restrict__ hout, float* __restrict__ accL,
           const uint2* __restrict__ w1f, const float* __restrict__ b1v,
           const uint2* __restrict__ w2f, const float* __restrict__ b2v) {
    extern __shared__ char sm[];
    __half (*o16)[136] = (__half(*)[136])(sm + C_O16);   // [48][136]
    __half (*u16)[264] = (__half(*)[264])(sm + C_U16);   // [48][264]
    float  (*o32)[132] = (float(*)[132]) (sm + C_O32);   // [48][132]
    float*  gbuf       = (float*)(sm + C_GB);            // 512 floats
    const int tid = threadIdx.x, warp = tid >> 5, lane = tid & 31;
    const int g = lane >> 2, t = lane & 3;
    const int colj = tid & 127;
    const float* hgA = hg0 + (size_t)blockIdx.x * 6144;
    const float* t2g = t2  + (size_t)blockIdx.x * 6144;
    float* og = hout + (size_t)blockIdx.x * 6144;
    const float scIn = foldIn[colj], shIn = foldIn[128 + colj];
    const float sc1 = fold1[colj], sh1 = fold1[128 + colj];
    const float sc2 = fold2[colj], sh2 = fold2[128 + colj];

    if (tid < 256) gbuf[tid] = gcnb[(size_t)blockIdx.x * 512 + tid];
    if (tid < 256) gbuf[256 + tid] = gcnb[(size_t)blockIdx.x * 512 + 256 + tid];
    __syncthreads();
    for (int i = tid; i < 6144; i += 256) {
        int rr = i >> 7;
        float t1v = gbuf[(rr/12)*128 + colj] + fmaf(hgA[i], scIn, shIn);
        float o = fmaf(t1v, sc1, sh1) + fmaf(t2g[i], sc2, sh2);
        o32[rr][colj] = o;
        o16[rr][colj] = __float2half_rn(o);
    }
    __syncthreads();
    // mlp1: M=48, N=256, K=128 (+ReLU): 24 items
    for (int item = warp; item < 24; item += 8) {
        int mt = item / 8, ng = item % 8, m0 = mt * 16;
        float acc[4][4] = {};
        mtile<8,32>(&o16[m0 + g][2*t], 136, w1f, ng, lane, acc);
        int r0 = m0 + g, r1 = r0 + 8;
        #pragma unroll
        for (int j = 0; j < 4; ++j) {
            int nc = ng*32 + j*8 + 2*t;
            float b0 = b1v[nc], b1 = b1v[nc+1];
            *(__half2*)&u16[r0][nc] = __floats2half2_rn(fmaxf(acc[j][0]+b0, 0.f), fmaxf(acc[j][1]+b1, 0.f));
            *(__half2*)&u16[r1][nc] = __floats2half2_rn(fmaxf(acc[j][2]+b0, 0.f), fmaxf(acc[j][3]+b1, 0.f));
        }
    }
    __syncthreads();
    // mlp2: M=48, N=128, K=256 + residual: 12 items
    for (int item = warp; item < 12; item += 8) {
        int mt = item / 4, ng = item % 4, m0 = mt * 16;
        float acc[4][4] = {};
        mtile<16,16>(&u16[m0 + g][2*t], 264, w2f, ng, lane, acc);
        int r0 = m0 + g, r1 = r0 + 8;
        #pragma unroll
        for (int j = 0; j < 4; ++j) {
            int nc = ng*32 + j*8 + 2*t;
            float b0 = b2v[nc], b1 = b2v[nc+1];
            {
                float v0 = acc[j][0] + b0 + o32[r0][nc];
                float v1 = acc[j][1] + b1 + o32[r0][nc+1];
                og[r0*128+nc] = v0; og[r0*128+nc+1] = v1;
                o32[r0][nc] = v0; o32[r0][nc+1] = v1;
            }
            {
                float v0 = acc[j][2] + b0 + o32[r1][nc];
                float v1 = acc[j][3] + b1 + o32[r1][nc+1];
                og[r1*128+nc] = v0; og[r1*128+nc+1] = v1;
                o32[r1][nc] = v0; o32[r1][nc+1] = v1;
            }
        }
    }
    __syncthreads();
    {
        float s3 = 0.f, q3 = 0.f;
        for (int i = tid; i < 6144; i += 256) {
            float v = o32[i >> 7][colj];
            s3 += v; q3 = fmaf(v, v, q3);
        }
        float* red = (float*)u16;
        red[tid] = s3; red[256 + tid] = q3;
        __syncthreads();
        if (tid < 128) {
            atomicAdd(&accL[tid],       red[tid] + red[tid + 128]);
            atomicAdd(&accL[128 + tid], red[256 + tid] + red[384 + tid]);
        }
    }
}

extern "C" void kernel_launch(void* const* d_in, const int* in_sizes, int n_in,
                              void* d_out, int out_size) {
    const float* poses = (const float*)d_in[0];
    const float* emb_w = (const float*)d_in[1];
    const float* emb_b = (const float*)d_in[2];
    const float* cls_w = (const float*)d_in[3];
    const float* cls_b = (const float*)d_in[4];
    const float* PPj[12]; const float* PPi[12];
    for (int i = 0; i < 12; ++i) { PPj[i] = (const float*)d_in[5+i]; PPi[i] = (const float*)d_in[17+i]; }

    float *A, *Bb, *Cc, *A2, *B2, *C2, *acc, *fold, *wT; uint2* wf;
    cudaGetSymbolAddress((void**)&A,    g_A);
    cudaGetSymbolAddress((void**)&Bb,   g_B);
    cudaGetSymbolAddress((void**)&Cc,   g_C);
    cudaGetSymbolAddress((void**)&A2,   g_A2);
    cudaGetSymbolAddress((void**)&B2,   g_B2);
    cudaGetSymbolAddress((void**)&C2,   g_C2);
    cudaGetSymbolAddress((void**)&acc,  g_acc);
    cudaGetSymbolAddress((void**)&fold, g_fold);
    cudaGetSymbolAddress((void**)&wT,   g_wT);
    cudaGetSymbolAddress((void**)&wf,   g_wf);
    const float* foldId = fold + 18 * 256;
    uint2* wf2 = wf + 98304;

    cudaFuncSetAttribute(k1_s1, cudaFuncAttributeMaxDynamicSharedMemorySize, SM1);
    cudaFuncSetAttribute(k2_s1, cudaFuncAttributeMaxDynamicSharedMemorySize, SM2);
    cudaFuncSetAttribute(k1_s2, cudaFuncAttributeMaxDynamicSharedMemorySize, SM1B);
    cudaFuncSetAttribute(k2_s2, cudaFuncAttributeMaxDynamicSharedMemorySize, SM2B);

    init_kernel<<<18, 256>>>(acc, fold + 18 * 256);

    transpose_kernel<<<192, 256>>>(PPj[0], wT, 128, 128, 49152);
    transpose_kernel<<<192, 256>>>(PPi[0], wT + 49152, 128, 128, 49152);
    for (int l = 0; l < 3; ++l) {
        prep_frag<<<48, 256>>>(PPj[2]  + l*49152, wf + l*32768,          48, 128, 12288);
        prep_frag<<<16, 256>>>(PPj[4]  + l*16384, wf + l*32768 + 12288,  16, 128, 4096);
        prep_frag<<<32, 256>>>(PPj[8]  + l*32768, wf + l*32768 + 16384,  32, 128, 8192);
        prep_frag<<<32, 256>>>(PPj[10] + l*32768, wf + l*32768 + 24576,  16, 256, 8192);
        prep_frag<<<48, 256>>>(PPi[2]  + l*49152, wf2 + l*32768,         48, 128, 12288);
        prep_frag<<<16, 256>>>(PPi[4]  + l*16384, wf2 + l*32768 + 12288, 16, 128, 4096);
        prep_frag<<<32, 256>>>(PPi[8]  + l*32768, wf2 + l*32768 + 16384, 32, 128, 8192);
        prep_frag<<<32, 256>>>(PPi[10] + l*32768, wf2 + l*32768 + 24576, 16, 256, 8192);
    }

    embed_kernel<<<182784, 256>>>(poses, emb_w, emb_b, A, 46792704);

    // stage 1 (tensor-core, 2 CTAs/SM)
    const float* foldPrev = foldId;
    for (int l = 0; l < 3; ++l) {
        float* accL = acc + l * 768;
        float* foldL = fold + l * 768;
        k1_s1<<<10752, 256, SM1>>>(A, foldPrev, Bb, Cc, accL,
                                   wT + l*16384, PPj[1] + l*128, PPj[3] + l*384, PPj[5] + l*128,
                                   wf + l*32768, wf + l*32768 + 12288);
        finalize_kernel<<<2, 128>>>(accL, 1.f/365568.f, PPj[6] + l*384, PPj[7] + l*384, foldL,
                                    PPj[6] + l*384 + 128, PPj[7] + l*384 + 128, foldL + 256);
        k2_s1<<<5376, 256, SM2>>>(A, Bb, Cc, foldPrev, foldL, foldL + 256, A, accL + 512,
                                  wf + l*32768 + 16384, PPj[9] + l*256,
                                  wf + l*32768 + 24576, PPj[11] + l*128);
        finalize_kernel<<<1, 128>>>(accL + 512, 1.f/365568.f, PPj[6] + l*384 + 256,
                                    PPj[7] + l*384 + 256, foldL + 512, nullptr, nullptr, nullptr);
        foldPrev = foldL + 512;
    }

    pool1_kernel<<<10752, 256>>>(A, foldPrev, A2, 2752512);

    // stage 2 (tensor-core, 4 graphs x 12 nodes per block)
    foldPrev = foldId;
    for (int l = 0; l < 3; ++l) {
        float* accL = acc + 2304 + l * 768;
        float* foldL = fold + 2304 + l * 768;
        k1_s2<<<448, 256, SM1B>>>(A2, foldPrev, B2, C2, accL,
                                  wT + 49152 + l*16384, PPi[1] + l*128, PPi[3] + l*384, PPi[5] + l*128,
                                  wf2 + l*32768, wf2 + l*32768 + 12288);
        finalize_kernel<<<2, 128>>>(accL, 1.f/21504.f, PPi[6] + l*384, PPi[7] + l*384, foldL,
                                    PPi[6] + l*384 + 128, PPi[7] + l*384 + 128, foldL + 256);
        k2_s2<<<448, 256, SM2B>>>(A2, B2, C2, foldPrev, foldL, foldL + 256, A2, accL + 512,
                                  wf2 + l*32768 + 16384, PPi[9] + l*256,
                                  wf2 + l*32768 + 24576, PPi[11] + l*128);
        finalize_kernel<<<1, 128>>>(accL + 512, 1.f/21504.f, PPi[6] + l*384 + 256,
                                    PPi[7] + l*384 + 256, foldL + 512, nullptr, nullptr, nullptr);
        foldPrev = foldL + 512;
    }

    pool2_cls_kernel<<<256, 128>>>(A2, foldPrev, cls_w, cls_b, (float*)d_out);
}

// round 13
// speedup vs baseline: 1.3545x; 1.0638x over previous
#include <cuda_runtime.h>
#include <cuda_fp16.h>
#include <stdint.h>

#define D 128

static __device__ float g_A [46792704];
static __device__ float g_B [46792704];
static __device__ float g_C [46792704];
static __device__ float g_A2[ 2752512];
static __device__ float g_B2[ 2752512];
static __device__ float g_C2[ 2752512];
static __device__ float g_acc [18*256];
static __device__ float g_fold[19*256];
static __device__ float g_wT  [98304];
static __device__ uint2 g_wf  [196608];

__global__ void init_kernel(float* acc, float* foldId) {
    int t = blockIdx.x * blockDim.x + threadIdx.x;
    if (t < 18*256) acc[t] = 0.f;
    if (t < 128) { foldId[t] = 1.f; foldId[128 + t] = 0.f; }
}

__global__ void transpose_kernel(const float* __restrict__ src, float* __restrict__ dst,
                                 int R, int C, int total) {
    int idx = blockIdx.x * blockDim.x + threadIdx.x;
    if (idx >= total) return;
    int m = idx / (R * C), rc = idx - m * (R * C), cc = rc / R, r = rc - cc * R;
    dst[idx] = src[m * R * C + r * C + cc];
}

__global__ void prep_frag(const float* __restrict__ W, uint2* __restrict__ out,
                          int NT, int K, int total) {
    int idx = blockIdx.x * blockDim.x + threadIdx.x;
    if (idx >= total) return;
    int lane = idx & 31, tile = idx >> 5;
    int nt = tile % NT, kt = tile / NT;
    int g = lane >> 2, t = lane & 3;
    const float* w = W + (size_t)(nt * 8 + g) * K + kt * 16 + 2 * t;
    __half2 b0 = __floats2half2_rn(w[0], w[1]);
    __half2 b1 = __floats2half2_rn(w[8], w[9]);
    uint2 o; o.x = *(uint32_t*)&b0; o.y = *(uint32_t*)&b1;
    out[idx] = o;
}

__global__ void finalize_kernel(const float* __restrict__ acc, float invN,
                                const float* g0, const float* b0, float* f0,
                                const float* g1, const float* b1, float* f1) {
    int set = blockIdx.x, c = threadIdx.x;
    const float* a  = acc + set * 256;
    const float* gg = set ? g1 : g0;
    const float* bb = set ? b1 : b0;
    float* ff = set ? f1 : f0;
    float m = a[c] * invN;
    float v = fmaxf(a[128 + c] * invN - m * m, 0.f);
    float sc = rsqrtf(v + 1e-5f) * gg[c];
    ff[c] = sc;
    ff[128 + c] = fmaf(-m, sc, bb[c]);
}

__global__ void pool2_cls_kernel(const float* __restrict__ hin, const float* __restrict__ fold,
                                 const float* __restrict__ cw, const float* __restrict__ cb,
                                 float* __restrict__ out) {
    __shared__ float p_s[D];
    int b = blockIdx.x, c = threadIdx.x;
    const float* base = hin + (size_t)b * 84 * D + c;
    float s = 0.f;
    #pragma unroll 4
    for (int r = 0; r < 84; ++r) s += base[r * D];
    p_s[c] = fmaf(s * (1.f / 84.f), fold[c], fold[128 + c]);
    __syncthreads();
    if (c < 8) {
        float acc = cb[c];
        #pragma unroll 4
        for (int k = 0; k < D; ++k) acc = fmaf(p_s[k], cw[c * D + k], acc);
        out[b * 8 + c] = acc;
    }
}

__device__ __forceinline__ void mma16816(float* c, uint32_t a0, uint32_t a1,
                                         uint32_t a2, uint32_t a3, uint32_t b0, uint32_t b1) {
    asm("mma.sync.aligned.m16n8k16.row.col.f32.f16.f16.f32 "
        "{%0,%1,%2,%3},{%4,%5,%6,%7},{%8,%9},{%0,%1,%2,%3};"
        : "+f"(c[0]), "+f"(c[1]), "+f"(c[2]), "+f"(c[3])
        : "r"(a0), "r"(a1), "r"(a2), "r"(a3), "r"(b0), "r"(b1));
}

template<int KT, int NT>
__device__ __forceinline__ void mtile(const __half* a0p, int lda, const uint2* __restrict__ wf,
                                      int ng, int lane, float acc[4][4]) {
    const __half* a1p = a0p + 8 * lda;
    #pragma unroll
    for (int kt = 0; kt < KT; ++kt) {
        uint32_t a0 = *(const uint32_t*)(a0p + kt*16);
        uint32_t a1 = *(const uint32_t*)(a1p + kt*16);
        uint32_t a2 = *(const uint32_t*)(a0p + kt*16 + 8);
        uint32_t a3 = *(const uint32_t*)(a1p + kt*16 + 8);
        #pragma unroll
        for (int j = 0; j < 4; ++j) {
            uint2 b = wf[(kt*NT + ng*4 + j)*32 + lane];
            mma16816(acc[j], a0, a1, a2, a3, b.x, b.y);
        }
    }
}

// ---------------- stage-1 tensor kernels: 2 graphs (34 rows), 2 CTAs/SM ----
#define O_H16 0
#define O_Q16 13056
#define O_K16 26112
#define O_VT  39168
#define O_P   56576
#define O_SC  73984
#define O_MB  87584
#define O_H32 91680
#define SM1   109632

__global__ __launch_bounds__(256, 2)
void k1_s1(const float* __restrict__ hin, const float* __restrict__ foldIn,
           float* __restrict__ gcnb, float* __restrict__ t2, float* __restrict__ accL,
           const float* __restrict__ gwT, const float* __restrict__ gb,
           const float* __restrict__ qb, const float* __restrict__ ob,
           const uint2* __restrict__ qkvf, const uint2* __restrict__ owf,
           const float* __restrict__ poses, const float* __restrict__ ew,
           const float* __restrict__ eb) {
    extern __shared__ char sm[];
    __half (*h16)[136] = (__half(*)[136])(sm + O_H16);
    __half (*q16)[136] = (__half(*)[136])(sm + O_Q16);
    __half (*k16)[136] = (__half(*)[136])(sm + O_K16);
    __half (*vT )[34]  = (__half(*)[34]) (sm + O_VT);
    __half (*pp )[34]  = (__half(*)[34]) (sm + O_P);
    float  (*sc )[25]  = (float(*)[25])  (sm + O_SC);
    float*  mbuf       = (float*)(sm + O_MB);
    float  (*h32)[132] = (float(*)[132]) (sm + O_H32);

    const int tid = threadIdx.x, warp = tid >> 5, lane = tid & 31;
    const int g = lane >> 2, t = lane & 3;
    const int colj = tid & 127;
    const float* hg = hin + (size_t)blockIdx.x * 4352;
    float* t2g = t2 + (size_t)blockIdx.x * 4352;
    const float scIn = foldIn[colj], shIn = foldIn[128 + colj];

    {
        uint4 zz = make_uint4(0,0,0,0);
        uint4* z = (uint4*)(sm + O_VT);
        for (int i = tid; i < 2176; i += 256) z[i] = zz;
        uint4* zh = (uint4*)&h16[34][0];
        for (int i = tid; i < 238; i += 256) zh[i] = zz;
        if (poses) { // layer 0: fused embed (identity fold)
            float ewx = ew[2*colj], ewy = ew[2*colj + 1], ebc = eb[colj];
            for (int i = tid; i < 4352; i += 256) {
                int rr = i >> 7;
                int row = blockIdx.x * 34 + rr;
                float v = fmaf(poses[row*2], ewx, fmaf(poses[row*2 + 1], ewy, ebc));
                v = v > 0.f ? v : 0.01f * v;
                h32[rr][colj] = v;
                h16[rr][colj] = __float2half_rn(v);
            }
        } else {
            for (int i = tid; i < 4352; i += 256) {
                int rr = i >> 7;
                float v = fmaf(hg[i], scIn, shIn);
                h32[rr][colj] = v;
                h16[rr][colj] = __float2half_rn(v);
            }
        }
    }
    __syncthreads();
    {
        int gi = tid >> 7, cc = tid & 127;
        float s = 0.f, q = 0.f;
        #pragma unroll
        for (int r = 0; r < 17; ++r) {
            float v = h32[gi*17 + r][cc];
            s += v; q = fmaf(v, v, q);
        }
        mbuf[tid] = s * (1.f / 17.f);
        float* scr = (float*)sc;
        scr[tid] = q;
        scr[256 + tid] = s;
    }
    __syncthreads();
    {
        int gi = tid >> 7, cc = tid & 127;
        float a = gb[cc];
        const float* mrow = mbuf + gi * 128;
        #pragma unroll 4
        for (int k = 0; k < 128; ++k) a = fmaf(mrow[k], gwT[k*128 + cc], a);
        gcnb[(size_t)blockIdx.x * 256 + tid] = a;
        float* scr = (float*)sc;
        float Sh = scr[256 + tid], Sq = scr[tid];
        scr[256 + tid] = fmaf(17.f, a, Sh);
        scr[tid] = fmaf(17.f * a, a, fmaf(2.f * a, Sh, Sq));
    }
    __syncthreads();
    if (tid < 128) {
        float* scr = (float*)sc;
        atomicAdd(&accL[tid],       scr[256 + tid] + scr[384 + tid]);
        atomicAdd(&accL[128 + tid], scr[tid] + scr[tid + 128]);
    }
    // qkv: M=48, N=384, K=128
    for (int item = warp; item < 36; item += 8) {
        int mt = item / 12, ng = item % 12, m0 = mt * 16;
        float acc[4][4] = {};
        mtile<8,48>(&h16[m0 + g][2*t], 136, qkvf, ng, lane, acc);
        int r0 = m0 + g, r1 = r0 + 8;
        #pragma unroll
        for (int j = 0; j < 4; ++j) {
            int nc = ng*32 + j*8 + 2*t;
            float b0 = qb[nc], b1 = qb[nc+1];
            float v00 = acc[j][0]+b0, v01 = acc[j][1]+b1, v10 = acc[j][2]+b0, v11 = acc[j][3]+b1;
            if (nc < 128) {
                *(__half2*)&q16[r0][nc] = __floats2half2_rn(v00, v01);
                *(__half2*)&q16[r1][nc] = __floats2half2_rn(v10, v11);
            } else if (nc < 256) {
                *(__half2*)&k16[r0][nc-128] = __floats2half2_rn(v00, v01);
                *(__half2*)&k16[r1][nc-128] = __floats2half2_rn(v10, v11);
            } else {
                int d = nc - 256;
                if (r0 < 34) { int gi = r0/17, sl = r0 - gi*17;
                    vT[gi*128+d][sl] = __float2half_rn(v00); vT[gi*128+d+1][sl] = __float2half_rn(v01); }
                if (r1 < 34) { int gi = r1/17, sl = r1 - gi*17;
                    vT[gi*128+d][sl] = __float2half_rn(v10); vT[gi*128+d+1][sl] = __float2half_rn(v11); }
            }
        }
    }
    __syncthreads();
    // scores
    for (int item = warp; item < 48; item += 8) {
        int gi = item / 24, r = item % 24, hh = r / 6, r2 = r % 6, mt = r2 / 3, nt = r2 % 3;
        int base = gi * 17;
        float acc[4] = {};
        const __half* a0p = &q16[base + mt*16 + g][hh*32 + 2*t];
        const __half* a1p = a0p + 8*136;
        const __half* br  = &k16[base + nt*8 + g][hh*32 + 2*t];
        #pragma unroll
        for (int kt = 0; kt < 2; ++kt) {
            mma16816(acc, *(const uint32_t*)(a0p+kt*16), *(const uint32_t*)(a1p+kt*16),
                     *(const uint32_t*)(a0p+kt*16+8), *(const uint32_t*)(a1p+kt*16+8),
                     *(const uint32_t*)(br+kt*16), *(const uint32_t*)(br+kt*16+8));
        }
        const float invs = 0.17677669529663687f;
        int q0 = mt*16 + g, ss = nt*8 + 2*t, row = (gi*4 + hh)*17;
        if (q0 < 17)     { sc[row+q0][ss]   = acc[0]*invs; sc[row+q0][ss+1]   = acc[1]*invs; }
        if (q0 + 8 < 17) { sc[row+q0+8][ss] = acc[2]*invs; sc[row+q0+8][ss+1] = acc[3]*invs; }
    }
    __syncthreads();
    for (int idx = tid; idx < 136; idx += 256) {
        int gh = idx / 17, q = idx - gh*17;
        float e[17], mx = -1e30f;
        #pragma unroll
        for (int s = 0; s < 17; ++s) mx = fmaxf(mx, sc[gh*17+q][s]);
        float sum = 0.f;
        #pragma unroll
        for (int s = 0; s < 17; ++s) { e[s] = __expf(sc[gh*17+q][s] - mx); sum += e[s]; }
        float inv = 1.f / sum;
        #pragma unroll
        for (int s = 0; s < 17; ++s) pp[gh*32 + q][s] = __float2half_rn(e[s] * inv);
    }
    __syncthreads();
    // attn @ V -> q16
    for (int item = warp; item < 16; item += 8) {
        int gi = item / 8, r = item % 8, hh = r / 2, mt = r % 2;
        float acc[4][4] = {};
        const __half* a0p = &pp[(gi*4+hh)*32 + mt*16 + g][2*t];
        const __half* a1p = a0p + 8*34;
        #pragma unroll
        for (int kt = 0; kt < 2; ++kt) {
            uint32_t a0 = *(const uint32_t*)(a0p+kt*16), a1 = *(const uint32_t*)(a1p+kt*16);
            uint32_t a2 = *(const uint32_t*)(a0p+kt*16+8), a3 = *(const uint32_t*)(a1p+kt*16+8);
            #pragma unroll
            for (int j = 0; j < 4; ++j) {
                const __half* bp = &vT[gi*128 + hh*32 + j*8 + g][kt*16 + 2*t];
                mma16816(acc[j], a0, a1, a2, a3, *(const uint32_t*)bp, *(const uint32_t*)(bp+8));
            }
        }
        int q0 = mt*16 + g;
        #pragma unroll
        for (int j = 0; j < 4; ++j) {
            int col = hh*32 + j*8 + 2*t;
            if (q0 < 17)     *(__half2*)&q16[gi*17+q0][col]   = __floats2half2_rn(acc[j][0], acc[j][1]);
            if (q0 + 8 < 17) *(__half2*)&q16[gi*17+q0+8][col] = __floats2half2_rn(acc[j][2], acc[j][3]);
        }
    }
    __syncthreads();
    // out-proj + residual -> t2 AND h32
    for (int item = warp; item < 12; item += 8) {
        int mt = item / 4, ng = item % 4, m0 = mt * 16;
        float acc[4][4] = {};
        mtile<8,16>(&q16[m0 + g][2*t], 136, owf, ng, lane, acc);
        int r0 = m0 + g, r1 = r0 + 8;
        #pragma unroll
        for (int j = 0; j < 4; ++j) {
            int nc = ng*32 + j*8 + 2*t;
            float b0 = ob[nc], b1 = ob[nc+1];
            if (r0 < 34) {
                float v0 = acc[j][0] + b0 + h32[r0][nc];
                float v1 = acc[j][1] + b1 + h32[r0][nc+1];
                t2g[r0*128+nc] = v0; t2g[r0*128+nc+1] = v1;
                h32[r0][nc] = v0; h32[r0][nc+1] = v1;
            }
            if (r1 < 34) {
                float v0 = acc[j][2] + b0 + h32[r1][nc];
                float v1 = acc[j][3] + b1 + h32[r1][nc+1];
                t2g[r1*128+nc] = v0; t2g[r1*128+nc+1] = v1;
                h32[r1][nc] = v0; h32[r1][nc+1] = v1;
            }
        }
    }
    __syncthreads();
    {
        float s2 = 0.f, q2 = 0.f;
        for (int i = tid; i < 4352; i += 256) {
            float v = h32[i >> 7][colj];
            s2 += v; q2 = fmaf(v, v, q2);
        }
        mbuf[tid] = s2; mbuf[256 + tid] = q2;
        __syncthreads();
        if (tid < 128) {
            atomicAdd(&accL[256 + tid], mbuf[tid] + mbuf[tid + 128]);
            atomicAdd(&accL[384 + tid], mbuf[256 + tid] + mbuf[384 + tid]);
        }
    }
}

// 4 graphs (68 rows) per block, 2 CTAs/SM
#define P_O16 0
#define P_U16 21760
#define P_O32 64000
#define P_GB  99904
#define SM2   101952

__global__ __launch_bounds__(256, 2)
void k2_s1(const float* __restrict__ hg0, const float* __restrict__ gcnb,
           const float* __restrict__ t2, const float* __restrict__ foldIn,
           const float* __restrict__ fold1, const float* __restrict__ fold2,
           float* __restrict__ hout, float* __restrict__ accL,
           const uint2* __restrict__ w1f, const float* __restrict__ b1v,
           const uint2* __restrict__ w2f, const float* __restrict__ b2v,
           const float* __restrict__ poses, const float* __restrict__ ew,
           const float* __restrict__ eb, float* __restrict__ pool_out) {
    extern __shared__ char sm[];
    __half (*o16)[136] = (__half(*)[136])(sm + P_O16);
    __half (*u16)[264] = (__half(*)[264])(sm + P_U16);
    float  (*o32)[132] = (float(*)[132]) (sm + P_O32);
    float*  gbuf       = (float*)(sm + P_GB);
    const int tid = threadIdx.x, warp = tid >> 5, lane = tid & 31;
    const int g = lane >> 2, t = lane & 3;
    const int colj = tid & 127;
    const float* hgA = hg0 + (size_t)blockIdx.x * 8704;
    const float* t2g = t2  + (size_t)blockIdx.x * 8704;
    float* og = hout + (size_t)blockIdx.x * 8704;
    const float scIn = foldIn[colj], shIn = foldIn[128 + colj];
    const float sc1 = fold1[colj], sh1 = fold1[128 + colj];
    const float sc2 = fold2[colj], sh2 = fold2[128 + colj];

    for (int j = tid; j < 512; j += 256)
        gbuf[j] = gcnb[(size_t)blockIdx.x * 512 + j];
    {
        uint4 zz = make_uint4(0,0,0,0);
        uint4* z = (uint4*)&o16[68][0];
        for (int i = tid; i < 204; i += 256) z[i] = zz;
    }
    __syncthreads();
    if (poses) { // layer 0: recompute embed (identity input fold)
        float ewx = ew[2*colj], ewy = ew[2*colj + 1], ebc = eb[colj];
        for (int i = tid; i < 8704; i += 256) {
            int rr = i >> 7;
            int row = blockIdx.x * 68 + rr;
            float hv = fmaf(poses[row*2], ewx, fmaf(poses[row*2 + 1], ewy, ebc));
            hv = hv > 0.f ? hv : 0.01f * hv;
            float t1v = gbuf[(rr/17)*128 + colj] + hv;
            float o = fmaf(t1v, sc1, sh1) + fmaf(t2g[i], sc2, sh2);
            o32[rr][colj] = o;
            o16[rr][colj] = __float2half_rn(o);
        }
    } else {
        for (int i = tid; i < 8704; i += 256) {
            int rr = i >> 7;
            float t1v = gbuf[(rr/17)*128 + colj] + fmaf(hgA[i], scIn, shIn);
            float o = fmaf(t1v, sc1, sh1) + fmaf(t2g[i], sc2, sh2);
            o32[rr][colj] = o;
            o16[rr][colj] = __float2half_rn(o);
        }
    }
    __syncthreads();
    for (int item = warp; item < 40; item += 8) {
        int mt = item / 8, ng = item % 8, m0 = mt * 16;
        float acc[4][4] = {};
        mtile<8,32>(&o16[m0 + g][2*t], 136, w1f, ng, lane, acc);
        int r0 = m0 + g, r1 = r0 + 8;
        #pragma unroll
        for (int j = 0; j < 4; ++j) {
            int nc = ng*32 + j*8 + 2*t;
            float b0 = b1v[nc], b1 = b1v[nc+1];
            *(__half2*)&u16[r0][nc] = __floats2half2_rn(fmaxf(acc[j][0]+b0, 0.f), fmaxf(acc[j][1]+b1, 0.f));
            *(__half2*)&u16[r1][nc] = __floats2half2_rn(fmaxf(acc[j][2]+b0, 0.f), fmaxf(acc[j][3]+b1, 0.f));
        }
    }
    __syncthreads();
    for (int item = warp; item < 20; item += 8) {
        int mt = item / 4, ng = item % 4, m0 = mt * 16;
        float acc[4][4] = {};
        mtile<16,16>(&u16[m0 + g][2*t], 264, w2f, ng, lane, acc);
        int r0 = m0 + g, r1 = r0 + 8;
        #pragma unroll
        for (int j = 0; j < 4; ++j) {
            int nc = ng*32 + j*8 + 2*t;
            float b0 = b2v[nc], b1 = b2v[nc+1];
            if (r0 < 68) {
                float v0 = acc[j][0] + b0 + o32[r0][nc];
                float v1 = acc[j][1] + b1 + o32[r0][nc+1];
                og[r0*128+nc] = v0; og[r0*128+nc+1] = v1;
                o32[r0][nc] = v0; o32[r0][nc+1] = v1;
            }
            if (r1 < 68) {
                float v0 = acc[j][2] + b0 + o32[r1][nc];
                float v1 = acc[j][3] + b1 + o32[r1][nc+1];
                og[r1*128+nc] = v0; og[r1*128+nc+1] = v1;
                o32[r1][nc] = v0; o32[r1][nc+1] = v1;
            }
        }
    }
    __syncthreads();
    if (pool_out) { // last layer: fused per-graph mean (raw; fold composed later)
        for (int j = tid; j < 512; j += 256) {
            int gi = j >> 7, cc = j & 127;
            float s = 0.f;
            #pragma unroll
            for (int r = 0; r < 17; ++r) s += o32[gi*17 + r][cc];
            pool_out[(size_t)blockIdx.x * 512 + j] = s * (1.f / 17.f);
        }
    }
    {
        float s3 = 0.f, q3 = 0.f;
        for (int i = tid; i < 8704; i += 256) {
            float v = o32[i >> 7][colj];
            s3 += v; q3 = fmaf(v, v, q3);
        }
        float* red = (float*)u16;
        red[tid] = s3; red[256 + tid] = q3;
        __syncthreads();
        if (tid < 128) {
            atomicAdd(&accL[tid],       red[tid] + red[tid + 128]);
            atomicAdd(&accL[128 + tid], red[256 + tid] + red[384 + tid]);
        }
    }
}

// ========== stage-2 tensor kernels: 4 graphs x 12 nodes = 48 rows ==========
#define B_H16 0
#define B_Q16 13056
#define B_K16 27200
#define B_VT  41344
#define B_P   57728
#define B_SC  65920
#define B_MB  78976
#define B_H32 83072
#define SM1B  108416

__global__ __launch_bounds__(256, 2)
void k1_s2(const float* __restrict__ hin, const float* __restrict__ foldIn,
           float* __restrict__ gcnb, float* __restrict__ t2, float* __restrict__ accL,
           const float* __restrict__ gwT, const float* __restrict__ gb,
           const float* __restrict__ qb, const float* __restrict__ ob,
           const uint2* __restrict__ qkvf, const uint2* __restrict__ owf) {
    extern __shared__ char sm[];
    __half (*h16)[136] = (__half(*)[136])(sm + B_H16);
    __half (*q16)[136] = (__half(*)[136])(sm + B_Q16);
    __half (*k16)[136] = (__half(*)[136])(sm + B_K16);
    __half (*vT )[16]  = (__half(*)[16]) (sm + B_VT);
    __half (*pp )[16]  = (__half(*)[16]) (sm + B_P);
    float  (*sc )[17]  = (float(*)[17])  (sm + B_SC);
    float*  mbuf       = (float*)(sm + B_MB);
    float  (*h32)[132] = (float(*)[132]) (sm + B_H32);

    const int tid = threadIdx.x, warp = tid >> 5, lane = tid & 31;
    const int g = lane >> 2, t = lane & 3;
    const int colj = tid & 127;
    const float* hg = hin + (size_t)blockIdx.x * 6144;
    float* t2g = t2 + (size_t)blockIdx.x * 6144;
    const float scIn = foldIn[colj], shIn = foldIn[128 + colj];

    {
        uint4 zz = make_uint4(0,0,0,0);
        uint4* z = (uint4*)(sm + B_VT);
        for (int i = tid; i < 1536; i += 256) z[i] = zz;
        uint4* zq = (uint4*)&q16[48][0];
        for (int i = tid; i < 68; i += 256) zq[i] = zz;
        uint4* zk = (uint4*)&k16[48][0];
        for (int i = tid; i < 68; i += 256) zk[i] = zz;
        for (int i = tid; i < 6144; i += 256) {
            int rr = i >> 7;
            float v = fmaf(hg[i], scIn, shIn);
            h32[rr][colj] = v;
            h16[rr][colj] = __float2half_rn(v);
        }
    }
    __syncthreads();
    {
        float* scr = (float*)sc;
        for (int j = tid; j < 512; j += 256) {
            int gi = j >> 7, cc = j & 127;
            float s = 0.f, q = 0.f;
            #pragma unroll
            for (int r = 0; r < 12; ++r) {
                float v = h32[gi*12 + r][cc];
                s += v; q = fmaf(v, v, q);
            }
            mbuf[j] = s * (1.f / 12.f);
            scr[j] = q; scr[512 + j] = s;
        }
    }
    __syncthreads();
    {
        float* scr = (float*)sc;
        for (int j = tid; j < 512; j += 256) {
            int gi = j >> 7, cc = j & 127;
            float a = gb[cc];
            const float* mrow = mbuf + gi * 128;
            #pragma unroll 4
            for (int k = 0; k < 128; ++k) a = fmaf(mrow[k], gwT[k*128 + cc], a);
            gcnb[(size_t)blockIdx.x * 512 + j] = a;
            float Sh = scr[512 + j], Sq = scr[j];
            scr[512 + j] = fmaf(12.f, a, Sh);
            scr[j] = fmaf(12.f * a, a, fmaf(2.f * a, Sh, Sq));
        }
    }
    __syncthreads();
    if (tid < 128) {
        float* scr = (float*)sc;
        atomicAdd(&accL[tid],       scr[512+tid] + scr[640+tid] + scr[768+tid] + scr[896+tid]);
        atomicAdd(&accL[128 + tid], scr[tid] + scr[128+tid] + scr[256+tid] + scr[384+tid]);
    }
    for (int item = warp; item < 36; item += 8) {
        int mt = item / 12, ng = item % 12, m0 = mt * 16;
        float acc[4][4] = {};
        mtile<8,48>(&h16[m0 + g][2*t], 136, qkvf, ng, lane, acc);
        int r0 = m0 + g, r1 = r0 + 8;
        #pragma unroll
        for (int j = 0; j < 4; ++j) {
            int nc = ng*32 + j*8 + 2*t;
            float b0 = qb[nc], b1 = qb[nc+1];
            float v00 = acc[j][0]+b0, v01 = acc[j][1]+b1, v10 = acc[j][2]+b0, v11 = acc[j][3]+b1;
            if (nc < 128) {
                *(__half2*)&q16[r0][nc] = __floats2half2_rn(v00, v01);
                *(__half2*)&q16[r1][nc] = __floats2half2_rn(v10, v11);
            } else if (nc < 256) {
                *(__half2*)&k16[r0][nc-128] = __floats2half2_rn(v00, v01);
                *(__half2*)&k16[r1][nc-128] = __floats2half2_rn(v10, v11);
            } else {
                int d = nc - 256;
                { int gi = r0/12, sl = r0 - gi*12;
                  vT[gi*128+d][sl] = __float2half_rn(v00); vT[gi*128+d+1][sl] = __float2half_rn(v01); }
                { int gi = r1/12, sl = r1 - gi*12;
                  vT[gi*128+d][sl] = __float2half_rn(v10); vT[gi*128+d+1][sl] = __float2half_rn(v11); }
            }
        }
    }
    __syncthreads();
    for (int item = warp; item < 32; item += 8) {
        int gi = item / 8, r = item % 8, hh = r / 2, nt = r % 2;
        int base = gi * 12;
        float acc[4] = {};
        const __half* a0p = &q16[base + g][hh*32 + 2*t];
        const __half* a1p = a0p + 8*136;
        const __half* br  = &k16[base + nt*8 + g][hh*32 + 2*t];
        #pragma unroll
        for (int kt = 0; kt < 2; ++kt) {
            mma16816(acc, *(const uint32_t*)(a0p+kt*16), *(const uint32_t*)(a1p+kt*16),
                     *(const uint32_t*)(a0p+kt*16+8), *(const uint32_t*)(a1p+kt*16+8),
                     *(const uint32_t*)(br+kt*16), *(const uint32_t*)(br+kt*16+8));
        }
        const float invs = 0.17677669529663687f;
        int ss = nt*8 + 2*t, row = (gi*4 + hh)*12;
        { sc[row+g][ss] = acc[0]*invs; sc[row+g][ss+1] = acc[1]*invs; }
        if (g + 8 < 12) { sc[row+g+8][ss] = acc[2]*invs; sc[row+g+8][ss+1] = acc[3]*invs; }
    }
    __syncthreads();
    if (tid < 192) {
        int gh = tid / 12, q = tid - gh*12;
        float e[12], mx = -1e30f;
        #pragma unroll
        for (int s = 0; s < 12; ++s) mx = fmaxf(mx, sc[gh*12+q][s]);
        float sum = 0.f;
        #pragma unroll
        for (int s = 0; s < 12; ++s) { e[s] = __expf(sc[gh*12+q][s] - mx); sum += e[s]; }
        float inv = 1.f / sum;
        #pragma unroll
        for (int s = 0; s < 12; ++s) pp[gh*16 + q][s] = __float2half_rn(e[s] * inv);
    }
    __syncthreads();
    for (int item = warp; item < 16; item += 8) {
        int gi = item / 4, hh = item % 4;
        float acc[4][4] = {};
        const __half* a0p = &pp[(gi*4+hh)*16 + g][2*t];
        const __half* a1p = a0p + 8*16;
        uint32_t a0 = *(const uint32_t*)a0p,       a1 = *(const uint32_t*)a1p;
        uint32_t a2 = *(const uint32_t*)(a0p + 8), a3 = *(const uint32_t*)(a1p + 8);
        #pragma unroll
        for (int j = 0; j < 4; ++j) {
            const __half* bp = &vT[gi*128 + hh*32 + j*8 + g][2*t];
            mma16816(acc[j], a0, a1, a2, a3, *(const uint32_t*)bp, *(const uint32_t*)(bp+8));
        }
        #pragma unroll
        for (int j = 0; j < 4; ++j) {
            int col = hh*32 + j*8 + 2*t;
            *(__half2*)&q16[gi*12+g][col] = __floats2half2_rn(acc[j][0], acc[j][1]);
            if (g + 8 < 12) *(__half2*)&q16[gi*12+g+8][col] = __floats2half2_rn(acc[j][2], acc[j][3]);
        }
    }
    __syncthreads();
    for (int item = warp; item < 12; item += 8) {
        int mt = item / 4, ng = item % 4, m0 = mt * 16;
        float acc[4][4] = {};
        mtile<8,16>(&q16[m0 + g][2*t], 136, owf, ng, lane, acc);
        int r0 = m0 + g, r1 = r0 + 8;
        #pragma unroll
        for (int j = 0; j < 4; ++j) {
            int nc = ng*32 + j*8 + 2*t;
            float b0 = ob[nc], b1 = ob[nc+1];
            {
                float v0 = acc[j][0] + b0 + h32[r0][nc];
                float v1 = acc[j][1] + b1 + h32[r0][nc+1];
                t2g[r0*128+nc] = v0; t2g[r0*128+nc+1] = v1;
                h32[r0][nc] = v0; h32[r0][nc+1] = v1;
            }
            {
                float v0 = acc[j][2] + b0 + h32[r1][nc];
                float v1 = acc[j][3] + b1 + h32[r1][nc+1];
                t2g[r1*128+nc] = v0; t2g[r1*128+nc+1] = v1;
                h32[r1][nc] = v0; h32[r1][nc+1] = v1;
            }
        }
    }
    __syncthreads();
    {
        float s2 = 0.f, q2 = 0.f;
        for (int i = tid; i < 6144; i += 256) {
            float v = h32[i >> 7][colj];
            s2 += v; q2 = fmaf(v, v, q2);
        }
        mbuf[tid] = s2; mbuf[256 + tid] = q2;
        __syncthreads();
        if (tid < 128) {
            atomicAdd(&accL[256 + tid], mbuf[tid] + mbuf[tid + 128]);
            atomicAdd(&accL[384 + tid], mbuf[256 + tid] + mbuf[384 + tid]);
        }
    }
}

#define C_O16 0
#define C_U16 13056
#define C_O32 38400
#define C_GB  63744
#define SM2B  65792

__global__ __launch_bounds__(256, 2)
void k2_s2(const float* __restrict__ hg0, const float* __restrict__ gcnb,
           const float* __restrict__ t2, const float* __restrict__ foldIn,
           const float* __restrict__ fold1, const float* __restrict__ fold2,
           float* __restrict__ hout, float* __restrict__ accL,
           const uint2* __restrict__ w1f, const float* __restrict__ b1v,
           const uint2* __restrict__ w2f, const float* __restrict__ b2v) {
    extern __shared__ char sm[];
    __half (*o16)[136] = (__half(*)[136])(sm + C_O16);
    __half (*u16)[264] = (__half(*)[264])(sm + C_U16);
    float  (*o32)[132] = (float(*)[132]) (sm + C_O32);
    float*  gbuf       = (float*)(sm + C_GB);
    const int tid = threadIdx.x, warp = tid >> 5, lane = tid & 31;
    const int g = lane >> 2, t = lane & 3;
    const int colj = tid & 127;
    const float* hgA = hg0 + (size_t)blockIdx.x * 6144;
    const float* t2g = t2  + (size_t)blockIdx.x * 6144;
    float* og = hout + (size_t)blockIdx.x * 6144;
    const float scIn = foldIn[colj], shIn = foldIn[128 + colj];
    const float sc1 = fold1[colj], sh1 = fold1[128 + colj];
    const float sc2 = fold2[colj], sh2 = fold2[128 + colj];

    if (tid < 256) gbuf[tid] = gcnb[(size_t)blockIdx.x * 512 + tid];
    if (tid < 256) gbuf[256 + tid] = gcnb[(size_t)blockIdx.x * 512 + 256 + tid];
    __syncthreads();
    for (int i = tid; i < 6144; i += 256) {
        int rr = i >> 7;
        float t1v = gbuf[(rr/12)*128 + colj] + fmaf(hgA[i], scIn, shIn);
        float o = fmaf(t1v, sc1, sh1) + fmaf(t2g[i], sc2, sh2);
        o32[rr][colj] = o;
        o16[rr][colj] = __float2half_rn(o);
    }
    __syncthreads();
    for (int item = warp; item < 24; item += 8) {
        int mt = item / 8, ng = item % 8, m0 = mt * 16;
        float acc[4][4] = {};
        mtile<8,32>(&o16[m0 + g][2*t], 136, w1f, ng, lane, acc);
        int r0 = m0 + g, r1 = r0 + 8;
        #pragma unroll
        for (int j = 0; j < 4; ++j) {
            int nc = ng*32 + j*8 + 2*t;
            float b0 = b1v[nc], b1 = b1v[nc+1];
            *(__half2*)&u16[r0][nc] = __floats2half2_rn(fmaxf(acc[j][0]+b0, 0.f), fmaxf(acc[j][1]+b1, 0.f));
            *(__half2*)&u16[r1][nc] = __floats2half2_rn(fmaxf(acc[j][2]+b0, 0.f), fmaxf(acc[j][3]+b1, 0.f));
        }
    }
    __syncthreads();
    for (int item = warp; item < 12; item += 8) {
        int mt = item / 4, ng = item % 4, m0 = mt * 16;
        float acc[4][4] = {};
        mtile<16,16>(&u16[m0 + g][2*t], 264, w2f, ng, lane, acc);
        int r0 = m0 + g, r1 = r0 + 8;
        #pragma unroll
        for (int j = 0; j < 4; ++j) {
            int nc = ng*32 + j*8 + 2*t;
            float b0 = b2v[nc], b1 = b2v[nc+1];
            {
                float v0 = acc[j][0] + b0 + o32[r0][nc];
                float v1 = acc[j][1] + b1 + o32[r0][nc+1];
                og[r0*128+nc] = v0; og[r0*128+nc+1] = v1;
                o32[r0][nc] = v0; o32[r0][nc+1] = v1;
            }
            {
                float v0 = acc[j][2] + b0 + o32[r1][nc];
                float v1 = acc[j][3] + b1 + o32[r1][nc+1];
                og[r1*128+nc] = v0; og[r1*128+nc+1] = v1;
                o32[r1][nc] = v0; o32[r1][nc+1] = v1;
            }
        }
    }
    __syncthreads();
    {
        float s3 = 0.f, q3 = 0.f;
        for (int i = tid; i < 6144; i += 256) {
            float v = o32[i >> 7][colj];
            s3 += v; q3 = fmaf(v, v, q3);
        }
        float* red = (float*)u16;
        red[tid] = s3; red[256 + tid] = q3;
        __syncthreads();
        if (tid < 128) {
            atomicAdd(&accL[tid],       red[tid] + red[tid + 128]);
            atomicAdd(&accL[128 + tid], red[256 + tid] + red[384 + tid]);
        }
    }
}

extern "C" void kernel_launch(void* const* d_in, const int* in_sizes, int n_in,
                              void* d_out, int out_size) {
    const float* poses = (const float*)d_in[0];
    const float* emb_w = (const float*)d_in[1];
    const float* emb_b = (const float*)d_in[2];
    const float* cls_w = (const float*)d_in[3];
    const float* cls_b = (const float*)d_in[4];
    const float* PPj[12]; const float* PPi[12];
    for (int i = 0; i < 12; ++i) { PPj[i] = (const float*)d_in[5+i]; PPi[i] = (const float*)d_in[17+i]; }

    float *A, *Bb, *Cc, *A2, *B2, *C2, *acc, *fold, *wT; uint2* wf;
    cudaGetSymbolAddress((void**)&A,    g_A);
    cudaGetSymbolAddress((void**)&Bb,   g_B);
    cudaGetSymbolAddress((void**)&Cc,   g_C);
    cudaGetSymbolAddress((void**)&A2,   g_A2);
    cudaGetSymbolAddress((void**)&B2,   g_B2);
    cudaGetSymbolAddress((void**)&C2,   g_C2);
    cudaGetSymbolAddress((void**)&acc,  g_acc);
    cudaGetSymbolAddress((void**)&fold, g_fold);
    cudaGetSymbolAddress((void**)&wT,   g_wT);
    cudaGetSymbolAddress((void**)&wf,   g_wf);
    const float* foldId = fold + 18 * 256;
    uint2* wf2 = wf + 98304;

    cudaFuncSetAttribute(k1_s1, cudaFuncAttributeMaxDynamicSharedMemorySize, SM1);
    cudaFuncSetAttribute(k2_s1, cudaFuncAttributeMaxDynamicSharedMemorySize, SM2);
    cudaFuncSetAttribute(k1_s2, cudaFuncAttributeMaxDynamicSharedMemorySize, SM1B);
    cudaFuncSetAttribute(k2_s2, cudaFuncAttributeMaxDynamicSharedMemorySize, SM2B);

    init_kernel<<<18, 256>>>(acc, fold + 18 * 256);

    transpose_kernel<<<192, 256>>>(PPj[0], wT, 128, 128, 49152);
    transpose_kernel<<<192, 256>>>(PPi[0], wT + 49152, 128, 128, 49152);
    for (int l = 0; l < 3; ++l) {
        prep_frag<<<48, 256>>>(PPj[2]  + l*49152, wf + l*32768,          48, 128, 12288);
        prep_frag<<<16, 256>>>(PPj[4]  + l*16384, wf + l*32768 + 12288,  16, 128, 4096);
        prep_frag<<<32, 256>>>(PPj[8]  + l*32768, wf + l*32768 + 16384,  32, 128, 8192);
        prep_frag<<<32, 256>>>(PPj[10] + l*32768, wf + l*32768 + 24576,  16, 256, 8192);
        prep_frag<<<48, 256>>>(PPi[2]  + l*49152, wf2 + l*32768,         48, 128, 12288);
        prep_frag<<<16, 256>>>(PPi[4]  + l*16384, wf2 + l*32768 + 12288, 16, 128, 4096);
        prep_frag<<<32, 256>>>(PPi[8]  + l*32768, wf2 + l*32768 + 16384, 32, 128, 8192);
        prep_frag<<<32, 256>>>(PPi[10] + l*32768, wf2 + l*32768 + 24576, 16, 256, 8192);
    }

    // stage 1 (tensor-core; embed fused into layer 0, pool fused into layer 2)
    const float* foldPrev = foldId;
    for (int l = 0; l < 3; ++l) {
        float* accL = acc + l * 768;
        float* foldL = fold + l * 768;
        const float* pz = (l == 0) ? poses : nullptr;
        k1_s1<<<10752, 256, SM1>>>(A, foldPrev, Bb, Cc, accL,
                                   wT + l*16384, PPj[1] + l*128, PPj[3] + l*384, PPj[5] + l*128,
                                   wf + l*32768, wf + l*32768 + 12288,
                                   pz, emb_w, emb_b);
        finalize_kernel<<<2, 128>>>(accL, 1.f/365568.f, PPj[6] + l*384, PPj[7] + l*384, foldL,
                                    PPj[6] + l*384 + 128, PPj[7] + l*384 + 128, foldL + 256);
        k2_s1<<<5376, 256, SM2>>>(A, Bb, Cc, foldPrev, foldL, foldL + 256, A, accL + 512,
                                  wf + l*32768 + 16384, PPj[9] + l*256,
                                  wf + l*32768 + 24576, PPj[11] + l*128,
                                  pz, emb_w, emb_b, (l == 2) ? A2 : nullptr);
        finalize_kernel<<<1, 128>>>(accL + 512, 1.f/365568.f, PPj[6] + l*384 + 256,
                                    PPj[7] + l*384 + 256, foldL + 512, nullptr, nullptr, nullptr);
        foldPrev = foldL + 512;
    }
    // foldPrev = stage-1 final fold; A2 holds RAW means -> compose into stage-2 layer-0 BN

    // stage 2 (tensor-core)
    for (int l = 0; l < 3; ++l) {
        float* accL = acc + 2304 + l * 768;
        float* foldL = fold + 2304 + l * 768;
        k1_s2<<<448, 256, SM1B>>>(A2, foldPrev, B2, C2, accL,
                                  wT + 49152 + l*16384, PPi[1] + l*128, PPi[3] + l*384, PPi[5] + l*128,
                                  wf2 + l*32768, wf2 + l*32768 + 12288);
        finalize_kernel<<<2, 128>>>(accL, 1.f/21504.f, PPi[6] + l*384, PPi[7] + l*384, foldL,
                                    PPi[6] + l*384 + 128, PPi[7] + l*384 + 128, foldL + 256);
        k2_s2<<<448, 256, SM2B>>>(A2, B2, C2, foldPrev, foldL, foldL + 256, A2, accL + 512,
                                  wf2 + l*32768 + 16384, PPi[9] + l*256,
                                  wf2 + l*32768 + 24576, PPi[11] + l*128);
        finalize_kernel<<<1, 128>>>(accL + 512, 1.f/21504.f, PPi[6] + l*384 + 256,
                                    PPi[7] + l*384 + 256, foldL + 512, nullptr, nullptr, nullptr);
        foldPrev = foldL + 512;
    }

    pool2_cls_kernel<<<256, 128>>>(A2, foldPrev, cls_w, cls_b, (float*)d_out);
}

// round 14
// speedup vs baseline: 1.3887x; 1.0253x over previous
#include <cuda_runtime.h>
#include <cuda_fp16.h>
#include <stdint.h>

#define D 128

static __device__ float g_A [46792704];
static __device__ float g_B [46792704];
static __device__ float g_C [46792704];
static __device__ float g_A2[ 2752512];
static __device__ float g_B2[ 2752512];
static __device__ float g_C2[ 2752512];
static __device__ float g_acc [18*256];
static __device__ float g_wT  [98304];
static __device__ uint2 g_wf  [196608];

__global__ void init_kernel(float* acc) {
    int t = blockIdx.x * blockDim.x + threadIdx.x;
    if (t < 18*256) acc[t] = 0.f;
}

__global__ void transpose_kernel(const float* __restrict__ src, float* __restrict__ dst,
                                 int R, int C, int total) {
    int idx = blockIdx.x * blockDim.x + threadIdx.x;
    if (idx >= total) return;
    int m = idx / (R * C), rc = idx - m * (R * C), cc = rc / R, r = rc - cc * R;
    dst[idx] = src[m * R * C + r * C + cc];
}

__global__ void prep_frag(const float* __restrict__ W, uint2* __restrict__ out,
                          int NT, int K, int total) {
    int idx = blockIdx.x * blockDim.x + threadIdx.x;
    if (idx >= total) return;
    int lane = idx & 31, tile = idx >> 5;
    int nt = tile % NT, kt = tile / NT;
    int g = lane >> 2, t = lane & 3;
    const float* w = W + (size_t)(nt * 8 + g) * K + kt * 16 + 2 * t;
    __half2 b0 = __floats2half2_rn(w[0], w[1]);
    __half2 b1 = __floats2half2_rn(w[8], w[9]);
    uint2 o; o.x = *(uint32_t*)&b0; o.y = *(uint32_t*)&b1;
    out[idx] = o;
}

// inline BN fold from raw sums
__device__ __forceinline__ float2 mkfold(const float* __restrict__ a, float invN,
                                         const float* __restrict__ gg,
                                         const float* __restrict__ bb, int c) {
    float m = a[c] * invN;
    float v = fmaxf(a[128 + c] * invN - m * m, 0.f);
    float s = rsqrtf(v + 1e-5f) * gg[c];
    return make_float2(s, fmaf(-m, s, bb[c]));
}

__global__ void pool2_cls_kernel(const float* __restrict__ hin,
                                 const float* __restrict__ accIn, const float* __restrict__ gIn,
                                 const float* __restrict__ bIn, float invN,
                                 const float* __restrict__ cw, const float* __restrict__ cb,
                                 float* __restrict__ out) {
    __shared__ float p_s[D];
    int b = blockIdx.x, c = threadIdx.x;
    float2 f = mkfold(accIn, invN, gIn, bIn, c);
    const float* base = hin + (size_t)b * 84 * D + c;
    float s = 0.f;
    #pragma unroll 4
    for (int r = 0; r < 84; ++r) s += base[r * D];
    p_s[c] = fmaf(s * (1.f / 84.f), f.x, f.y);
    __syncthreads();
    if (c < 8) {
        float acc = cb[c];
        #pragma unroll 4
        for (int k = 0; k < D; ++k) acc = fmaf(p_s[k], cw[c * D + k], acc);
        out[b * 8 + c] = acc;
    }
}

__device__ __forceinline__ void mma16816(float* c, uint32_t a0, uint32_t a1,
                                         uint32_t a2, uint32_t a3, uint32_t b0, uint32_t b1) {
    asm("mma.sync.aligned.m16n8k16.row.col.f32.f16.f16.f32 "
        "{%0,%1,%2,%3},{%4,%5,%6,%7},{%8,%9},{%0,%1,%2,%3};"
        : "+f"(c[0]), "+f"(c[1]), "+f"(c[2]), "+f"(c[3])
        : "r"(a0), "r"(a1), "r"(a2), "r"(a3), "r"(b0), "r"(b1));
}

template<int KT, int NT>
__device__ __forceinline__ void mtile(const __half* a0p, int lda, const uint2* __restrict__ wf,
                                      int ng, int lane, float acc[4][4]) {
    const __half* a1p = a0p + 8 * lda;
    #pragma unroll
    for (int kt = 0; kt < KT; ++kt) {
        uint32_t a0 = *(const uint32_t*)(a0p + kt*16);
        uint32_t a1 = *(const uint32_t*)(a1p + kt*16);
        uint32_t a2 = *(const uint32_t*)(a0p + kt*16 + 8);
        uint32_t a3 = *(const uint32_t*)(a1p + kt*16 + 8);
        #pragma unroll
        for (int j = 0; j < 4; ++j) {
            uint2 b = wf[(kt*NT + ng*4 + j)*32 + lane];
            mma16816(acc[j], a0, a1, a2, a3, b.x, b.y);
        }
    }
}

// ---------------- stage-1 tensor kernels: 2 graphs (34 rows), 2 CTAs/SM ----
#define O_H16 0
#define O_Q16 13056
#define O_K16 26112
#define O_VT  39168
#define O_P   56576
#define O_SC  73984
#define O_MB  87584
#define O_H32 91680
#define SM1   109632

__global__ __launch_bounds__(256, 2)
void k1_s1(const float* __restrict__ hin,
           const float* __restrict__ accIn, const float* __restrict__ gIn,
           const float* __restrict__ bIn, float invNIn,
           float* __restrict__ gcnb, __half* __restrict__ t2, float* __restrict__ accL,
           const float* __restrict__ gwT, const float* __restrict__ gb,
           const float* __restrict__ qb, const float* __restrict__ ob,
           const uint2* __restrict__ qkvf, const uint2* __restrict__ owf,
           const float* __restrict__ poses, const float* __restrict__ ew,
           const float* __restrict__ eb) {
    extern __shared__ char sm[];
    __half (*h16)[136] = (__half(*)[136])(sm + O_H16);
    __half (*q16)[136] = (__half(*)[136])(sm + O_Q16);
    __half (*k16)[136] = (__half(*)[136])(sm + O_K16);
    __half (*vT )[34]  = (__half(*)[34]) (sm + O_VT);
    __half (*pp )[34]  = (__half(*)[34]) (sm + O_P);
    float  (*sc )[25]  = (float(*)[25])  (sm + O_SC);
    float*  mbuf       = (float*)(sm + O_MB);
    float  (*h32)[132] = (float(*)[132]) (sm + O_H32);

    const int tid = threadIdx.x, warp = tid >> 5, lane = tid & 31;
    const int g = lane >> 2, t = lane & 3;
    const int colj = tid & 127;
    const float* hg = hin + (size_t)blockIdx.x * 4352;
    __half* t2g = t2 + (size_t)blockIdx.x * 4352;

    {
        uint4 zz = make_uint4(0,0,0,0);
        uint4* z = (uint4*)(sm + O_VT);
        for (int i = tid; i < 2176; i += 256) z[i] = zz;
        uint4* zh = (uint4*)&h16[34][0];
        for (int i = tid; i < 238; i += 256) zh[i] = zz;
        if (poses) { // layer 0: fused embed
            float ewx = ew[2*colj], ewy = ew[2*colj + 1], ebc = eb[colj];
            for (int i = tid; i < 4352; i += 256) {
                int rr = i >> 7;
                int row = blockIdx.x * 34 + rr;
                float v = fmaf(poses[row*2], ewx, fmaf(poses[row*2 + 1], ewy, ebc));
                v = v > 0.f ? v : 0.01f * v;
                h32[rr][colj] = v;
                h16[rr][colj] = __float2half_rn(v);
            }
        } else {
            float2 f = mkfold(accIn, invNIn, gIn, bIn, colj);
            for (int i = tid; i < 4352; i += 256) {
                int rr = i >> 7;
                float v = fmaf(hg[i], f.x, f.y);
                h32[rr][colj] = v;
                h16[rr][colj] = __float2half_rn(v);
            }
        }
    }
    __syncthreads();
    {
        int gi = tid >> 7, cc = tid & 127;
        float s = 0.f, q = 0.f;
        #pragma unroll
        for (int r = 0; r < 17; ++r) {
            float v = h32[gi*17 + r][cc];
            s += v; q = fmaf(v, v, q);
        }
        mbuf[tid] = s * (1.f / 17.f);
        float* scr = (float*)sc;
        scr[tid] = q;
        scr[256 + tid] = s;
    }
    __syncthreads();
    {
        int gi = tid >> 7, cc = tid & 127;
        float a = gb[cc];
        const float* mrow = mbuf + gi * 128;
        #pragma unroll 4
        for (int k = 0; k < 128; ++k) a = fmaf(mrow[k], gwT[k*128 + cc], a);
        gcnb[(size_t)blockIdx.x * 256 + tid] = a;
        float* scr = (float*)sc;
        float Sh = scr[256 + tid], Sq = scr[tid];
        scr[256 + tid] = fmaf(17.f, a, Sh);
        scr[tid] = fmaf(17.f * a, a, fmaf(2.f * a, Sh, Sq));
    }
    __syncthreads();
    if (tid < 128) {
        float* scr = (float*)sc;
        atomicAdd(&accL[tid],       scr[256 + tid] + scr[384 + tid]);
        atomicAdd(&accL[128 + tid], scr[tid] + scr[tid + 128]);
    }
    // qkv: M=48, N=384, K=128
    for (int item = warp; item < 36; item += 8) {
        int mt = item / 12, ng = item % 12, m0 = mt * 16;
        float acc[4][4] = {};
        mtile<8,48>(&h16[m0 + g][2*t], 136, qkvf, ng, lane, acc);
        int r0 = m0 + g, r1 = r0 + 8;
        #pragma unroll
        for (int j = 0; j < 4; ++j) {
            int nc = ng*32 + j*8 + 2*t;
            float b0 = qb[nc], b1 = qb[nc+1];
            float v00 = acc[j][0]+b0, v01 = acc[j][1]+b1, v10 = acc[j][2]+b0, v11 = acc[j][3]+b1;
            if (nc < 128) {
                *(__half2*)&q16[r0][nc] = __floats2half2_rn(v00, v01);
                *(__half2*)&q16[r1][nc] = __floats2half2_rn(v10, v11);
            } else if (nc < 256) {
                *(__half2*)&k16[r0][nc-128] = __floats2half2_rn(v00, v01);
                *(__half2*)&k16[r1][nc-128] = __floats2half2_rn(v10, v11);
            } else {
                int d = nc - 256;
                if (r0 < 34) { int gi = r0/17, sl = r0 - gi*17;
                    vT[gi*128+d][sl] = __float2half_rn(v00); vT[gi*128+d+1][sl] = __float2half_rn(v01); }
                if (r1 < 34) { int gi = r1/17, sl = r1 - gi*17;
                    vT[gi*128+d][sl] = __float2half_rn(v10); vT[gi*128+d+1][sl] = __float2half_rn(v11); }
            }
        }
    }
    __syncthreads();
    // scores
    for (int item = warp; item < 48; item += 8) {
        int gi = item / 24, r = item % 24, hh = r / 6, r2 = r % 6, mt = r2 / 3, nt = r2 % 3;
        int base = gi * 17;
        float acc[4] = {};
        const __half* a0p = &q16[base + mt*16 + g][hh*32 + 2*t];
        const __half* a1p = a0p + 8*136;
        const __half* br  = &k16[base + nt*8 + g][hh*32 + 2*t];
        #pragma unroll
        for (int kt = 0; kt < 2; ++kt) {
            mma16816(acc, *(const uint32_t*)(a0p+kt*16), *(const uint32_t*)(a1p+kt*16),
                     *(const uint32_t*)(a0p+kt*16+8), *(const uint32_t*)(a1p+kt*16+8),
                     *(const uint32_t*)(br+kt*16), *(const uint32_t*)(br+kt*16+8));
        }
        const float invs = 0.17677669529663687f;
        int q0 = mt*16 + g, ss = nt*8 + 2*t, row = (gi*4 + hh)*17;
        if (q0 < 17)     { sc[row+q0][ss]   = acc[0]*invs; sc[row+q0][ss+1]   = acc[1]*invs; }
        if (q0 + 8 < 17) { sc[row+q0+8][ss] = acc[2]*invs; sc[row+q0+8][ss+1] = acc[3]*invs; }
    }
    __syncthreads();
    for (int idx = tid; idx < 136; idx += 256) {
        int gh = idx / 17, q = idx - gh*17;
        float e[17], mx = -1e30f;
        #pragma unroll
        for (int s = 0; s < 17; ++s) mx = fmaxf(mx, sc[gh*17+q][s]);
        float sum = 0.f;
        #pragma unroll
        for (int s = 0; s < 17; ++s) { e[s] = __expf(sc[gh*17+q][s] - mx); sum += e[s]; }
        float inv = 1.f / sum;
        #pragma unroll
        for (int s = 0; s < 17; ++s) pp[gh*32 + q][s] = __float2half_rn(e[s] * inv);
    }
    __syncthreads();
    // attn @ V -> q16
    for (int item = warp; item < 16; item += 8) {
        int gi = item / 8, r = item % 8, hh = r / 2, mt = r % 2;
        float acc[4][4] = {};
        const __half* a0p = &pp[(gi*4+hh)*32 + mt*16 + g][2*t];
        const __half* a1p = a0p + 8*34;
        #pragma unroll
        for (int kt = 0; kt < 2; ++kt) {
            uint32_t a0 = *(const uint32_t*)(a0p+kt*16), a1 = *(const uint32_t*)(a1p+kt*16);
            uint32_t a2 = *(const uint32_t*)(a0p+kt*16+8), a3 = *(const uint32_t*)(a1p+kt*16+8);
            #pragma unroll
            for (int j = 0; j < 4; ++j) {
                const __half* bp = &vT[gi*128 + hh*32 + j*8 + g][kt*16 + 2*t];
                mma16816(acc[j], a0, a1, a2, a3, *(const uint32_t*)bp, *(const uint32_t*)(bp+8));
            }
        }
        int q0 = mt*16 + g;
        #pragma unroll
        for (int j = 0; j < 4; ++j) {
            int col = hh*32 + j*8 + 2*t;
            if (q0 < 17)     *(__half2*)&q16[gi*17+q0][col]   = __floats2half2_rn(acc[j][0], acc[j][1]);
            if (q0 + 8 < 17) *(__half2*)&q16[gi*17+q0+8][col] = __floats2half2_rn(acc[j][2], acc[j][3]);
        }
    }
    __syncthreads();
    // out-proj + residual -> t2 (fp16, quantize-then-stat) AND h32
    for (int item = warp; item < 12; item += 8) {
        int mt = item / 4, ng = item % 4, m0 = mt * 16;
        float acc[4][4] = {};
        mtile<8,16>(&q16[m0 + g][2*t], 136, owf, ng, lane, acc);
        int r0 = m0 + g, r1 = r0 + 8;
        #pragma unroll
        for (int j = 0; j < 4; ++j) {
            int nc = ng*32 + j*8 + 2*t;
            float b0 = ob[nc], b1 = ob[nc+1];
            if (r0 < 34) {
                __half q0h = __float2half_rn(acc[j][0] + b0 + h32[r0][nc]);
                __half q1h = __float2half_rn(acc[j][1] + b1 + h32[r0][nc+1]);
                *(__half2*)&t2g[r0*128+nc] = __halves2half2(q0h, q1h);
                h32[r0][nc] = __half2float(q0h); h32[r0][nc+1] = __half2float(q1h);
            }
            if (r1 < 34) {
                __half q0h = __float2half_rn(acc[j][2] + b0 + h32[r1][nc]);
                __half q1h = __float2half_rn(acc[j][3] + b1 + h32[r1][nc+1]);
                *(__half2*)&t2g[r1*128+nc] = __halves2half2(q0h, q1h);
                h32[r1][nc] = __half2float(q0h); h32[r1][nc+1] = __half2float(q1h);
            }
        }
    }
    __syncthreads();
    {
        float s2 = 0.f, q2 = 0.f;
        for (int i = tid; i < 4352; i += 256) {
            float v = h32[i >> 7][colj];
            s2 += v; q2 = fmaf(v, v, q2);
        }
        mbuf[tid] = s2; mbuf[256 + tid] = q2;
        __syncthreads();
        if (tid < 128) {
            atomicAdd(&accL[256 + tid], mbuf[tid] + mbuf[tid + 128]);
            atomicAdd(&accL[384 + tid], mbuf[256 + tid] + mbuf[384 + tid]);
        }
    }
}

// 4 graphs (68 rows) per block, 2 CTAs/SM
#define P_O16 0
#define P_U16 21760
#define P_O32 64000
#define P_GB  99904
#define SM2   101952

__global__ __launch_bounds__(256, 2)
void k2_s1(const float* __restrict__ hg0, const float* __restrict__ gcnb,
           const __half* __restrict__ t2,
           const float* __restrict__ accIn, const float* __restrict__ gIn,
           const float* __restrict__ bIn, float invNIn,
           const float* __restrict__ accL, const float* __restrict__ bngL,
           const float* __restrict__ bnbL, float invNC,
           float* __restrict__ hout, float* __restrict__ accO,
           const uint2* __restrict__ w1f, const float* __restrict__ b1v,
           const uint2* __restrict__ w2f, const float* __restrict__ b2v,
           const float* __restrict__ poses, const float* __restrict__ ew,
           const float* __restrict__ eb, float* __restrict__ pool_out) {
    extern __shared__ char sm[];
    __half (*o16)[136] = (__half(*)[136])(sm + P_O16);
    __half (*u16)[264] = (__half(*)[264])(sm + P_U16);
    float  (*o32)[132] = (float(*)[132]) (sm + P_O32);
    float*  gbuf       = (float*)(sm + P_GB);
    const int tid = threadIdx.x, warp = tid >> 5, lane = tid & 31;
    const int g = lane >> 2, t = lane & 3;
    const int colj = tid & 127;
    const float* hgA = hg0 + (size_t)blockIdx.x * 8704;
    const __half* t2g = t2 + (size_t)blockIdx.x * 8704;
    float* og = hout + (size_t)blockIdx.x * 8704;
    float2 f1 = mkfold(accL, invNC, bngL, bnbL, colj);
    float2 f2 = mkfold(accL + 256, invNC, bngL + 128, bnbL + 128, colj);

    for (int j = tid; j < 512; j += 256)
        gbuf[j] = gcnb[(size_t)blockIdx.x * 512 + j];
    {
        uint4 zz = make_uint4(0,0,0,0);
        uint4* z = (uint4*)&o16[68][0];
        for (int i = tid; i < 204; i += 256) z[i] = zz;
    }
    __syncthreads();
    if (poses) { // layer 0: recompute embed
        float ewx = ew[2*colj], ewy = ew[2*colj + 1], ebc = eb[colj];
        for (int i = tid; i < 8704; i += 256) {
            int rr = i >> 7;
            int row = blockIdx.x * 68 + rr;
            float hv = fmaf(poses[row*2], ewx, fmaf(poses[row*2 + 1], ewy, ebc));
            hv = hv > 0.f ? hv : 0.01f * hv;
            float t1v = gbuf[(rr/17)*128 + colj] + hv;
            float o = fmaf(t1v, f1.x, f1.y) + fmaf(__half2float(t2g[i]), f2.x, f2.y);
            o32[rr][colj] = o;
            o16[rr][colj] = __float2half_rn(o);
        }
    } else {
        float2 fi = mkfold(accIn, invNIn, gIn, bIn, colj);
        for (int i = tid; i < 8704; i += 256) {
            int rr = i >> 7;
            float t1v = gbuf[(rr/17)*128 + colj] + fmaf(hgA[i], fi.x, fi.y);
            float o = fmaf(t1v, f1.x, f1.y) + fmaf(__half2float(t2g[i]), f2.x, f2.y);
            o32[rr][colj] = o;
            o16[rr][colj] = __float2half_rn(o);
        }
    }
    __syncthreads();
    for (int item = warp; item < 40; item += 8) {
        int mt = item / 8, ng = item % 8, m0 = mt * 16;
        float acc[4][4] = {};
        mtile<8,32>(&o16[m0 + g][2*t], 136, w1f, ng, lane, acc);
        int r0 = m0 + g, r1 = r0 + 8;
        #pragma unroll
        for (int j = 0; j < 4; ++j) {
            int nc = ng*32 + j*8 + 2*t;
            float b0 = b1v[nc], b1 = b1v[nc+1];
            *(__half2*)&u16[r0][nc] = __floats2half2_rn(fmaxf(acc[j][0]+b0, 0.f), fmaxf(acc[j][1]+b1, 0.f));
            *(__half2*)&u16[r1][nc] = __floats2half2_rn(fmaxf(acc[j][2]+b0, 0.f), fmaxf(acc[j][3]+b1, 0.f));
        }
    }
    __syncthreads();
    for (int item = warp; item < 20; item += 8) {
        int mt = item / 4, ng = item % 4, m0 = mt * 16;
        float acc[4][4] = {};
        mtile<16,16>(&u16[m0 + g][2*t], 264, w2f, ng, lane, acc);
        int r0 = m0 + g, r1 = r0 + 8;
        #pragma unroll
        for (int j = 0; j < 4; ++j) {
            int nc = ng*32 + j*8 + 2*t;
            float b0 = b2v[nc], b1 = b2v[nc+1];
            if (r0 < 68) {
                float v0 = acc[j][0] + b0 + o32[r0][nc];
                float v1 = acc[j][1] + b1 + o32[r0][nc+1];
                og[r0*128+nc] = v0; og[r0*128+nc+1] = v1;
                o32[r0][nc] = v0; o32[r0][nc+1] = v1;
            }
            if (r1 < 68) {
                float v0 = acc[j][2] + b0 + o32[r1][nc];
                float v1 = acc[j][3] + b1 + o32[r1][nc+1];
                og[r1*128+nc] = v0; og[r1*128+nc+1] = v1;
                o32[r1][nc] = v0; o32[r1][nc+1] = v1;
            }
        }
    }
    __syncthreads();
    if (pool_out) {
        for (int j = tid; j < 512; j += 256) {
            int gi = j >> 7, cc = j & 127;
            float s = 0.f;
            #pragma unroll
            for (int r = 0; r < 17; ++r) s += o32[gi*17 + r][cc];
            pool_out[(size_t)blockIdx.x * 512 + j] = s * (1.f / 17.f);
        }
    }
    {
        float s3 = 0.f, q3 = 0.f;
        for (int i = tid; i < 8704; i += 256) {
            float v = o32[i >> 7][colj];
            s3 += v; q3 = fmaf(v, v, q3);
        }
        float* red = (float*)u16;
        red[tid] = s3; red[256 + tid] = q3;
        __syncthreads();
        if (tid < 128) {
            atomicAdd((float*)&accO[tid],       red[tid] + red[tid + 128]);
            atomicAdd((float*)&accO[128 + tid], red[256 + tid] + red[384 + tid]);
        }
    }
}

// ========== stage-2 tensor kernels: 4 graphs x 12 nodes = 48 rows ==========
#define B_H16 0
#define B_Q16 13056
#define B_K16 27200
#define B_VT  41344
#define B_P   57728
#define B_SC  65920
#define B_MB  78976
#define B_H32 83072
#define SM1B  108416

__global__ __launch_bounds__(256, 2)
void k1_s2(const float* __restrict__ hin,
           const float* __restrict__ accIn, const float* __restrict__ gIn,
           const float* __restrict__ bIn, float invNIn,
           float* __restrict__ gcnb, __half* __restrict__ t2, float* __restrict__ accL,
           const float* __restrict__ gwT, const float* __restrict__ gb,
           const float* __restrict__ qb, const float* __restrict__ ob,
           const uint2* __restrict__ qkvf, const uint2* __restrict__ owf) {
    extern __shared__ char sm[];
    __half (*h16)[136] = (__half(*)[136])(sm + B_H16);
    __half (*q16)[136] = (__half(*)[136])(sm + B_Q16);
    __half (*k16)[136] = (__half(*)[136])(sm + B_K16);
    __half (*vT )[16]  = (__half(*)[16]) (sm + B_VT);
    __half (*pp )[16]  = (__half(*)[16]) (sm + B_P);
    float  (*sc )[17]  = (float(*)[17])  (sm + B_SC);
    float*  mbuf       = (float*)(sm + B_MB);
    float  (*h32)[132] = (float(*)[132]) (sm + B_H32);

    const int tid = threadIdx.x, warp = tid >> 5, lane = tid & 31;
    const int g = lane >> 2, t = lane & 3;
    const int colj = tid & 127;
    const float* hg = hin + (size_t)blockIdx.x * 6144;
    __half* t2g = t2 + (size_t)blockIdx.x * 6144;

    {
        uint4 zz = make_uint4(0,0,0,0);
        uint4* z = (uint4*)(sm + B_VT);
        for (int i = tid; i < 1536; i += 256) z[i] = zz;
        uint4* zq = (uint4*)&q16[48][0];
        for (int i = tid; i < 68; i += 256) zq[i] = zz;
        uint4* zk = (uint4*)&k16[48][0];
        for (int i = tid; i < 68; i += 256) zk[i] = zz;
        float2 f = mkfold(accIn, invNIn, gIn, bIn, colj);
        for (int i = tid; i < 6144; i += 256) {
            int rr = i >> 7;
            float v = fmaf(hg[i], f.x, f.y);
            h32[rr][colj] = v;
            h16[rr][colj] = __float2half_rn(v);
        }
    }
    __syncthreads();
    {
        float* scr = (float*)sc;
        for (int j = tid; j < 512; j += 256) {
            int gi = j >> 7, cc = j & 127;
            float s = 0.f, q = 0.f;
            #pragma unroll
            for (int r = 0; r < 12; ++r) {
                float v = h32[gi*12 + r][cc];
                s += v; q = fmaf(v, v, q);
            }
            mbuf[j] = s * (1.f / 12.f);
            scr[j] = q; scr[512 + j] = s;
        }
    }
    __syncthreads();
    {
        float* scr = (float*)sc;
        for (int j = tid; j < 512; j += 256) {
            int gi = j >> 7, cc = j & 127;
            float a = gb[cc];
            const float* mrow = mbuf + gi * 128;
            #pragma unroll 4
            for (int k = 0; k < 128; ++k) a = fmaf(mrow[k], gwT[k*128 + cc], a);
            gcnb[(size_t)blockIdx.x * 512 + j] = a;
            float Sh = scr[512 + j], Sq = scr[j];
            scr[512 + j] = fmaf(12.f, a, Sh);
            scr[j] = fmaf(12.f * a, a, fmaf(2.f * a, Sh, Sq));
        }
    }
    __syncthreads();
    if (tid < 128) {
        float* scr = (float*)sc;
        atomicAdd(&accL[tid],       scr[512+tid] + scr[640+tid] + scr[768+tid] + scr[896+tid]);
        atomicAdd(&accL[128 + tid], scr[tid] + scr[128+tid] + scr[256+tid] + scr[384+tid]);
    }
    for (int item = warp; item < 36; item += 8) {
        int mt = item / 12, ng = item % 12, m0 = mt * 16;
        float acc[4][4] = {};
        mtile<8,48>(&h16[m0 + g][2*t], 136, qkvf, ng, lane, acc);
        int r0 = m0 + g, r1 = r0 + 8;
        #pragma unroll
        for (int j = 0; j < 4; ++j) {
            int nc = ng*32 + j*8 + 2*t;
            float b0 = qb[nc], b1 = qb[nc+1];
            float v00 = acc[j][0]+b0, v01 = acc[j][1]+b1, v10 = acc[j][2]+b0, v11 = acc[j][3]+b1;
            if (nc < 128) {
                *(__half2*)&q16[r0][nc] = __floats2half2_rn(v00, v01);
                *(__half2*)&q16[r1][nc] = __floats2half2_rn(v10, v11);
            } else if (nc < 256) {
                *(__half2*)&k16[r0][nc-128] = __floats2half2_rn(v00, v01);
                *(__half2*)&k16[r1][nc-128] = __floats2half2_rn(v10, v11);
            } else {
                int d = nc - 256;
                { int gi = r0/12, sl = r0 - gi*12;
                  vT[gi*128+d][sl] = __float2half_rn(v00); vT[gi*128+d+1][sl] = __float2half_rn(v01); }
                { int gi = r1/12, sl = r1 - gi*12;
                  vT[gi*128+d][sl] = __float2half_rn(v10); vT[gi*128+d+1][sl] = __float2half_rn(v11); }
            }
        }
    }
    __syncthreads();
    for (int item = warp; item < 32; item += 8) {
        int gi = item / 8, r = item % 8, hh = r / 2, nt = r % 2;
        int base = gi * 12;
        float acc[4] = {};
        const __half* a0p = &q16[base + g][hh*32 + 2*t];
        const __half* a1p = a0p + 8*136;
        const __half* br  = &k16[base + nt*8 + g][hh*32 + 2*t];
        #pragma unroll
        for (int kt = 0; kt < 2; ++kt) {
            mma16816(acc, *(const uint32_t*)(a0p+kt*16), *(const uint32_t*)(a1p+kt*16),
                     *(const uint32_t*)(a0p+kt*16+8), *(const uint32_t*)(a1p+kt*16+8),
                     *(const uint32_t*)(br+kt*16), *(const uint32_t*)(br+kt*16+8));
        }
        const float invs = 0.17677669529663687f;
        int ss = nt*8 + 2*t, row = (gi*4 + hh)*12;
        { sc[row+g][ss] = acc[0]*invs; sc[row+g][ss+1] = acc[1]*invs; }
        if (g + 8 < 12) { sc[row+g+8][ss] = acc[2]*invs; sc[row+g+8][ss+1] = acc[3]*invs; }
    }
    __syncthreads();
    if (tid < 192) {
        int gh = tid / 12, q = tid - gh*12;
        float e[12], mx = -1e30f;
        #pragma unroll
        for (int s = 0; s < 12; ++s) mx = fmaxf(mx, sc[gh*12+q][s]);
        float sum = 0.f;
        #pragma unroll
        for (int s = 0; s < 12; ++s) { e[s] = __expf(sc[gh*12+q][s] - mx); sum += e[s]; }
        float inv = 1.f / sum;
        #pragma unroll
        for (int s = 0; s < 12; ++s) pp[gh*16 + q][s] = __float2half_rn(e[s] * inv);
    }
    __syncthreads();
    for (int item = warp; item < 16; item += 8) {
        int gi = item / 4, hh = item % 4;
        float acc[4][4] = {};
        const __half* a0p = &pp[(gi*4+hh)*16 + g][2*t];
        const __half* a1p = a0p + 8*16;
        uint32_t a0 = *(const uint32_t*)a0p,       a1 = *(const uint32_t*)a1p;
        uint32_t a2 = *(const uint32_t*)(a0p + 8), a3 = *(const uint32_t*)(a1p + 8);
        #pragma unroll
        for (int j = 0; j < 4; ++j) {
            const __half* bp = &vT[gi*128 + hh*32 + j*8 + g][2*t];
            mma16816(acc[j], a0, a1, a2, a3, *(const uint32_t*)bp, *(const uint32_t*)(bp+8));
        }
        #pragma unroll
        for (int j = 0; j < 4; ++j) {
            int col = hh*32 + j*8 + 2*t;
            *(__half2*)&q16[gi*12+g][col] = __floats2half2_rn(acc[j][0], acc[j][1]);
            if (g + 8 < 12) *(__half2*)&q16[gi*12+g+8][col] = __floats2half2_rn(acc[j][2], acc[j][3]);
        }
    }
    __syncthreads();
    for (int item = warp; item < 12; item += 8) {
        int mt = item / 4, ng = item % 4, m0 = mt * 16;
        float acc[4][4] = {};
        mtile<8,16>(&q16[m0 + g][2*t], 136, owf, ng, lane, acc);
        int r0 = m0 + g, r1 = r0 + 8;
        #pragma unroll
        for (int j = 0; j < 4; ++j) {
            int nc = ng*32 + j*8 + 2*t;
            float b0 = ob[nc], b1 = ob[nc+1];
            {
                __half q0h = __float2half_rn(acc[j][0] + b0 + h32[r0][nc]);
                __half q1h = __float2half_rn(acc[j][1] + b1 + h32[r0][nc+1]);
                *(__half2*)&t2g[r0*128+nc] = __halves2half2(q0h, q1h);
                h32[r0][nc] = __half2float(q0h); h32[r0][nc+1] = __half2float(q1h);
            }
            {
                __half q0h = __float2half_rn(acc[j][2] + b0 + h32[r1][nc]);
                __half q1h = __float2half_rn(acc[j][3] + b1 + h32[r1][nc+1]);
                *(__half2*)&t2g[r1*128+nc] = __halves2half2(q0h, q1h);
                h32[r1][nc] = __half2float(q0h); h32[r1][nc+1] = __half2float(q1h);
            }
        }
    }
    __syncthreads();
    {
        float s2 = 0.f, q2 = 0.f;
        for (int i = tid; i < 6144; i += 256) {
            float v = h32[i >> 7][colj];
            s2 += v; q2 = fmaf(v, v, q2);
        }
        mbuf[tid] = s2; mbuf[256 + tid] = q2;
        __syncthreads();
        if (tid < 128) {
            atomicAdd(&accL[256 + tid], mbuf[tid] + mbuf[tid + 128]);
            atomicAdd(&accL[384 + tid], mbuf[256 + tid] + mbuf[384 + tid]);
        }
    }
}

#define C_O16 0
#define C_U16 13056
#define C_O32 38400
#define C_GB  63744
#define SM2B  65792

__global__ __launch_bounds__(256, 2)
void k2_s2(const float* __restrict__ hg0, const float* __restrict__ gcnb,
           const __half* __restrict__ t2,
           const float* __restrict__ accIn, const float* __restrict__ gIn,
           const float* __restrict__ bIn, float invNIn,
           const float* __restrict__ accL, const float* __restrict__ bngL,
           const float* __restrict__ bnbL, float invNC,
           float* __restrict__ hout, float* __restrict__ accO,
           const uint2* __restrict__ w1f, const float* __restrict__ b1v,
           const uint2* __restrict__ w2f, const float* __restrict__ b2v) {
    extern __shared__ char sm[];
    __half (*o16)[136] = (__half(*)[136])(sm + C_O16);
    __half (*u16)[264] = (__half(*)[264])(sm + C_U16);
    float  (*o32)[132] = (float(*)[132]) (sm + C_O32);
    float*  gbuf       = (float*)(sm + C_GB);
    const int tid = threadIdx.x, warp = tid >> 5, lane = tid & 31;
    const int g = lane >> 2, t = lane & 3;
    const int colj = tid & 127;
    const float* hgA = hg0 + (size_t)blockIdx.x * 6144;
    const __half* t2g = t2 + (size_t)blockIdx.x * 6144;
    float* og = hout + (size_t)blockIdx.x * 6144;
    float2 fi = mkfold(accIn, invNIn, gIn, bIn, colj);
    float2 f1 = mkfold(accL, invNC, bngL, bnbL, colj);
    float2 f2 = mkfold(accL + 256, invNC, bngL + 128, bnbL + 128, colj);

    if (tid < 256) gbuf[tid] = gcnb[(size_t)blockIdx.x * 512 + tid];
    if (tid < 256) gbuf[256 + tid] = gcnb[(size_t)blockIdx.x * 512 + 256 + tid];
    __syncthreads();
    for (int i = tid; i < 6144; i += 256) {
        int rr = i >> 7;
        float t1v = gbuf[(rr/12)*128 + colj] + fmaf(hgA[i], fi.x, fi.y);
        float o = fmaf(t1v, f1.x, f1.y) + fmaf(__half2float(t2g[i]), f2.x, f2.y);
        o32[rr][colj] = o;
        o16[rr][colj] = __float2half_rn(o);
    }
    __syncthreads();
    for (int item = warp; item < 24; item += 8) {
        int mt = item / 8, ng = item % 8, m0 = mt * 16;
        float acc[4][4] = {};
        mtile<8,32>(&o16[m0 + g][2*t], 136, w1f, ng, lane, acc);
        int r0 = m0 + g, r1 = r0 + 8;
        #pragma unroll
        for (int j = 0; j < 4; ++j) {
            int nc = ng*32 + j*8 + 2*t;
            float b0 = b1v[nc], b1 = b1v[nc+1];
            *(__half2*)&u16[r0][nc] = __floats2half2_rn(fmaxf(acc[j][0]+b0, 0.f), fmaxf(acc[j][1]+b1, 0.f));
            *(__half2*)&u16[r1][nc] = __floats2half2_rn(fmaxf(acc[j][2]+b0, 0.f), fmaxf(acc[j][3]+b1, 0.f));
        }
    }
    __syncthreads();
    for (int item = warp; item < 12; item += 8) {
        int mt = item / 4, ng = item % 4, m0 = mt * 16;
        float acc[4][4] = {};
        mtile<16,16>(&u16[m0 + g][2*t], 264, w2f, ng, lane, acc);
        int r0 = m0 + g, r1 = r0 + 8;
        #pragma unroll
        for (int j = 0; j < 4; ++j) {
            int nc = ng*32 + j*8 + 2*t;
            float b0 = b2v[nc], b1 = b2v[nc+1];
            {
                float v0 = acc[j][0] + b0 + o32[r0][nc];
                float v1 = acc[j][1] + b1 + o32[r0][nc+1];
                og[r0*128+nc] = v0; og[r0*128+nc+1] = v1;
                o32[r0][nc] = v0; o32[r0][nc+1] = v1;
            }
            {
                float v0 = acc[j][2] + b0 + o32[r1][nc];
                float v1 = acc[j][3] + b1 + o32[r1][nc+1];
                og[r1*128+nc] = v0; og[r1*128+nc+1] = v1;
                o32[r1][nc] = v0; o32[r1][nc+1] = v1;
            }
        }
    }
    __syncthreads();
    {
        float s3 = 0.f, q3 = 0.f;
        for (int i = tid; i < 6144; i += 256) {
            float v = o32[i >> 7][colj];
            s3 += v; q3 = fmaf(v, v, q3);
        }
        float* red = (float*)u16;
        red[tid] = s3; red[256 + tid] = q3;
        __syncthreads();
        if (tid < 128) {
            atomicAdd((float*)&accO[tid],       red[tid] + red[tid + 128]);
            atomicAdd((float*)&accO[128 + tid], red[256 + tid] + red[384 + tid]);
        }
    }
}

extern "C" void kernel_launch(void* const* d_in, const int* in_sizes, int n_in,
                              void* d_out, int out_size) {
    const float* poses = (const float*)d_in[0];
    const float* emb_w = (const float*)d_in[1];
    const float* emb_b = (const float*)d_in[2];
    const float* cls_w = (const float*)d_in[3];
    const float* cls_b = (const float*)d_in[4];
    const float* PPj[12]; const float* PPi[12];
    for (int i = 0; i < 12; ++i) { PPj[i] = (const float*)d_in[5+i]; PPi[i] = (const float*)d_in[17+i]; }

    float *A, *Bb, *Cc, *A2, *B2, *C2, *acc, *wT; uint2* wf;
    cudaGetSymbolAddress((void**)&A,    g_A);
    cudaGetSymbolAddress((void**)&Bb,   g_B);
    cudaGetSymbolAddress((void**)&Cc,   g_C);
    cudaGetSymbolAddress((void**)&A2,   g_A2);
    cudaGetSymbolAddress((void**)&B2,   g_B2);
    cudaGetSymbolAddress((void**)&C2,   g_C2);
    cudaGetSymbolAddress((void**)&acc,  g_acc);
    cudaGetSymbolAddress((void**)&wT,   g_wT);
    cudaGetSymbolAddress((void**)&wf,   g_wf);
    uint2* wf2 = wf + 98304;
    __half* Ch  = (__half*)Cc;
    __half* C2h = (__half*)C2;
    const float inv1 = 1.f / 365568.f, inv2 = 1.f / 21504.f;

    cudaFuncSetAttribute(k1_s1, cudaFuncAttributeMaxDynamicSharedMemorySize, SM1);
    cudaFuncSetAttribute(k2_s1, cudaFuncAttributeMaxDynamicSharedMemorySize, SM2);
    cudaFuncSetAttribute(k1_s2, cudaFuncAttributeMaxDynamicSharedMemorySize, SM1B);
    cudaFuncSetAttribute(k2_s2, cudaFuncAttributeMaxDynamicSharedMemorySize, SM2B);

    init_kernel<<<18, 256>>>(acc);

    transpose_kernel<<<192, 256>>>(PPj[0], wT, 128, 128, 49152);
    transpose_kernel<<<192, 256>>>(PPi[0], wT + 49152, 128, 128, 49152);
    for (int l = 0; l < 3; ++l) {
        prep_frag<<<48, 256>>>(PPj[2]  + l*49152, wf + l*32768,          48, 128, 12288);
        prep_frag<<<16, 256>>>(PPj[4]  + l*16384, wf + l*32768 + 12288,  16, 128, 4096);
        prep_frag<<<32, 256>>>(PPj[8]  + l*32768, wf + l*32768 + 16384,  32, 128, 8192);
        prep_frag<<<32, 256>>>(PPj[10] + l*32768, wf + l*32768 + 24576,  16, 256, 8192);
        prep_frag<<<48, 256>>>(PPi[2]  + l*49152, wf2 + l*32768,         48, 128, 12288);
        prep_frag<<<16, 256>>>(PPi[4]  + l*16384, wf2 + l*32768 + 12288, 16, 128, 4096);
        prep_frag<<<32, 256>>>(PPi[8]  + l*32768, wf2 + l*32768 + 16384, 32, 128, 8192);
        prep_frag<<<32, 256>>>(PPi[10] + l*32768, wf2 + l*32768 + 24576, 16, 256, 8192);
    }

    // stage 1: folds computed inline from raw acc sums (no finalize kernels)
    const float* accPrev = nullptr;
    const float* gPrev = nullptr;
    const float* bPrev = nullptr;
    for (int l = 0; l < 3; ++l) {
        float* accL = acc + l * 768;
        const float* pz = (l == 0) ? poses : nullptr;
        k1_s1<<<10752, 256, SM1>>>(A, accPrev, gPrev, bPrev, inv1,
                                   Bb, Ch, accL,
                                   wT + l*16384, PPj[1] + l*128, PPj[3] + l*384, PPj[5] + l*128,
                                   wf + l*32768, wf + l*32768 + 12288,
                                   pz, emb_w, emb_b);
        k2_s1<<<5376, 256, SM2>>>(A, Bb, Ch, accPrev, gPrev, bPrev, inv1,
                                  accL, PPj[6] + l*384, PPj[7] + l*384, inv1,
                                  A, accL + 512,
                                  wf + l*32768 + 16384, PPj[9] + l*256,
                                  wf + l*32768 + 24576, PPj[11] + l*128,
                                  pz, emb_w, emb_b, (l == 2) ? A2 : nullptr);
        accPrev = accL + 512;
        gPrev = PPj[6] + l*384 + 256;
        bPrev = PPj[7] + l*384 + 256;
    }
    // accPrev/gPrev/bPrev = stage-1 final output BN (invN = inv1); A2 holds raw means

    // stage 2
    float invNIn = inv1;
    for (int l = 0; l < 3; ++l) {
        float* accL = acc + 2304 + l * 768;
        k1_s2<<<448, 256, SM1B>>>(A2, accPrev, gPrev, bPrev, invNIn,
                                  B2, C2h, accL,
                                  wT + 49152 + l*16384, PPi[1] + l*128, PPi[3] + l*384, PPi[5] + l*128,
                                  wf2 + l*32768, wf2 + l*32768 + 12288);
        k2_s2<<<448, 256, SM2B>>>(A2, B2, C2h, accPrev, gPrev, bPrev, invNIn,
                                  accL, PPi[6] + l*384, PPi[7] + l*384, inv2,
                                  A2, accL + 512,
                                  wf2 + l*32768 + 16384, PPi[9] + l*256,
                                  wf2 + l*32768 + 24576, PPi[11] + l*128);
        accPrev = accL + 512;
        gPrev = PPi[6] + l*384 + 256;
        bPrev = PPi[7] + l*384 + 256;
        invNIn = inv2;
    }

    pool2_cls_kernel<<<256, 128>>>(A2, accPrev, gPrev, bPrev, inv2,
                                   cls_w, cls_b, (float*)d_out);
}

// round 15
// speedup vs baseline: 1.4126x; 1.0172x over previous
#include <cuda_runtime.h>
#include <cuda_fp16.h>
#include <stdint.h>

#define D 128

static __device__ float g_A [46792704];
static __device__ float g_B [46792704];
static __device__ float g_C [46792704];
static __device__ float g_A2[ 2752512];
static __device__ float g_B2[ 2752512];
static __device__ float g_C2[ 2752512];
static __device__ float g_acc [18*256];
static __device__ float g_wT  [98304];
static __device__ uint2 g_wf  [196608];

__global__ void init_kernel(float* acc) {
    int t = blockIdx.x * blockDim.x + threadIdx.x;
    if (t < 18*256) acc[t] = 0.f;
}

__global__ void transpose_kernel(const float* __restrict__ src, float* __restrict__ dst,
                                 int R, int C, int total) {
    int idx = blockIdx.x * blockDim.x + threadIdx.x;
    if (idx >= total) return;
    int m = idx / (R * C), rc = idx - m * (R * C), cc = rc / R, r = rc - cc * R;
    dst[idx] = src[m * R * C + r * C + cc];
}

__global__ void prep_frag(const float* __restrict__ W, uint2* __restrict__ out,
                          int NT, int K, int total) {
    int idx = blockIdx.x * blockDim.x + threadIdx.x;
    if (idx >= total) return;
    int lane = idx & 31, tile = idx >> 5;
    int nt = tile % NT, kt = tile / NT;
    int g = lane >> 2, t = lane & 3;
    const float* w = W + (size_t)(nt * 8 + g) * K + kt * 16 + 2 * t;
    __half2 b0 = __floats2half2_rn(w[0], w[1]);
    __half2 b1 = __floats2half2_rn(w[8], w[9]);
    uint2 o; o.x = *(uint32_t*)&b0; o.y = *(uint32_t*)&b1;
    out[idx] = o;
}

// inline BN fold from raw sums
__device__ __forceinline__ float2 mkfold(const float* __restrict__ a, float invN,
                                         const float* __restrict__ gg,
                                         const float* __restrict__ bb, int c) {
    float m = a[c] * invN;
    float v = fmaxf(a[128 + c] * invN - m * m, 0.f);
    float s = rsqrtf(v + 1e-5f) * gg[c];
    return make_float2(s, fmaf(-m, s, bb[c]));
}

__global__ void pool2_cls_kernel(const float* __restrict__ hin,
                                 const float* __restrict__ accIn, const float* __restrict__ gIn,
                                 const float* __restrict__ bIn, float invN,
                                 const float* __restrict__ cw, const float* __restrict__ cb,
                                 float* __restrict__ out) {
    __shared__ float p_s[D];
    int b = blockIdx.x, c = threadIdx.x;
    float2 f = mkfold(accIn, invN, gIn, bIn, c);
    const float* base = hin + (size_t)b * 84 * D + c;
    float s = 0.f;
    #pragma unroll 4
    for (int r = 0; r < 84; ++r) s += base[r * D];
    p_s[c] = fmaf(s * (1.f / 84.f), f.x, f.y);
    __syncthreads();
    if (c < 8) {
        float acc = cb[c];
        #pragma unroll 4
        for (int k = 0; k < D; ++k) acc = fmaf(p_s[k], cw[c * D + k], acc);
        out[b * 8 + c] = acc;
    }
}

__device__ __forceinline__ void mma16816(float* c, uint32_t a0, uint32_t a1,
                                         uint32_t a2, uint32_t a3, uint32_t b0, uint32_t b1) {
    asm("mma.sync.aligned.m16n8k16.row.col.f32.f16.f16.f32 "
        "{%0,%1,%2,%3},{%4,%5,%6,%7},{%8,%9},{%0,%1,%2,%3};"
        : "+f"(c[0]), "+f"(c[1]), "+f"(c[2]), "+f"(c[3])
        : "r"(a0), "r"(a1), "r"(a2), "r"(a3), "r"(b0), "r"(b1));
}

template<int KT, int NT>
__device__ __forceinline__ void mtile(const __half* a0p, int lda, const uint2* __restrict__ wf,
                                      int ng, int lane, float acc[4][4]) {
    const __half* a1p = a0p + 8 * lda;
    #pragma unroll
    for (int kt = 0; kt < KT; ++kt) {
        uint32_t a0 = *(const uint32_t*)(a0p + kt*16);
        uint32_t a1 = *(const uint32_t*)(a1p + kt*16);
        uint32_t a2 = *(const uint32_t*)(a0p + kt*16 + 8);
        uint32_t a3 = *(const uint32_t*)(a1p + kt*16 + 8);
        #pragma unroll
        for (int j = 0; j < 4; ++j) {
            uint2 b = wf[(kt*NT + ng*4 + j)*32 + lane];
            mma16816(acc[j], a0, a1, a2, a3, b.x, b.y);
        }
    }
}

// ---------------- stage-1 tensor kernels: 2 graphs (34 rows), 2 CTAs/SM ----
#define O_H16 0
#define O_Q16 13056
#define O_K16 26112
#define O_VT  39168
#define O_P   56576
#define O_SC  73984
#define O_MB  87584
#define O_H32 91680
#define SM1   109632

__global__ __launch_bounds__(256, 2)
void k1_s1(const __half* __restrict__ hin,
           const float* __restrict__ accIn, const float* __restrict__ gIn,
           const float* __restrict__ bIn, float invNIn,
           float* __restrict__ gcnb, __half* __restrict__ t2, float* __restrict__ accL,
           const float* __restrict__ gwT, const float* __restrict__ gb,
           const float* __restrict__ qb, const float* __restrict__ ob,
           const uint2* __restrict__ qkvf, const uint2* __restrict__ owf,
           const float* __restrict__ poses, const float* __restrict__ ew,
           const float* __restrict__ eb) {
    extern __shared__ char sm[];
    __half (*h16)[136] = (__half(*)[136])(sm + O_H16);
    __half (*q16)[136] = (__half(*)[136])(sm + O_Q16);
    __half (*k16)[136] = (__half(*)[136])(sm + O_K16);
    __half (*vT )[34]  = (__half(*)[34]) (sm + O_VT);
    __half (*pp )[34]  = (__half(*)[34]) (sm + O_P);
    float  (*sc )[25]  = (float(*)[25])  (sm + O_SC);
    float*  mbuf       = (float*)(sm + O_MB);
    float  (*h32)[132] = (float(*)[132]) (sm + O_H32);

    const int tid = threadIdx.x, warp = tid >> 5, lane = tid & 31;
    const int g = lane >> 2, t = lane & 3;
    const int colj = tid & 127;
    const __half* hg = hin + (size_t)blockIdx.x * 4352;
    __half* t2g = t2 + (size_t)blockIdx.x * 4352;

    {
        uint4 zz = make_uint4(0,0,0,0);
        uint4* z = (uint4*)(sm + O_VT);
        for (int i = tid; i < 2176; i += 256) z[i] = zz;
        uint4* zh = (uint4*)&h16[34][0];
        for (int i = tid; i < 238; i += 256) zh[i] = zz;
        if (poses) { // layer 0: fused embed
            float ewx = ew[2*colj], ewy = ew[2*colj + 1], ebc = eb[colj];
            for (int i = tid; i < 4352; i += 256) {
                int rr = i >> 7;
                int row = blockIdx.x * 34 + rr;
                float v = fmaf(poses[row*2], ewx, fmaf(poses[row*2 + 1], ewy, ebc));
                v = v > 0.f ? v : 0.01f * v;
                h32[rr][colj] = v;
                h16[rr][colj] = __float2half_rn(v);
            }
        } else {
            float2 f = mkfold(accIn, invNIn, gIn, bIn, colj);
            for (int i = tid; i < 4352; i += 256) {
                int rr = i >> 7;
                float v = fmaf(__half2float(hg[i]), f.x, f.y);
                h32[rr][colj] = v;
                h16[rr][colj] = __float2half_rn(v);
            }
        }
    }
    __syncthreads();
    {
        int gi = tid >> 7, cc = tid & 127;
        float s = 0.f, q = 0.f;
        #pragma unroll
        for (int r = 0; r < 17; ++r) {
            float v = h32[gi*17 + r][cc];
            s += v; q = fmaf(v, v, q);
        }
        mbuf[tid] = s * (1.f / 17.f);
        float* scr = (float*)sc;
        scr[tid] = q;
        scr[256 + tid] = s;
    }
    __syncthreads();
    {
        int gi = tid >> 7, cc = tid & 127;
        float a = gb[cc];
        const float* mrow = mbuf + gi * 128;
        #pragma unroll 4
        for (int k = 0; k < 128; ++k) a = fmaf(mrow[k], gwT[k*128 + cc], a);
        gcnb[(size_t)blockIdx.x * 256 + tid] = a;
        float* scr = (float*)sc;
        float Sh = scr[256 + tid], Sq = scr[tid];
        scr[256 + tid] = fmaf(17.f, a, Sh);
        scr[tid] = fmaf(17.f * a, a, fmaf(2.f * a, Sh, Sq));
    }
    __syncthreads();
    if (tid < 128) {
        float* scr = (float*)sc;
        atomicAdd(&accL[tid],       scr[256 + tid] + scr[384 + tid]);
        atomicAdd(&accL[128 + tid], scr[tid] + scr[tid + 128]);
    }
    // qkv: M=48, N=384, K=128
    for (int item = warp; item < 36; item += 8) {
        int mt = item / 12, ng = item % 12, m0 = mt * 16;
        float acc[4][4] = {};
        mtile<8,48>(&h16[m0 + g][2*t], 136, qkvf, ng, lane, acc);
        int r0 = m0 + g, r1 = r0 + 8;
        #pragma unroll
        for (int j = 0; j < 4; ++j) {
            int nc = ng*32 + j*8 + 2*t;
            float b0 = qb[nc], b1 = qb[nc+1];
            float v00 = acc[j][0]+b0, v01 = acc[j][1]+b1, v10 = acc[j][2]+b0, v11 = acc[j][3]+b1;
            if (nc < 128) {
                *(__half2*)&q16[r0][nc] = __floats2half2_rn(v00, v01);
                *(__half2*)&q16[r1][nc] = __floats2half2_rn(v10, v11);
            } else if (nc < 256) {
                *(__half2*)&k16[r0][nc-128] = __floats2half2_rn(v00, v01);
                *(__half2*)&k16[r1][nc-128] = __floats2half2_rn(v10, v11);
            } else {
                int d = nc - 256;
                if (r0 < 34) { int gi = r0/17, sl = r0 - gi*17;
                    vT[gi*128+d][sl] = __float2half_rn(v00); vT[gi*128+d+1][sl] = __float2half_rn(v01); }
                if (r1 < 34) { int gi = r1/17, sl = r1 - gi*17;
                    vT[gi*128+d][sl] = __float2half_rn(v10); vT[gi*128+d+1][sl] = __float2half_rn(v11); }
            }
        }
    }
    __syncthreads();
    // scores
    for (int item = warp; item < 48; item += 8) {
        int gi = item / 24, r = item % 24, hh = r / 6, r2 = r % 6, mt = r2 / 3, nt = r2 % 3;
        int base = gi * 17;
        float acc[4] = {};
        const __half* a0p = &q16[base + mt*16 + g][hh*32 + 2*t];
        const __half* a1p = a0p + 8*136;
        const __half* br  = &k16[base + nt*8 + g][hh*32 + 2*t];
        #pragma unroll
        for (int kt = 0; kt < 2; ++kt) {
            mma16816(acc, *(const uint32_t*)(a0p+kt*16), *(const uint32_t*)(a1p+kt*16),
                     *(const uint32_t*)(a0p+kt*16+8), *(const uint32_t*)(a1p+kt*16+8),
                     *(const uint32_t*)(br+kt*16), *(const uint32_t*)(br+kt*16+8));
        }
        const float invs = 0.17677669529663687f;
        int q0 = mt*16 + g, ss = nt*8 + 2*t, row = (gi*4 + hh)*17;
        if (q0 < 17)     { sc[row+q0][ss]   = acc[0]*invs; sc[row+q0][ss+1]   = acc[1]*invs; }
        if (q0 + 8 < 17) { sc[row+q0+8][ss] = acc[2]*invs; sc[row+q0+8][ss+1] = acc[3]*invs; }
    }
    __syncthreads();
    for (int idx = tid; idx < 136; idx += 256) {
        int gh = idx / 17, q = idx - gh*17;
        float e[17], mx = -1e30f;
        #pragma unroll
        for (int s = 0; s < 17; ++s) mx = fmaxf(mx, sc[gh*17+q][s]);
        float sum = 0.f;
        #pragma unroll
        for (int s = 0; s < 17; ++s) { e[s] = __expf(sc[gh*17+q][s] - mx); sum += e[s]; }
        float inv = 1.f / sum;
        #pragma unroll
        for (int s = 0; s < 17; ++s) pp[gh*32 + q][s] = __float2half_rn(e[s] * inv);
    }
    __syncthreads();
    // attn @ V -> q16
    for (int item = warp; item < 16; item += 8) {
        int gi = item / 8, r = item % 8, hh = r / 2, mt = r % 2;
        float acc[4][4] = {};
        const __half* a0p = &pp[(gi*4+hh)*32 + mt*16 + g][2*t];
        const __half* a1p = a0p + 8*34;
        #pragma unroll
        for (int kt = 0; kt < 2; ++kt) {
            uint32_t a0 = *(const uint32_t*)(a0p+kt*16), a1 = *(const uint32_t*)(a1p+kt*16);
            uint32_t a2 = *(const uint32_t*)(a0p+kt*16+8), a3 = *(const uint32_t*)(a1p+kt*16+8);
            #pragma unroll
            for (int j = 0; j < 4; ++j) {
                const __half* bp = &vT[gi*128 + hh*32 + j*8 + g][kt*16 + 2*t];
                mma16816(acc[j], a0, a1, a2, a3, *(const uint32_t*)bp, *(const uint32_t*)(bp+8));
            }
        }
        int q0 = mt*16 + g;
        #pragma unroll
        for (int j = 0; j < 4; ++j) {
            int col = hh*32 + j*8 + 2*t;
            if (q0 < 17)     *(__half2*)&q16[gi*17+q0][col]   = __floats2half2_rn(acc[j][0], acc[j][1]);
            if (q0 + 8 < 17) *(__half2*)&q16[gi*17+q0+8][col] = __floats2half2_rn(acc[j][2], acc[j][3]);
        }
    }
    __syncthreads();
    // out-proj + residual -> t2 (fp16, quantize-then-stat) AND h32
    for (int item = warp; item < 12; item += 8) {
        int mt = item / 4, ng = item % 4, m0 = mt * 16;
        float acc[4][4] = {};
        mtile<8,16>(&q16[m0 + g][2*t], 136, owf, ng, lane, acc);
        int r0 = m0 + g, r1 = r0 + 8;
        #pragma unroll
        for (int j = 0; j < 4; ++j) {
            int nc = ng*32 + j*8 + 2*t;
            float b0 = ob[nc], b1 = ob[nc+1];
            if (r0 < 34) {
                __half q0h = __float2half_rn(acc[j][0] + b0 + h32[r0][nc]);
                __half q1h = __float2half_rn(acc[j][1] + b1 + h32[r0][nc+1]);
                *(__half2*)&t2g[r0*128+nc] = __halves2half2(q0h, q1h);
                h32[r0][nc] = __half2float(q0h); h32[r0][nc+1] = __half2float(q1h);
            }
            if (r1 < 34) {
                __half q0h = __float2half_rn(acc[j][2] + b0 + h32[r1][nc]);
                __half q1h = __float2half_rn(acc[j][3] + b1 + h32[r1][nc+1]);
                *(__half2*)&t2g[r1*128+nc] = __halves2half2(q0h, q1h);
                h32[r1][nc] = __half2float(q0h); h32[r1][nc+1] = __half2float(q1h);
            }
        }
    }
    __syncthreads();
    {
        float s2 = 0.f, q2 = 0.f;
        for (int i = tid; i < 4352; i += 256) {
            float v = h32[i >> 7][colj];
            s2 += v; q2 = fmaf(v, v, q2);
        }
        mbuf[tid] = s2; mbuf[256 + tid] = q2;
        __syncthreads();
        if (tid < 128) {
            atomicAdd(&accL[256 + tid], mbuf[tid] + mbuf[tid + 128]);
            atomicAdd(&accL[384 + tid], mbuf[256 + tid] + mbuf[384 + tid]);
        }
    }
}

// 4 graphs (68 rows) per block, 2 CTAs/SM
#define P_O16 0
#define P_U16 21760
#define P_O32 64000
#define P_GB  99904
#define SM2   101952

__global__ __launch_bounds__(256, 2)
void k2_s1(const __half* __restrict__ hg0, const float* __restrict__ gcnb,
           const __half* __restrict__ t2,
           const float* __restrict__ accIn, const float* __restrict__ gIn,
           const float* __restrict__ bIn, float invNIn,
           const float* __restrict__ accL, const float* __restrict__ bngL,
           const float* __restrict__ bnbL, float invNC,
           __half* __restrict__ hout, float* __restrict__ accO,
           const uint2* __restrict__ w1f, const float* __restrict__ b1v,
           const uint2* __restrict__ w2f, const float* __restrict__ b2v,
           const float* __restrict__ poses, const float* __restrict__ ew,
           const float* __restrict__ eb, float* __restrict__ pool_out) {
    extern __shared__ char sm[];
    __half (*o16)[136] = (__half(*)[136])(sm + P_O16);
    __half (*u16)[264] = (__half(*)[264])(sm + P_U16);
    float  (*o32)[132] = (float(*)[132]) (sm + P_O32);
    float*  gbuf       = (float*)(sm + P_GB);
    const int tid = threadIdx.x, warp = tid >> 5, lane = tid & 31;
    const int g = lane >> 2, t = lane & 3;
    const int colj = tid & 127;
    const __half* hgA = hg0 + (size_t)blockIdx.x * 8704;
    const __half* t2g = t2 + (size_t)blockIdx.x * 8704;
    __half* og = hout + (size_t)blockIdx.x * 8704;
    float2 f1 = mkfold(accL, invNC, bngL, bnbL, colj);
    float2 f2 = mkfold(accL + 256, invNC, bngL + 128, bnbL + 128, colj);

    for (int j = tid; j < 512; j += 256)
        gbuf[j] = gcnb[(size_t)blockIdx.x * 512 + j];
    {
        uint4 zz = make_uint4(0,0,0,0);
        uint4* z = (uint4*)&o16[68][0];
        for (int i = tid; i < 204; i += 256) z[i] = zz;
    }
    __syncthreads();
    if (poses) { // layer 0: recompute embed
        float ewx = ew[2*colj], ewy = ew[2*colj + 1], ebc = eb[colj];
        for (int i = tid; i < 8704; i += 256) {
            int rr = i >> 7;
            int row = blockIdx.x * 68 + rr;
            float hv = fmaf(poses[row*2], ewx, fmaf(poses[row*2 + 1], ewy, ebc));
            hv = hv > 0.f ? hv : 0.01f * hv;
            float t1v = gbuf[(rr/17)*128 + colj] + hv;
            float o = fmaf(t1v, f1.x, f1.y) + fmaf(__half2float(t2g[i]), f2.x, f2.y);
            o32[rr][colj] = o;
            o16[rr][colj] = __float2half_rn(o);
        }
    } else {
        float2 fi = mkfold(accIn, invNIn, gIn, bIn, colj);
        for (int i = tid; i < 8704; i += 256) {
            int rr = i >> 7;
            float t1v = gbuf[(rr/17)*128 + colj] + fmaf(__half2float(hgA[i]), fi.x, fi.y);
            float o = fmaf(t1v, f1.x, f1.y) + fmaf(__half2float(t2g[i]), f2.x, f2.y);
            o32[rr][colj] = o;
            o16[rr][colj] = __float2half_rn(o);
        }
    }
    __syncthreads();
    for (int item = warp; item < 40; item += 8) {
        int mt = item / 8, ng = item % 8, m0 = mt * 16;
        float acc[4][4] = {};
        mtile<8,32>(&o16[m0 + g][2*t], 136, w1f, ng, lane, acc);
        int r0 = m0 + g, r1 = r0 + 8;
        #pragma unroll
        for (int j = 0; j < 4; ++j) {
            int nc = ng*32 + j*8 + 2*t;
            float b0 = b1v[nc], b1 = b1v[nc+1];
            *(__half2*)&u16[r0][nc] = __floats2half2_rn(fmaxf(acc[j][0]+b0, 0.f), fmaxf(acc[j][1]+b1, 0.f));
            *(__half2*)&u16[r1][nc] = __floats2half2_rn(fmaxf(acc[j][2]+b0, 0.f), fmaxf(acc[j][3]+b1, 0.f));
        }
    }
    __syncthreads();
    // mlp2 + residual -> og (fp16, quantize-then-stat) AND o32
    for (int item = warp; item < 20; item += 8) {
        int mt = item / 4, ng = item % 4, m0 = mt * 16;
        float acc[4][4] = {};
        mtile<16,16>(&u16[m0 + g][2*t], 264, w2f, ng, lane, acc);
        int r0 = m0 + g, r1 = r0 + 8;
        #pragma unroll
        for (int j = 0; j < 4; ++j) {
            int nc = ng*32 + j*8 + 2*t;
            float b0 = b2v[nc], b1 = b2v[nc+1];
            if (r0 < 68) {
                __half q0h = __float2half_rn(acc[j][0] + b0 + o32[r0][nc]);
                __half q1h = __float2half_rn(acc[j][1] + b1 + o32[r0][nc+1]);
                *(__half2*)&og[r0*128+nc] = __halves2half2(q0h, q1h);
                o32[r0][nc] = __half2float(q0h); o32[r0][nc+1] = __half2float(q1h);
            }
            if (r1 < 68) {
                __half q0h = __float2half_rn(acc[j][2] + b0 + o32[r1][nc]);
                __half q1h = __float2half_rn(acc[j][3] + b1 + o32[r1][nc+1]);
                *(__half2*)&og[r1*128+nc] = __halves2half2(q0h, q1h);
                o32[r1][nc] = __half2float(q0h); o32[r1][nc+1] = __half2float(q1h);
            }
        }
    }
    __syncthreads();
    if (pool_out) {
        for (int j = tid; j < 512; j += 256) {
            int gi = j >> 7, cc = j & 127;
            float s = 0.f;
            #pragma unroll
            for (int r = 0; r < 17; ++r) s += o32[gi*17 + r][cc];
            pool_out[(size_t)blockIdx.x * 512 + j] = s * (1.f / 17.f);
        }
    }
    {
        float s3 = 0.f, q3 = 0.f;
        for (int i = tid; i < 8704; i += 256) {
            float v = o32[i >> 7][colj];
            s3 += v; q3 = fmaf(v, v, q3);
        }
        float* red = (float*)u16;
        red[tid] = s3; red[256 + tid] = q3;
        __syncthreads();
        if (tid < 128) {
            atomicAdd((float*)&accO[tid],       red[tid] + red[tid + 128]);
            atomicAdd((float*)&accO[128 + tid], red[256 + tid] + red[384 + tid]);
        }
    }
}

// ========== stage-2 tensor kernels: 4 graphs x 12 nodes = 48 rows ==========
#define B_H16 0
#define B_Q16 13056
#define B_K16 27200
#define B_VT  41344
#define B_P   57728
#define B_SC  65920
#define B_MB  78976
#define B_H32 83072
#define SM1B  108416

__global__ __launch_bounds__(256, 2)
void k1_s2(const float* __restrict__ hin,
           const float* __restrict__ accIn, const float* __restrict__ gIn,
           const float* __restrict__ bIn, float invNIn,
           float* __restrict__ gcnb, __half* __restrict__ t2, float* __restrict__ accL,
           const float* __restrict__ gwT, const float* __restrict__ gb,
           const float* __restrict__ qb, const float* __restrict__ ob,
           const uint2* __restrict__ qkvf, const uint2* __restrict__ owf) {
    extern __shared__ char sm[];
    __half (*h16)[136] = (__half(*)[136])(sm + B_H16);
    __half (*q16)[136] = (__half(*)[136])(sm + B_Q16);
    __half (*k16)[136] = (__half(*)[136])(sm + B_K16);
    __half (*vT )[16]  = (__half(*)[16]) (sm + B_VT);
    __half (*pp )[16]  = (__half(*)[16]) (sm + B_P);
    float  (*sc )[17]  = (float(*)[17])  (sm + B_SC);
    float*  mbuf       = (float*)(sm + B_MB);
    float  (*h32)[132] = (float(*)[132]) (sm + B_H32);

    const int tid = threadIdx.x, warp = tid >> 5, lane = tid & 31;
    const int g = lane >> 2, t = lane & 3;
    const int colj = tid & 127;
    const float* hg = hin + (size_t)blockIdx.x * 6144;
    __half* t2g = t2 + (size_t)blockIdx.x * 6144;

    {
        uint4 zz = make_uint4(0,0,0,0);
        uint4* z = (uint4*)(sm + B_VT);
        for (int i = tid; i < 1536; i += 256) z[i] = zz;
        uint4* zq = (uint4*)&q16[48][0];
        for (int i = tid; i < 68; i += 256) zq[i] = zz;
        uint4* zk = (uint4*)&k16[48][0];
        for (int i = tid; i < 68; i += 256) zk[i] = zz;
        float2 f = mkfold(accIn, invNIn, gIn, bIn, colj);
        for (int i = tid; i < 6144; i += 256) {
            int rr = i >> 7;
            float v = fmaf(hg[i], f.x, f.y);
            h32[rr][colj] = v;
            h16[rr][colj] = __float2half_rn(v);
        }
    }
    __syncthreads();
    {
        float* scr = (float*)sc;
        for (int j = tid; j < 512; j += 256) {
            int gi = j >> 7, cc = j & 127;
            float s = 0.f, q = 0.f;
            #pragma unroll
            for (int r = 0; r < 12; ++r) {
                float v = h32[gi*12 + r][cc];
                s += v; q = fmaf(v, v, q);
            }
            mbuf[j] = s * (1.f / 12.f);
            scr[j] = q; scr[512 + j] = s;
        }
    }
    __syncthreads();
    {
        float* scr = (float*)sc;
        for (int j = tid; j < 512; j += 256) {
            int gi = j >> 7, cc = j & 127;
            float a = gb[cc];
            const float* mrow = mbuf + gi * 128;
            #pragma unroll 4
            for (int k = 0; k < 128; ++k) a = fmaf(mrow[k], gwT[k*128 + cc], a);
            gcnb[(size_t)blockIdx.x * 512 + j] = a;
            float Sh = scr[512 + j], Sq = scr[j];
            scr[512 + j] = fmaf(12.f, a, Sh);
            scr[j] = fmaf(12.f * a, a, fmaf(2.f * a, Sh, Sq));
        }
    }
    __syncthreads();
    if (tid < 128) {
        float* scr = (float*)sc;
        atomicAdd(&accL[tid],       scr[512+tid] + scr[640+tid] + scr[768+tid] + scr[896+tid]);
        atomicAdd(&accL[128 + tid], scr[tid] + scr[128+tid] + scr[256+tid] + scr[384+tid]);
    }
    for (int item = warp; item < 36; item += 8) {
        int mt = item / 12, ng = item % 12, m0 = mt * 16;
        float acc[4][4] = {};
        mtile<8,48>(&h16[m0 + g][2*t], 136, qkvf, ng, lane, acc);
        int r0 = m0 + g, r1 = r0 + 8;
        #pragma unroll
        for (int j = 0; j < 4; ++j) {
            int nc = ng*32 + j*8 + 2*t;
            float b0 = qb[nc], b1 = qb[nc+1];
            float v00 = acc[j][0]+b0, v01 = acc[j][1]+b1, v10 = acc[j][2]+b0, v11 = acc[j][3]+b1;
            if (nc < 128) {
                *(__half2*)&q16[r0][nc] = __floats2half2_rn(v00, v01);
                *(__half2*)&q16[r1][nc] = __floats2half2_rn(v10, v11);
            } else if (nc < 256) {
                *(__half2*)&k16[r0][nc-128] = __floats2half2_rn(v00, v01);
                *(__half2*)&k16[r1][nc-128] = __floats2half2_rn(v10, v11);
            } else {
                int d = nc - 256;
                { int gi = r0/12, sl = r0 - gi*12;
                  vT[gi*128+d][sl] = __float2half_rn(v00); vT[gi*128+d+1][sl] = __float2half_rn(v01); }
                { int gi = r1/12, sl = r1 - gi*12;
                  vT[gi*128+d][sl] = __float2half_rn(v10); vT[gi*128+d+1][sl] = __float2half_rn(v11); }
            }
        }
    }
    __syncthreads();
    for (int item = warp; item < 32; item += 8) {
        int gi = item / 8, r = item % 8, hh = r / 2, nt = r % 2;
        int base = gi * 12;
        float acc[4] = {};
        const __half* a0p = &q16[base + g][hh*32 + 2*t];
        const __half* a1p = a0p + 8*136;
        const __half* br  = &k16[base + nt*8 + g][hh*32 + 2*t];
        #pragma unroll
        for (int kt = 0; kt < 2; ++kt) {
            mma16816(acc, *(const uint32_t*)(a0p+kt*16), *(const uint32_t*)(a1p+kt*16),
                     *(const uint32_t*)(a0p+kt*16+8), *(const uint32_t*)(a1p+kt*16+8),
                     *(const uint32_t*)(br+kt*16), *(const uint32_t*)(br+kt*16+8));
        }
        const float invs = 0.17677669529663687f;
        int ss = nt*8 + 2*t, row = (gi*4 + hh)*12;
        { sc[row+g][ss] = acc[0]*invs; sc[row+g][ss+1] = acc[1]*invs; }
        if (g + 8 < 12) { sc[row+g+8][ss] = acc[2]*invs; sc[row+g+8][ss+1] = acc[3]*invs; }
    }
    __syncthreads();
    if (tid < 192) {
        int gh = tid / 12, q = tid - gh*12;
        float e[12], mx = -1e30f;
        #pragma unroll
        for (int s = 0; s < 12; ++s) mx = fmaxf(mx, sc[gh*12+q][s]);
        float sum = 0.f;
        #pragma unroll
        for (int s = 0; s < 12; ++s) { e[s] = __expf(sc[gh*12+q][s] - mx); sum += e[s]; }
        float inv = 1.f / sum;
        #pragma unroll
        for (int s = 0; s < 12; ++s) pp[gh*16 + q][s] = __float2half_rn(e[s] * inv);
    }
    __syncthreads();
    for (int item = warp; item < 16; item += 8) {
        int gi = item / 4, hh = item % 4;
        float acc[4][4] = {};
        const __half* a0p = &pp[(gi*4+hh)*16 + g][2*t];
        const __half* a1p = a0p + 8*16;
        uint32_t a0 = *(const uint32_t*)a0p,       a1 = *(const uint32_t*)a1p;
        uint32_t a2 = *(const uint32_t*)(a0p + 8), a3 = *(const uint32_t*)(a1p + 8);
        #pragma unroll
        for (int j = 0; j < 4; ++j) {
            const __half* bp = &vT[gi*128 + hh*32 + j*8 + g][2*t];
            mma16816(acc[j], a0, a1, a2, a3, *(const uint32_t*)bp, *(const uint32_t*)(bp+8));
        }
        #pragma unroll
        for (int j = 0; j < 4; ++j) {
            int col = hh*32 + j*8 + 2*t;
            *(__half2*)&q16[gi*12+g][col] = __floats2half2_rn(acc[j][0], acc[j][1]);
            if (g + 8 < 12) *(__half2*)&q16[gi*12+g+8][col] = __floats2half2_rn(acc[j][2], acc[j][3]);
        }
    }
    __syncthreads();
    for (int item = warp; item < 12; item += 8) {
        int mt = item / 4, ng = item % 4, m0 = mt * 16;
        float acc[4][4] = {};
        mtile<8,16>(&q16[m0 + g][2*t], 136, owf, ng, lane, acc);
        int r0 = m0 + g, r1 = r0 + 8;
        #pragma unroll
        for (int j = 0; j < 4; ++j) {
            int nc = ng*32 + j*8 + 2*t;
            float b0 = ob[nc], b1 = ob[nc+1];
            {
                __half q0h = __float2half_rn(acc[j][0] + b0 + h32[r0][nc]);
                __half q1h = __float2half_rn(acc[j][1] + b1 + h32[r0][nc+1]);
                *(__half2*)&t2g[r0*128+nc] = __halves2half2(q0h, q1h);
                h32[r0][nc] = __half2float(q0h); h32[r0][nc+1] = __half2float(q1h);
            }
            {
                __half q0h = __float2half_rn(acc[j][2] + b0 + h32[r1][nc]);
                __half q1h = __float2half_rn(acc[j][3] + b1 + h32[r1][nc+1]);
                *(__half2*)&t2g[r1*128+nc] = __halves2half2(q0h, q1h);
                h32[r1][nc] = __half2float(q0h); h32[r1][nc+1] = __half2float(q1h);
            }
        }
    }
    __syncthreads();
    {
        float s2 = 0.f, q2 = 0.f;
        for (int i = tid; i < 6144; i += 256) {
            float v = h32[i >> 7][colj];
            s2 += v; q2 = fmaf(v, v, q2);
        }
        mbuf[tid] = s2; mbuf[256 + tid] = q2;
        __syncthreads();
        if (tid < 128) {
            atomicAdd(&accL[256 + tid], mbuf[tid] + mbuf[tid + 128]);
            atomicAdd(&accL[384 + tid], mbuf[256 + tid] + mbuf[384 + tid]);
        }
    }
}

#define C_O16 0
#define C_U16 13056
#define C_O32 38400
#define C_GB  63744
#define SM2B  65792

__global__ __launch_bounds__(256, 2)
void k2_s2(const float* __restrict__ hg0, const float* __restrict__ gcnb,
           const __half* __restrict__ t2,
           const float* __restrict__ accIn, const float* __restrict__ gIn,
           const float* __restrict__ bIn, float invNIn,
           const float* __restrict__ accL, const float* __restrict__ bngL,
           const float* __restrict__ bnbL, float invNC,
           float* __restrict__ hout, float* __restrict__ accO,
           const uint2* __restrict__ w1f, const float* __restrict__ b1v,
           const uint2* __restrict__ w2f, const float* __restrict__ b2v) {
    extern __shared__ char sm[];
    __half (*o16)[136] = (__half(*)[136])(sm + C_O16);
    __half (*u16)[264] = (__half(*)[264])(sm + C_U16);
    float  (*o32)[132] = (float(*)[132]) (sm + C_O32);
    float*  gbuf       = (float*)(sm + C_GB);
    const int tid = threadIdx.x, warp = tid >> 5, lane = tid & 31;
    const int g = lane >> 2, t = lane & 3;
    const int colj = tid & 127;
    const float* hgA = hg0 + (size_t)blockIdx.x * 6144;
    const __half* t2g = t2 + (size_t)blockIdx.x * 6144;
    float* og = hout + (size_t)blockIdx.x * 6144;
    float2 fi = mkfold(accIn, invNIn, gIn, bIn, colj);
    float2 f1 = mkfold(accL, invNC, bngL, bnbL, colj);
    float2 f2 = mkfold(accL + 256, invNC, bngL + 128, bnbL + 128, colj);

    if (tid < 256) gbuf[tid] = gcnb[(size_t)blockIdx.x * 512 + tid];
    if (tid < 256) gbuf[256 + tid] = gcnb[(size_t)blockIdx.x * 512 + 256 + tid];
    __syncthreads();
    for (int i = tid; i < 6144; i += 256) {
        int rr = i >> 7;
        float t1v = gbuf[(rr/12)*128 + colj] + fmaf(hgA[i], fi.x, fi.y);
        float o = fmaf(t1v, f1.x, f1.y) + fmaf(__half2float(t2g[i]), f2.x, f2.y);
        o32[rr][colj] = o;
        o16[rr][colj] = __float2half_rn(o);
    }
    __syncthreads();
    for (int item = warp; item < 24; item += 8) {
        int mt = item / 8, ng = item % 8, m0 = mt * 16;
        float acc[4][4] = {};
        mtile<8,32>(&o16[m0 + g][2*t], 136, w1f, ng, lane, acc);
        int r0 = m0 + g, r1 = r0 + 8;
        #pragma unroll
        for (int j = 0; j < 4; ++j) {
            int nc = ng*32 + j*8 + 2*t;
            float b0 = b1v[nc], b1 = b1v[nc+1];
            *(__half2*)&u16[r0][nc] = __floats2half2_rn(fmaxf(acc[j][0]+b0, 0.f), fmaxf(acc[j][1]+b1, 0.f));
            *(__half2*)&u16[r1][nc] = __floats2half2_rn(fmaxf(acc[j][2]+b0, 0.f), fmaxf(acc[j][3]+b1, 0.f));
        }
    }
    __syncthreads();
    for (int item = warp; item < 12; item += 8) {
        int mt = item / 4, ng = item % 4, m0 = mt * 16;
        float acc[4][4] = {};
        mtile<16,16>(&u16[m0 + g][2*t], 264, w2f, ng, lane, acc);
        int r0 = m0 + g, r1 = r0 + 8;
        #pragma unroll
        for (int j = 0; j < 4; ++j) {
            int nc = ng*32 + j*8 + 2*t;
            float b0 = b2v[nc], b1 = b2v[nc+1];
            {
                float v0 = acc[j][0] + b0 + o32[r0][nc];
                float v1 = acc[j][1] + b1 + o32[r0][nc+1];
                og[r0*128+nc] = v0; og[r0*128+nc+1] = v1;
                o32[r0][nc] = v0; o32[r0][nc+1] = v1;
            }
            {
                float v0 = acc[j][2] + b0 + o32[r1][nc];
                float v1 = acc[j][3] + b1 + o32[r1][nc+1];
                og[r1*128+nc] = v0; og[r1*128+nc+1] = v1;
                o32[r1][nc] = v0; o32[r1][nc+1] = v1;
            }
        }
    }
    __syncthreads();
    {
        float s3 = 0.f, q3 = 0.f;
        for (int i = tid; i < 6144; i += 256) {
            float v = o32[i >> 7][colj];
            s3 += v; q3 = fmaf(v, v, q3);
        }
        float* red = (float*)u16;
        red[tid] = s3; red[256 + tid] = q3;
        __syncthreads();
        if (tid < 128) {
            atomicAdd((float*)&accO[tid],       red[tid] + red[tid + 128]);
            atomicAdd((float*)&accO[128 + tid], red[256 + tid] + red[384 + tid]);
        }
    }
}

extern "C" void kernel_launch(void* const* d_in, const int* in_sizes, int n_in,
                              void* d_out, int out_size) {
    const float* poses = (const float*)d_in[0];
    const float* emb_w = (const float*)d_in[1];
    const float* emb_b = (const float*)d_in[2];
    const float* cls_w = (const float*)d_in[3];
    const float* cls_b = (const float*)d_in[4];
    const float* PPj[12]; const float* PPi[12];
    for (int i = 0; i < 12; ++i) { PPj[i] = (const float*)d_in[5+i]; PPi[i] = (const float*)d_in[17+i]; }

    float *A, *Bb, *Cc, *A2, *B2, *C2, *acc, *wT; uint2* wf;
    cudaGetSymbolAddress((void**)&A,    g_A);
    cudaGetSymbolAddress((void**)&Bb,   g_B);
    cudaGetSymbolAddress((void**)&Cc,   g_C);
    cudaGetSymbolAddress((void**)&A2,   g_A2);
    cudaGetSymbolAddress((void**)&B2,   g_B2);
    cudaGetSymbolAddress((void**)&C2,   g_C2);
    cudaGetSymbolAddress((void**)&acc,  g_acc);
    cudaGetSymbolAddress((void**)&wT,   g_wT);
    cudaGetSymbolAddress((void**)&wf,   g_wf);
    uint2* wf2 = wf + 98304;
    __half* Ah  = (__half*)A;
    __half* Ch  = (__half*)Cc;
    __half* C2h = (__half*)C2;
    const float inv1 = 1.f / 365568.f, inv2 = 1.f / 21504.f;

    cudaFuncSetAttribute(k1_s1, cudaFuncAttributeMaxDynamicSharedMemorySize, SM1);
    cudaFuncSetAttribute(k2_s1, cudaFuncAttributeMaxDynamicSharedMemorySize, SM2);
    cudaFuncSetAttribute(k1_s2, cudaFuncAttributeMaxDynamicSharedMemorySize, SM1B);
    cudaFuncSetAttribute(k2_s2, cudaFuncAttributeMaxDynamicSharedMemorySize, SM2B);

    init_kernel<<<18, 256>>>(acc);

    transpose_kernel<<<192, 256>>>(PPj[0], wT, 128, 128, 49152);
    transpose_kernel<<<192, 256>>>(PPi[0], wT + 49152, 128, 128, 49152);
    for (int l = 0; l < 3; ++l) {
        prep_frag<<<48, 256>>>(PPj[2]  + l*49152, wf + l*32768,          48, 128, 12288);
        prep_frag<<<16, 256>>>(PPj[4]  + l*16384, wf + l*32768 + 12288,  16, 128, 4096);
        prep_frag<<<32, 256>>>(PPj[8]  + l*32768, wf + l*32768 + 16384,  32, 128, 8192);
        prep_frag<<<32, 256>>>(PPj[10] + l*32768, wf + l*32768 + 24576,  16, 256, 8192);
        prep_frag<<<48, 256>>>(PPi[2]  + l*49152, wf2 + l*32768,         48, 128, 12288);
        prep_frag<<<16, 256>>>(PPi[4]  + l*16384, wf2 + l*32768 + 12288, 16, 128, 4096);
        prep_frag<<<32, 256>>>(PPi[8]  + l*32768, wf2 + l*32768 + 16384, 32, 128, 8192);
        prep_frag<<<32, 256>>>(PPi[10] + l*32768, wf2 + l*32768 + 24576, 16, 256, 8192);
    }

    // stage 1 (A stored fp16; folds inline; embed fused l0; pool fused l2)
    const float* accPrev = nullptr;
    const float* gPrev = nullptr;
    const float* bPrev = nullptr;
    for (int l = 0; l < 3; ++l) {
        float* accL = acc + l * 768;
        const float* pz = (l == 0) ? poses : nullptr;
        k1_s1<<<10752, 256, SM1>>>(Ah, accPrev, gPrev, bPrev, inv1,
                                   Bb, Ch, accL,
                                   wT + l*16384, PPj[1] + l*128, PPj[3] + l*384, PPj[5] + l*128,
                                   wf + l*32768, wf + l*32768 + 12288,
                                   pz, emb_w, emb_b);
        k2_s1<<<5376, 256, SM2>>>(Ah, Bb, Ch, accPrev, gPrev, bPrev, inv1,
                                  accL, PPj[6] + l*384, PPj[7] + l*384, inv1,
                                  Ah, accL + 512,
                                  wf + l*32768 + 16384, PPj[9] + l*256,
                                  wf + l*32768 + 24576, PPj[11] + l*128,
                                  pz, emb_w, emb_b, (l == 2) ? A2 : nullptr);
        accPrev = accL + 512;
        gPrev = PPj[6] + l*384 + 256;
        bPrev = PPj[7] + l*384 + 256;
    }

    // stage 2 (A2 fp32)
    float invNIn = inv1;
    for (int l = 0; l < 3; ++l) {
        float* accL = acc + 2304 + l * 768;
        k1_s2<<<448, 256, SM1B>>>(A2, accPrev, gPrev, bPrev, invNIn,
                                  B2, C2h, accL,
                                  wT + 49152 + l*16384, PPi[1] + l*128, PPi[3] + l*384, PPi[5] + l*128,
                                  wf2 + l*32768, wf2 + l*32768 + 12288);
        k2_s2<<<448, 256, SM2B>>>(A2, B2, C2h, accPrev, gPrev, bPrev, invNIn,
                                  accL, PPi[6] + l*384, PPi[7] + l*384, inv2,
                                  A2, accL + 512,
                                  wf2 + l*32768 + 16384, PPi[9] + l*256,
                                  wf2 + l*32768 + 24576, PPi[11] + l*128);
        accPrev = accL + 512;
        gPrev = PPi[6] + l*384 + 256;
        bPrev = PPi[7] + l*384 + 256;
        invNIn = inv2;
    }

    pool2_cls_kernel<<<256, 128>>>(A2, accPrev, gPrev, bPrev, inv2,
                                   cls_w, cls_b, (float*)d_out);
}

// round 16
// speedup vs baseline: 1.4386x; 1.0184x over previous
#include <cuda_runtime.h>
#include <cuda_fp16.h>
#include <stdint.h>

#define D 128

static __device__ float g_A [46792704];
static __device__ float g_B [46792704];
static __device__ float g_C [46792704];
static __device__ float g_A2[ 2752512];
static __device__ float g_B2[ 2752512];
static __device__ float g_C2[ 2752512];
static __device__ float g_acc [18*256];
static __device__ float g_wT  [98304];
static __device__ uint2 g_wf  [196608];

__global__ void init_kernel(float* acc) {
    int t = blockIdx.x * blockDim.x + threadIdx.x;
    if (t < 18*256) acc[t] = 0.f;
}

__global__ void transpose_kernel(const float* __restrict__ src, float* __restrict__ dst,
                                 int R, int C, int total) {
    int idx = blockIdx.x * blockDim.x + threadIdx.x;
    if (idx >= total) return;
    int m = idx / (R * C), rc = idx - m * (R * C), cc = rc / R, r = rc - cc * R;
    dst[idx] = src[m * R * C + r * C + cc];
}

__global__ void prep_frag(const float* __restrict__ W, uint2* __restrict__ out,
                          int NT, int K, int total) {
    int idx = blockIdx.x * blockDim.x + threadIdx.x;
    if (idx >= total) return;
    int lane = idx & 31, tile = idx >> 5;
    int nt = tile % NT, kt = tile / NT;
    int g = lane >> 2, t = lane & 3;
    const float* w = W + (size_t)(nt * 8 + g) * K + kt * 16 + 2 * t;
    __half2 b0 = __floats2half2_rn(w[0], w[1]);
    __half2 b1 = __floats2half2_rn(w[8], w[9]);
    uint2 o; o.x = *(uint32_t*)&b0; o.y = *(uint32_t*)&b1;
    out[idx] = o;
}

// inline BN fold from raw sums
__device__ __forceinline__ float2 mkfold(const float* __restrict__ a, float invN,
                                         const float* __restrict__ gg,
                                         const float* __restrict__ bb, int c) {
    float m = a[c] * invN;
    float v = fmaxf(a[128 + c] * invN - m * m, 0.f);
    float s = rsqrtf(v + 1e-5f) * gg[c];
    return make_float2(s, fmaf(-m, s, bb[c]));
}

__global__ void pool2_cls_kernel(const float* __restrict__ hin,
                                 const float* __restrict__ accIn, const float* __restrict__ gIn,
                                 const float* __restrict__ bIn, float invN,
                                 const float* __restrict__ cw, const float* __restrict__ cb,
                                 float* __restrict__ out) {
    __shared__ float p_s[D];
    int b = blockIdx.x, c = threadIdx.x;
    float2 f = mkfold(accIn, invN, gIn, bIn, c);
    const float* base = hin + (size_t)b * 84 * D + c;
    float s = 0.f;
    #pragma unroll 4
    for (int r = 0; r < 84; ++r) s += base[r * D];
    p_s[c] = fmaf(s * (1.f / 84.f), f.x, f.y);
    __syncthreads();
    if (c < 8) {
        float acc = cb[c];
        #pragma unroll 4
        for (int k = 0; k < D; ++k) acc = fmaf(p_s[k], cw[c * D + k], acc);
        out[b * 8 + c] = acc;
    }
}

__device__ __forceinline__ void mma16816(float* c, uint32_t a0, uint32_t a1,
                                         uint32_t a2, uint32_t a3, uint32_t b0, uint32_t b1) {
    asm("mma.sync.aligned.m16n8k16.row.col.f32.f16.f16.f32 "
        "{%0,%1,%2,%3},{%4,%5,%6,%7},{%8,%9},{%0,%1,%2,%3};"
        : "+f"(c[0]), "+f"(c[1]), "+f"(c[2]), "+f"(c[3])
        : "r"(a0), "r"(a1), "r"(a2), "r"(a3), "r"(b0), "r"(b1));
}

template<int KT, int NT>
__device__ __forceinline__ void mtile(const __half* a0p, int lda, const uint2* __restrict__ wf,
                                      int ng, int lane, float acc[4][4]) {
    const __half* a1p = a0p + 8 * lda;
    #pragma unroll
    for (int kt = 0; kt < KT; ++kt) {
        uint32_t a0 = *(const uint32_t*)(a0p + kt*16);
        uint32_t a1 = *(const uint32_t*)(a1p + kt*16);
        uint32_t a2 = *(const uint32_t*)(a0p + kt*16 + 8);
        uint32_t a3 = *(const uint32_t*)(a1p + kt*16 + 8);
        #pragma unroll
        for (int j = 0; j < 4; ++j) {
            uint2 b = wf[(kt*NT + ng*4 + j)*32 + lane];
            mma16816(acc[j], a0, a1, a2, a3, b.x, b.y);
        }
    }
}

// ---------------- stage-1 tensor kernels: 2 graphs (34 rows), 2 CTAs/SM ----
#define O_H16 0
#define O_Q16 13056
#define O_K16 26112
#define O_VT  39168
#define O_P   56576
#define O_SC  73984
#define O_MB  87584
#define O_H32 91680
#define SM1   109632

__global__ __launch_bounds__(256, 2)
void k1_s1(const __half* __restrict__ hin,
           const float* __restrict__ accIn, const float* __restrict__ gIn,
           const float* __restrict__ bIn, float invNIn,
           float* __restrict__ gcnb, __half* __restrict__ t2, float* __restrict__ accL,
           const float* __restrict__ gwT, const float* __restrict__ gb,
           const float* __restrict__ qb, const float* __restrict__ ob,
           const uint2* __restrict__ qkvf, const uint2* __restrict__ owf,
           const float* __restrict__ poses, const float* __restrict__ ew,
           const float* __restrict__ eb) {
    extern __shared__ char sm[];
    __half (*h16)[136] = (__half(*)[136])(sm + O_H16);
    __half (*q16)[136] = (__half(*)[136])(sm + O_Q16);
    __half (*k16)[136] = (__half(*)[136])(sm + O_K16);
    __half (*vT )[34]  = (__half(*)[34]) (sm + O_VT);
    __half (*pp )[34]  = (__half(*)[34]) (sm + O_P);
    float  (*sc )[25]  = (float(*)[25])  (sm + O_SC);
    float*  mbuf       = (float*)(sm + O_MB);
    float  (*h32)[132] = (float(*)[132]) (sm + O_H32);

    const int tid = threadIdx.x, warp = tid >> 5, lane = tid & 31;
    const int g = lane >> 2, t = lane & 3;
    const int colj = tid & 127;
    const int col0 = (2 * tid) & 127;
    const __half* hg = hin + (size_t)blockIdx.x * 4352;
    __half* t2g = t2 + (size_t)blockIdx.x * 4352;

    {
        uint4 zz = make_uint4(0,0,0,0);
        uint4* z = (uint4*)(sm + O_VT);
        for (int i = tid; i < 2176; i += 256) z[i] = zz;
        uint4* zh = (uint4*)&h16[34][0];
        for (int i = tid; i < 238; i += 256) zh[i] = zz;
        if (poses) { // layer 0: fused embed (2 cols/thread)
            float ewx0 = ew[2*col0], ewy0 = ew[2*col0+1], eb0 = eb[col0];
            float ewx1 = ew[2*col0+2], ewy1 = ew[2*col0+3], eb1 = eb[col0+1];
            const float2* pz2 = (const float2*)poses;
            for (int i2 = tid; i2 < 2176; i2 += 256) {
                int rr = i2 >> 6;
                float2 p = pz2[blockIdx.x * 34 + rr];
                float v0 = fmaf(p.x, ewx0, fmaf(p.y, ewy0, eb0));
                float v1 = fmaf(p.x, ewx1, fmaf(p.y, ewy1, eb1));
                v0 = v0 > 0.f ? v0 : 0.01f * v0;
                v1 = v1 > 0.f ? v1 : 0.01f * v1;
                h32[rr][col0] = v0; h32[rr][col0+1] = v1;
                *(__half2*)&h16[rr][col0] = __floats2half2_rn(v0, v1);
            }
        } else {
            float2 f0 = mkfold(accIn, invNIn, gIn, bIn, col0);
            float2 f1 = mkfold(accIn, invNIn, gIn, bIn, col0 + 1);
            const __half2* hg2 = (const __half2*)hg;
            for (int i2 = tid; i2 < 2176; i2 += 256) {
                int rr = i2 >> 6;
                float2 hv = __half22float2(hg2[i2]);
                float v0 = fmaf(hv.x, f0.x, f0.y);
                float v1 = fmaf(hv.y, f1.x, f1.y);
                h32[rr][col0] = v0; h32[rr][col0+1] = v1;
                *(__half2*)&h16[rr][col0] = __floats2half2_rn(v0, v1);
            }
        }
    }
    __syncthreads();
    {
        int gi = tid >> 7, cc = tid & 127;
        float s = 0.f, q = 0.f;
        #pragma unroll
        for (int r = 0; r < 17; ++r) {
            float v = h32[gi*17 + r][cc];
            s += v; q = fmaf(v, v, q);
        }
        mbuf[tid] = s * (1.f / 17.f);
        float* scr = (float*)sc;
        scr[tid] = q;
        scr[256 + tid] = s;
    }
    __syncthreads();
    {
        int gi = tid >> 7, cc = tid & 127;
        float a = gb[cc];
        const float* mrow = mbuf + gi * 128;
        #pragma unroll 4
        for (int k = 0; k < 128; ++k) a = fmaf(mrow[k], gwT[k*128 + cc], a);
        gcnb[(size_t)blockIdx.x * 256 + tid] = a;
        float* scr = (float*)sc;
        float Sh = scr[256 + tid], Sq = scr[tid];
        scr[256 + tid] = fmaf(17.f, a, Sh);
        scr[tid] = fmaf(17.f * a, a, fmaf(2.f * a, Sh, Sq));
    }
    __syncthreads();
    if (tid < 128) {
        float* scr = (float*)sc;
        atomicAdd(&accL[tid],       scr[256 + tid] + scr[384 + tid]);
        atomicAdd(&accL[128 + tid], scr[tid] + scr[tid + 128]);
    }
    // qkv: M=48, N=384, K=128
    for (int item = warp; item < 36; item += 8) {
        int mt = item / 12, ng = item % 12, m0 = mt * 16;
        float acc[4][4] = {};
        mtile<8,48>(&h16[m0 + g][2*t], 136, qkvf, ng, lane, acc);
        int r0 = m0 + g, r1 = r0 + 8;
        #pragma unroll
        for (int j = 0; j < 4; ++j) {
            int nc = ng*32 + j*8 + 2*t;
            float b0 = qb[nc], b1 = qb[nc+1];
            float v00 = acc[j][0]+b0, v01 = acc[j][1]+b1, v10 = acc[j][2]+b0, v11 = acc[j][3]+b1;
            if (nc < 128) {
                *(__half2*)&q16[r0][nc] = __floats2half2_rn(v00, v01);
                *(__half2*)&q16[r1][nc] = __floats2half2_rn(v10, v11);
            } else if (nc < 256) {
                *(__half2*)&k16[r0][nc-128] = __floats2half2_rn(v00, v01);
                *(__half2*)&k16[r1][nc-128] = __floats2half2_rn(v10, v11);
            } else {
                int d = nc - 256;
                if (r0 < 34) { int gi = r0/17, sl = r0 - gi*17;
                    vT[gi*128+d][sl] = __float2half_rn(v00); vT[gi*128+d+1][sl] = __float2half_rn(v01); }
                if (r1 < 34) { int gi = r1/17, sl = r1 - gi*17;
                    vT[gi*128+d][sl] = __float2half_rn(v10); vT[gi*128+d+1][sl] = __float2half_rn(v11); }
            }
        }
    }
    __syncthreads();
    // scores
    for (int item = warp; item < 48; item += 8) {
        int gi = item / 24, r = item % 24, hh = r / 6, r2 = r % 6, mt = r2 / 3, nt = r2 % 3;
        int base = gi * 17;
        float acc[4] = {};
        const __half* a0p = &q16[base + mt*16 + g][hh*32 + 2*t];
        const __half* a1p = a0p + 8*136;
        const __half* br  = &k16[base + nt*8 + g][hh*32 + 2*t];
        #pragma unroll
        for (int kt = 0; kt < 2; ++kt) {
            mma16816(acc, *(const uint32_t*)(a0p+kt*16), *(const uint32_t*)(a1p+kt*16),
                     *(const uint32_t*)(a0p+kt*16+8), *(const uint32_t*)(a1p+kt*16+8),
                     *(const uint32_t*)(br+kt*16), *(const uint32_t*)(br+kt*16+8));
        }
        const float invs = 0.17677669529663687f;
        int q0 = mt*16 + g, ss = nt*8 + 2*t, row = (gi*4 + hh)*17;
        if (q0 < 17)     { sc[row+q0][ss]   = acc[0]*invs; sc[row+q0][ss+1]   = acc[1]*invs; }
        if (q0 + 8 < 17) { sc[row+q0+8][ss] = acc[2]*invs; sc[row+q0+8][ss+1] = acc[3]*invs; }
    }
    __syncthreads();
    for (int idx = tid; idx < 136; idx += 256) {
        int gh = idx / 17, q = idx - gh*17;
        float e[17], mx = -1e30f;
        #pragma unroll
        for (int s = 0; s < 17; ++s) mx = fmaxf(mx, sc[gh*17+q][s]);
        float sum = 0.f;
        #pragma unroll
        for (int s = 0; s < 17; ++s) { e[s] = __expf(sc[gh*17+q][s] - mx); sum += e[s]; }
        float inv = 1.f / sum;
        #pragma unroll
        for (int s = 0; s < 17; ++s) pp[gh*32 + q][s] = __float2half_rn(e[s] * inv);
    }
    __syncthreads();
    // attn @ V -> q16
    for (int item = warp; item < 16; item += 8) {
        int gi = item / 8, r = item % 8, hh = r / 2, mt = r % 2;
        float acc[4][4] = {};
        const __half* a0p = &pp[(gi*4+hh)*32 + mt*16 + g][2*t];
        const __half* a1p = a0p + 8*34;
        #pragma unroll
        for (int kt = 0; kt < 2; ++kt) {
            uint32_t a0 = *(const uint32_t*)(a0p+kt*16), a1 = *(const uint32_t*)(a1p+kt*16);
            uint32_t a2 = *(const uint32_t*)(a0p+kt*16+8), a3 = *(const uint32_t*)(a1p+kt*16+8);
            #pragma unroll
            for (int j = 0; j < 4; ++j) {
                const __half* bp = &vT[gi*128 + hh*32 + j*8 + g][kt*16 + 2*t];
                mma16816(acc[j], a0, a1, a2, a3, *(const uint32_t*)bp, *(const uint32_t*)(bp+8));
            }
        }
        int q0 = mt*16 + g;
        #pragma unroll
        for (int j = 0; j < 4; ++j) {
            int col = hh*32 + j*8 + 2*t;
            if (q0 < 17)     *(__half2*)&q16[gi*17+q0][col]   = __floats2half2_rn(acc[j][0], acc[j][1]);
            if (q0 + 8 < 17) *(__half2*)&q16[gi*17+q0+8][col] = __floats2half2_rn(acc[j][2], acc[j][3]);
        }
    }
    __syncthreads();
    // out-proj + residual -> t2 (fp16, quantize-then-stat) AND h32
    for (int item = warp; item < 12; item += 8) {
        int mt = item / 4, ng = item % 4, m0 = mt * 16;
        float acc[4][4] = {};
        mtile<8,16>(&q16[m0 + g][2*t], 136, owf, ng, lane, acc);
        int r0 = m0 + g, r1 = r0 + 8;
        #pragma unroll
        for (int j = 0; j < 4; ++j) {
            int nc = ng*32 + j*8 + 2*t;
            float b0 = ob[nc], b1 = ob[nc+1];
            if (r0 < 34) {
                __half q0h = __float2half_rn(acc[j][0] + b0 + h32[r0][nc]);
                __half q1h = __float2half_rn(acc[j][1] + b1 + h32[r0][nc+1]);
                *(__half2*)&t2g[r0*128+nc] = __halves2half2(q0h, q1h);
                h32[r0][nc] = __half2float(q0h); h32[r0][nc+1] = __half2float(q1h);
            }
            if (r1 < 34) {
                __half q0h = __float2half_rn(acc[j][2] + b0 + h32[r1][nc]);
                __half q1h = __float2half_rn(acc[j][3] + b1 + h32[r1][nc+1]);
                *(__half2*)&t2g[r1*128+nc] = __halves2half2(q0h, q1h);
                h32[r1][nc] = __half2float(q0h); h32[r1][nc+1] = __half2float(q1h);
            }
        }
    }
    __syncthreads();
    {
        float s2 = 0.f, q2 = 0.f;
        for (int i = tid; i < 4352; i += 256) {
            float v = h32[i >> 7][colj];
            s2 += v; q2 = fmaf(v, v, q2);
        }
        mbuf[tid] = s2; mbuf[256 + tid] = q2;
        __syncthreads();
        if (tid < 128) {
            atomicAdd(&accL[256 + tid], mbuf[tid] + mbuf[tid + 128]);
            atomicAdd(&accL[384 + tid], mbuf[256 + tid] + mbuf[384 + tid]);
        }
    }
}

// 4 graphs (68 rows) per block, 2 CTAs/SM
#define P_O16 0
#define P_U16 21760
#define P_O32 64000
#define P_GB  99904
#define SM2   101952

__global__ __launch_bounds__(256, 2)
void k2_s1(const __half* __restrict__ hg0, const float* __restrict__ gcnb,
           const __half* __restrict__ t2,
           const float* __restrict__ accIn, const float* __restrict__ gIn,
           const float* __restrict__ bIn, float invNIn,
           const float* __restrict__ accL, const float* __restrict__ bngL,
           const float* __restrict__ bnbL, float invNC,
           __half* __restrict__ hout, float* __restrict__ accO,
           const uint2* __restrict__ w1f, const float* __restrict__ b1v,
           const uint2* __restrict__ w2f, const float* __restrict__ b2v,
           const float* __restrict__ poses, const float* __restrict__ ew,
           const float* __restrict__ eb, float* __restrict__ pool_out) {
    extern __shared__ char sm[];
    __half (*o16)[136] = (__half(*)[136])(sm + P_O16);
    __half (*u16)[264] = (__half(*)[264])(sm + P_U16);
    float  (*o32)[132] = (float(*)[132]) (sm + P_O32);
    float*  gbuf       = (float*)(sm + P_GB);
    const int tid = threadIdx.x, warp = tid >> 5, lane = tid & 31;
    const int g = lane >> 2, t = lane & 3;
    const int colj = tid & 127;
    const int col0 = (2 * tid) & 127;
    const __half* hgA = hg0 + (size_t)blockIdx.x * 8704;
    const __half* t2g = t2 + (size_t)blockIdx.x * 8704;
    __half* og = hout + (size_t)blockIdx.x * 8704;
    float2 f1a = mkfold(accL, invNC, bngL, bnbL, col0);
    float2 f1b = mkfold(accL, invNC, bngL, bnbL, col0 + 1);
    float2 f2a = mkfold(accL + 256, invNC, bngL + 128, bnbL + 128, col0);
    float2 f2b = mkfold(accL + 256, invNC, bngL + 128, bnbL + 128, col0 + 1);

    for (int j = tid; j < 512; j += 256)
        gbuf[j] = gcnb[(size_t)blockIdx.x * 512 + j];
    {
        uint4 zz = make_uint4(0,0,0,0);
        uint4* z = (uint4*)&o16[68][0];
        for (int i = tid; i < 204; i += 256) z[i] = zz;
    }
    __syncthreads();
    const __half2* t2g2 = (const __half2*)t2g;
    if (poses) { // layer 0: recompute embed (2 cols/thread)
        float ewx0 = ew[2*col0], ewy0 = ew[2*col0+1], eb0 = eb[col0];
        float ewx1 = ew[2*col0+2], ewy1 = ew[2*col0+3], eb1 = eb[col0+1];
        const float2* pz2 = (const float2*)poses;
        for (int i2 = tid; i2 < 4352; i2 += 256) {
            int rr = i2 >> 6;
            float2 p = pz2[blockIdx.x * 68 + rr];
            float h0 = fmaf(p.x, ewx0, fmaf(p.y, ewy0, eb0));
            float h1 = fmaf(p.x, ewx1, fmaf(p.y, ewy1, eb1));
            h0 = h0 > 0.f ? h0 : 0.01f * h0;
            h1 = h1 > 0.f ? h1 : 0.01f * h1;
            float gc = gbuf[(rr/17)*128 + col0], gc1 = gbuf[(rr/17)*128 + col0 + 1];
            float2 tv = __half22float2(t2g2[i2]);
            float o0 = fmaf(gc + h0, f1a.x, f1a.y) + fmaf(tv.x, f2a.x, f2a.y);
            float o1 = fmaf(gc1 + h1, f1b.x, f1b.y) + fmaf(tv.y, f2b.x, f2b.y);
            o32[rr][col0] = o0; o32[rr][col0+1] = o1;
            *(__half2*)&o16[rr][col0] = __floats2half2_rn(o0, o1);
        }
    } else {
        float2 fia = mkfold(accIn, invNIn, gIn, bIn, col0);
        float2 fib = mkfold(accIn, invNIn, gIn, bIn, col0 + 1);
        const __half2* hg2 = (const __half2*)hgA;
        for (int i2 = tid; i2 < 4352; i2 += 256) {
            int rr = i2 >> 6;
            float2 hv = __half22float2(hg2[i2]);
            float gc = gbuf[(rr/17)*128 + col0], gc1 = gbuf[(rr/17)*128 + col0 + 1];
            float t10 = gc + fmaf(hv.x, fia.x, fia.y);
            float t11 = gc1 + fmaf(hv.y, fib.x, fib.y);
            float2 tv = __half22float2(t2g2[i2]);
            float o0 = fmaf(t10, f1a.x, f1a.y) + fmaf(tv.x, f2a.x, f2a.y);
            float o1 = fmaf(t11, f1b.x, f1b.y) + fmaf(tv.y, f2b.x, f2b.y);
            o32[rr][col0] = o0; o32[rr][col0+1] = o1;
            *(__half2*)&o16[rr][col0] = __floats2half2_rn(o0, o1);
        }
    }
    __syncthreads();
    for (int item = warp; item < 40; item += 8) {
        int mt = item / 8, ng = item % 8, m0 = mt * 16;
        float acc[4][4] = {};
        mtile<8,32>(&o16[m0 + g][2*t], 136, w1f, ng, lane, acc);
        int r0 = m0 + g, r1 = r0 + 8;
        #pragma unroll
        for (int j = 0; j < 4; ++j) {
            int nc = ng*32 + j*8 + 2*t;
            float b0 = b1v[nc], b1 = b1v[nc+1];
            *(__half2*)&u16[r0][nc] = __floats2half2_rn(fmaxf(acc[j][0]+b0, 0.f), fmaxf(acc[j][1]+b1, 0.f));
            *(__half2*)&u16[r1][nc] = __floats2half2_rn(fmaxf(acc[j][2]+b0, 0.f), fmaxf(acc[j][3]+b1, 0.f));
        }
    }
    __syncthreads();
    // mlp2 + residual -> og (fp16, quantize-then-stat) AND o32
    for (int item = warp; item < 20; item += 8) {
        int mt = item / 4, ng = item % 4, m0 = mt * 16;
        float acc[4][4] = {};
        mtile<16,16>(&u16[m0 + g][2*t], 264, w2f, ng, lane, acc);
        int r0 = m0 + g, r1 = r0 + 8;
        #pragma unroll
        for (int j = 0; j < 4; ++j) {
            int nc = ng*32 + j*8 + 2*t;
            float b0 = b2v[nc], b1 = b2v[nc+1];
            if (r0 < 68) {
                __half q0h = __float2half_rn(acc[j][0] + b0 + o32[r0][nc]);
                __half q1h = __float2half_rn(acc[j][1] + b1 + o32[r0][nc+1]);
                *(__half2*)&og[r0*128+nc] = __halves2half2(q0h, q1h);
                o32[r0][nc] = __half2float(q0h); o32[r0][nc+1] = __half2float(q1h);
            }
            if (r1 < 68) {
                __half q0h = __float2half_rn(acc[j][2] + b0 + o32[r1][nc]);
                __half q1h = __float2half_rn(acc[j][3] + b1 + o32[r1][nc+1]);
                *(__half2*)&og[r1*128+nc] = __halves2half2(q0h, q1h);
                o32[r1][nc] = __half2float(q0h); o32[r1][nc+1] = __half2float(q1h);
            }
        }
    }
    __syncthreads();
    if (pool_out) {
        for (int j = tid; j < 512; j += 256) {
            int gi = j >> 7, cc = j & 127;
            float s = 0.f;
            #pragma unroll
            for (int r = 0; r < 17; ++r) s += o32[gi*17 + r][cc];
            pool_out[(size_t)blockIdx.x * 512 + j] = s * (1.f / 17.f);
        }
    }
    {
        float s3 = 0.f, q3 = 0.f;
        for (int i = tid; i < 8704; i += 256) {
            float v = o32[i >> 7][colj];
            s3 += v; q3 = fmaf(v, v, q3);
        }
        float* red = (float*)u16;
        red[tid] = s3; red[256 + tid] = q3;
        __syncthreads();
        if (tid < 128) {
            atomicAdd((float*)&accO[tid],       red[tid] + red[tid + 128]);
            atomicAdd((float*)&accO[128 + tid], red[256 + tid] + red[384 + tid]);
        }
    }
}

// ========== stage-2 tensor kernels: 4 graphs x 12 nodes = 48 rows ==========
#define B_H16 0
#define B_Q16 13056
#define B_K16 27200
#define B_VT  41344
#define B_P   57728
#define B_SC  65920
#define B_MB  78976
#define B_H32 83072
#define SM1B  108416

__global__ __launch_bounds__(256, 2)
void k1_s2(const float* __restrict__ hin,
           const float* __restrict__ accIn, const float* __restrict__ gIn,
           const float* __restrict__ bIn, float invNIn,
           float* __restrict__ gcnb, __half* __restrict__ t2, float* __restrict__ accL,
           const float* __restrict__ gwT, const float* __restrict__ gb,
           const float* __restrict__ qb, const float* __restrict__ ob,
           const uint2* __restrict__ qkvf, const uint2* __restrict__ owf) {
    extern __shared__ char sm[];
    __half (*h16)[136] = (__half(*)[136])(sm + B_H16);
    __half (*q16)[136] = (__half(*)[136])(sm + B_Q16);
    __half (*k16)[136] = (__half(*)[136])(sm + B_K16);
    __half (*vT )[16]  = (__half(*)[16]) (sm + B_VT);
    __half (*pp )[16]  = (__half(*)[16]) (sm + B_P);
    float  (*sc )[17]  = (float(*)[17])  (sm + B_SC);
    float*  mbuf       = (float*)(sm + B_MB);
    float  (*h32)[132] = (float(*)[132]) (sm + B_H32);

    const int tid = threadIdx.x, warp = tid >> 5, lane = tid & 31;
    const int g = lane >> 2, t = lane & 3;
    const int colj = tid & 127;
    const float* hg = hin + (size_t)blockIdx.x * 6144;
    __half* t2g = t2 + (size_t)blockIdx.x * 6144;

    {
        uint4 zz = make_uint4(0,0,0,0);
        uint4* z = (uint4*)(sm + B_VT);
        for (int i = tid; i < 1536; i += 256) z[i] = zz;
        uint4* zq = (uint4*)&q16[48][0];
        for (int i = tid; i < 68; i += 256) zq[i] = zz;
        uint4* zk = (uint4*)&k16[48][0];
        for (int i = tid; i < 68; i += 256) zk[i] = zz;
        float2 f = mkfold(accIn, invNIn, gIn, bIn, colj);
        for (int i = tid; i < 6144; i += 256) {
            int rr = i >> 7;
            float v = fmaf(hg[i], f.x, f.y);
            h32[rr][colj] = v;
            h16[rr][colj] = __float2half_rn(v);
        }
    }
    __syncthreads();
    {
        float* scr = (float*)sc;
        for (int j = tid; j < 512; j += 256) {
            int gi = j >> 7, cc = j & 127;
            float s = 0.f, q = 0.f;
            #pragma unroll
            for (int r = 0; r < 12; ++r) {
                float v = h32[gi*12 + r][cc];
                s += v; q = fmaf(v, v, q);
            }
            mbuf[j] = s * (1.f / 12.f);
            scr[j] = q; scr[512 + j] = s;
        }
    }
    __syncthreads();
    {
        float* scr = (float*)sc;
        for (int j = tid; j < 512; j += 256) {
            int gi = j >> 7, cc = j & 127;
            float a = gb[cc];
            const float* mrow = mbuf + gi * 128;
            #pragma unroll 4
            for (int k = 0; k < 128; ++k) a = fmaf(mrow[k], gwT[k*128 + cc], a);
            gcnb[(size_t)blockIdx.x * 512 + j] = a;
            float Sh = scr[512 + j], Sq = scr[j];
            scr[512 + j] = fmaf(12.f, a, Sh);
            scr[j] = fmaf(12.f * a, a, fmaf(2.f * a, Sh, Sq));
        }
    }
    __syncthreads();
    if (tid < 128) {
        float* scr = (float*)sc;
        atomicAdd(&accL[tid],       scr[512+tid] + scr[640+tid] + scr[768+tid] + scr[896+tid]);
        atomicAdd(&accL[128 + tid], scr[tid] + scr[128+tid] + scr[256+tid] + scr[384+tid]);
    }
    for (int item = warp; item < 36; item += 8) {
        int mt = item / 12, ng = item % 12, m0 = mt * 16;
        float acc[4][4] = {};
        mtile<8,48>(&h16[m0 + g][2*t], 136, qkvf, ng, lane, acc);
        int r0 = m0 + g, r1 = r0 + 8;
        #pragma unroll
        for (int j = 0; j < 4; ++j) {
            int nc = ng*32 + j*8 + 2*t;
            float b0 = qb[nc], b1 = qb[nc+1];
            float v00 = acc[j][0]+b0, v01 = acc[j][1]+b1, v10 = acc[j][2]+b0, v11 = acc[j][3]+b1;
            if (nc < 128) {
                *(__half2*)&q16[r0][nc] = __floats2half2_rn(v00, v01);
                *(__half2*)&q16[r1][nc] = __floats2half2_rn(v10, v11);
            } else if (nc < 256) {
                *(__half2*)&k16[r0][nc-128] = __floats2half2_rn(v00, v01);
                *(__half2*)&k16[r1][nc-128] = __floats2half2_rn(v10, v11);
            } else {
                int d = nc - 256;
                { int gi = r0/12, sl = r0 - gi*12;
                  vT[gi*128+d][sl] = __float2half_rn(v00); vT[gi*128+d+1][sl] = __float2half_rn(v01); }
                { int gi = r1/12, sl = r1 - gi*12;
                  vT[gi*128+d][sl] = __float2half_rn(v10); vT[gi*128+d+1][sl] = __float2half_rn(v11); }
            }
        }
    }
    __syncthreads();
    for (int item = warp; item < 32; item += 8) {
        int gi = item / 8, r = item % 8, hh = r / 2, nt = r % 2;
        int base = gi * 12;
        float acc[4] = {};
        const __half* a0p = &q16[base + g][hh*32 + 2*t];
        const __half* a1p = a0p + 8*136;
        const __half* br  = &k16[base + nt*8 + g][hh*32 + 2*t];
        #pragma unroll
        for (int kt = 0; kt < 2; ++kt) {
            mma16816(acc, *(const uint32_t*)(a0p+kt*16), *(const uint32_t*)(a1p+kt*16),
                     *(const uint32_t*)(a0p+kt*16+8), *(const uint32_t*)(a1p+kt*16+8),
                     *(const uint32_t*)(br+kt*16), *(const uint32_t*)(br+kt*16+8));
        }
        const float invs = 0.17677669529663687f;
        int ss = nt*8 + 2*t, row = (gi*4 + hh)*12;
        { sc[row+g][ss] = acc[0]*invs; sc[row+g][ss+1] = acc[1]*invs; }
        if (g + 8 < 12) { sc[row+g+8][ss] = acc[2]*invs; sc[row+g+8][ss+1] = acc[3]*invs; }
    }
    __syncthreads();
    if (tid < 192) {
        int gh = tid / 12, q = tid - gh*12;
        float e[12], mx = -1e30f;
        #pragma unroll
        for (int s = 0; s < 12; ++s) mx = fmaxf(mx, sc[gh*12+q][s]);
        float sum = 0.f;
        #pragma unroll
        for (int s = 0; s < 12; ++s) { e[s] = __expf(sc[gh*12+q][s] - mx); sum += e[s]; }
        float inv = 1.f / sum;
        #pragma unroll
        for (int s = 0; s < 12; ++s) pp[gh*16 + q][s] = __float2half_rn(e[s] * inv);
    }
    __syncthreads();
    for (int item = warp; item < 16; item += 8) {
        int gi = item / 4, hh = item % 4;
        float acc[4][4] = {};
        const __half* a0p = &pp[(gi*4+hh)*16 + g][2*t];
        const __half* a1p = a0p + 8*16;
        uint32_t a0 = *(const uint32_t*)a0p,       a1 = *(const uint32_t*)a1p;
        uint32_t a2 = *(const uint32_t*)(a0p + 8), a3 = *(const uint32_t*)(a1p + 8);
        #pragma unroll
        for (int j = 0; j < 4; ++j) {
            const __half* bp = &vT[gi*128 + hh*32 + j*8 + g][2*t];
            mma16816(acc[j], a0, a1, a2, a3, *(const uint32_t*)bp, *(const uint32_t*)(bp+8));
        }
        #pragma unroll
        for (int j = 0; j < 4; ++j) {
            int col = hh*32 + j*8 + 2*t;
            *(__half2*)&q16[gi*12+g][col] = __floats2half2_rn(acc[j][0], acc[j][1]);
            if (g + 8 < 12) *(__half2*)&q16[gi*12+g+8][col] = __floats2half2_rn(acc[j][2], acc[j][3]);
        }
    }
    __syncthreads();
    for (int item = warp; item < 12; item += 8) {
        int mt = item / 4, ng = item % 4, m0 = mt * 16;
        float acc[4][4] = {};
        mtile<8,16>(&q16[m0 + g][2*t], 136, owf, ng, lane, acc);
        int r0 = m0 + g, r1 = r0 + 8;
        #pragma unroll
        for (int j = 0; j < 4; ++j) {
            int nc = ng*32 + j*8 + 2*t;
            float b0 = ob[nc], b1 = ob[nc+1];
            {
                __half q0h = __float2half_rn(acc[j][0] + b0 + h32[r0][nc]);
                __half q1h = __float2half_rn(acc[j][1] + b1 + h32[r0][nc+1]);
                *(__half2*)&t2g[r0*128+nc] = __halves2half2(q0h, q1h);
                h32[r0][nc] = __half2float(q0h); h32[r0][nc+1] = __half2float(q1h);
            }
            {
                __half q0h = __float2half_rn(acc[j][2] + b0 + h32[r1][nc]);
                __half q1h = __float2half_rn(acc[j][3] + b1 + h32[r1][nc+1]);
                *(__half2*)&t2g[r1*128+nc] = __halves2half2(q0h, q1h);
                h32[r1][nc] = __half2float(q0h); h32[r1][nc+1] = __half2float(q1h);
            }
        }
    }
    __syncthreads();
    {
        float s2 = 0.f, q2 = 0.f;
        for (int i = tid; i < 6144; i += 256) {
            float v = h32[i >> 7][colj];
            s2 += v; q2 = fmaf(v, v, q2);
        }
        mbuf[tid] = s2; mbuf[256 + tid] = q2;
        __syncthreads();
        if (tid < 128) {
            atomicAdd(&accL[256 + tid], mbuf[tid] + mbuf[tid + 128]);
            atomicAdd(&accL[384 + tid], mbuf[256 + tid] + mbuf[384 + tid]);
        }
    }
}

#define C_O16 0
#define C_U16 13056
#define C_O32 38400
#define C_GB  63744
#define SM2B  65792

__global__ __launch_bounds__(256, 2)
void k2_s2(const float* __restrict__ hg0, const float* __restrict__ gcnb,
           const __half* __restrict__ t2,
           const float* __restrict__ accIn, const float* __restrict__ gIn,
           const float* __restrict__ bIn, float invNIn,
           const float* __restrict__ accL, const float* __restrict__ bngL,
           const float* __restrict__ bnbL, float invNC,
           float* __restrict__ hout, float* __restrict__ accO,
           const uint2* __restrict__ w1f, const float* __restrict__ b1v,
           const uint2* __restrict__ w2f, const float* __restrict__ b2v) {
    extern __shared__ char sm[];
    __half (*o16)[136] = (__half(*)[136])(sm + C_O16);
    __half (*u16)[264] = (__half(*)[264])(sm + C_U16);
    float  (*o32)[132] = (float(*)[132]) (sm + C_O32);
    float*  gbuf       = (float*)(sm + C_GB);
    const int tid = threadIdx.x, warp = tid >> 5, lane = tid & 31;
    const int g = lane >> 2, t = lane & 3;
    const int colj = tid & 127;
    const float* hgA = hg0 + (size_t)blockIdx.x * 6144;
    const __half* t2g = t2 + (size_t)blockIdx.x * 6144;
    float* og = hout + (size_t)blockIdx.x * 6144;
    float2 fi = mkfold(accIn, invNIn, gIn, bIn, colj);
    float2 f1 = mkfold(accL, invNC, bngL, bnbL, colj);
    float2 f2 = mkfold(accL + 256, invNC, bngL + 128, bnbL + 128, colj);

    if (tid < 256) gbuf[tid] = gcnb[(size_t)blockIdx.x * 512 + tid];
    if (tid < 256) gbuf[256 + tid] = gcnb[(size_t)blockIdx.x * 512 + 256 + tid];
    __syncthreads();
    for (int i = tid; i < 6144; i += 256) {
        int rr = i >> 7;
        float t1v = gbuf[(rr/12)*128 + colj] + fmaf(hgA[i], fi.x, fi.y);
        float o = fmaf(t1v, f1.x, f1.y) + fmaf(__half2float(t2g[i]), f2.x, f2.y);
        o32[rr][colj] = o;
        o16[rr][colj] = __float2half_rn(o);
    }
    __syncthreads();
    for (int item = warp; item < 24; item += 8) {
        int mt = item / 8, ng = item % 8, m0 = mt * 16;
        float acc[4][4] = {};
        mtile<8,32>(&o16[m0 + g][2*t], 136, w1f, ng, lane, acc);
        int r0 = m0 + g, r1 = r0 + 8;
        #pragma unroll
        for (int j = 0; j < 4; ++j) {
            int nc = ng*32 + j*8 + 2*t;
            float b0 = b1v[nc], b1 = b1v[nc+1];
            *(__half2*)&u16[r0][nc] = __floats2half2_rn(fmaxf(acc[j][0]+b0, 0.f), fmaxf(acc[j][1]+b1, 0.f));
            *(__half2*)&u16[r1][nc] = __floats2half2_rn(fmaxf(acc[j][2]+b0, 0.f), fmaxf(acc[j][3]+b1, 0.f));
        }
    }
    __syncthreads();
    for (int item = warp; item < 12; item += 8) {
        int mt = item / 4, ng = item % 4, m0 = mt * 16;
        float acc[4][4] = {};
        mtile<16,16>(&u16[m0 + g][2*t], 264, w2f, ng, lane, acc);
        int r0 = m0 + g, r1 = r0 + 8;
        #pragma unroll
        for (int j = 0; j < 4; ++j) {
            int nc = ng*32 + j*8 + 2*t;
            float b0 = b2v[nc], b1 = b2v[nc+1];
            {
                float v0 = acc[j][0] + b0 + o32[r0][nc];
                float v1 = acc[j][1] + b1 + o32[r0][nc+1];
                og[r0*128+nc] = v0; og[r0*128+nc+1] = v1;
                o32[r0][nc] = v0; o32[r0][nc+1] = v1;
            }
            {
                float v0 = acc[j][2] + b0 + o32[r1][nc];
                float v1 = acc[j][3] + b1 + o32[r1][nc+1];
                og[r1*128+nc] = v0; og[r1*128+nc+1] = v1;
                o32[r1][nc] = v0; o32[r1][nc+1] = v1;
            }
        }
    }
    __syncthreads();
    {
        float s3 = 0.f, q3 = 0.f;
        for (int i = tid; i < 6144; i += 256) {
            float v = o32[i >> 7][colj];
            s3 += v; q3 = fmaf(v, v, q3);
        }
        float* red = (float*)u16;
        red[tid] = s3; red[256 + tid] = q3;
        __syncthreads();
        if (tid < 128) {
            atomicAdd((float*)&accO[tid],       red[tid] + red[tid + 128]);
            atomicAdd((float*)&accO[128 + tid], red[256 + tid] + red[384 + tid]);
        }
    }
}

extern "C" void kernel_launch(void* const* d_in, const int* in_sizes, int n_in,
                              void* d_out, int out_size) {
    const float* poses = (const float*)d_in[0];
    const float* emb_w = (const float*)d_in[1];
    const float* emb_b = (const float*)d_in[2];
    const float* cls_w = (const float*)d_in[3];
    const float* cls_b = (const float*)d_in[4];
    const float* PPj[12]; const float* PPi[12];
    for (int i = 0; i < 12; ++i) { PPj[i] = (const float*)d_in[5+i]; PPi[i] = (const float*)d_in[17+i]; }

    float *A, *Bb, *Cc, *A2, *B2, *C2, *acc, *wT; uint2* wf;
    cudaGetSymbolAddress((void**)&A,    g_A);
    cudaGetSymbolAddress((void**)&Bb,   g_B);
    cudaGetSymbolAddress((void**)&Cc,   g_C);
    cudaGetSymbolAddress((void**)&A2,   g_A2);
    cudaGetSymbolAddress((void**)&B2,   g_B2);
    cudaGetSymbolAddress((void**)&C2,   g_C2);
    cudaGetSymbolAddress((void**)&acc,  g_acc);
    cudaGetSymbolAddress((void**)&wT,   g_wT);
    cudaGetSymbolAddress((void**)&wf,   g_wf);
    uint2* wf2 = wf + 98304;
    __half* Ah  = (__half*)A;
    __half* Ch  = (__half*)Cc;
    __half* C2h = (__half*)C2;
    const float inv1 = 1.f / 365568.f, inv2 = 1.f / 21504.f;

    cudaFuncSetAttribute(k1_s1, cudaFuncAttributeMaxDynamicSharedMemorySize, SM1);
    cudaFuncSetAttribute(k2_s1, cudaFuncAttributeMaxDynamicSharedMemorySize, SM2);
    cudaFuncSetAttribute(k1_s2, cudaFuncAttributeMaxDynamicSharedMemorySize, SM1B);
    cudaFuncSetAttribute(k2_s2, cudaFuncAttributeMaxDynamicSharedMemorySize, SM2B);

    init_kernel<<<18, 256>>>(acc);

    transpose_kernel<<<192, 256>>>(PPj[0], wT, 128, 128, 49152);
    transpose_kernel<<<192, 256>>>(PPi[0], wT + 49152, 128, 128, 49152);
    for (int l = 0; l < 3; ++l) {
        prep_frag<<<48, 256>>>(PPj[2]  + l*49152, wf + l*32768,          48, 128, 12288);
        prep_frag<<<16, 256>>>(PPj[4]  + l*16384, wf + l*32768 + 12288,  16, 128, 4096);
        prep_frag<<<32, 256>>>(PPj[8]  + l*32768, wf + l*32768 + 16384,  32, 128, 8192);
        prep_frag<<<32, 256>>>(PPj[10] + l*32768, wf + l*32768 + 24576,  16, 256, 8192);
        prep_frag<<<48, 256>>>(PPi[2]  + l*49152, wf2 + l*32768,         48, 128, 12288);
        prep_frag<<<16, 256>>>(PPi[4]  + l*16384, wf2 + l*32768 + 12288, 16, 128, 4096);
        prep_frag<<<32, 256>>>(PPi[8]  + l*32768, wf2 + l*32768 + 16384, 32, 128, 8192);
        prep_frag<<<32, 256>>>(PPi[10] + l*32768, wf2 + l*32768 + 24576, 16, 256, 8192);
    }

    // stage 1 (A/t2 fp16; folds inline; embed fused l0; pool fused l2)
    const float* accPrev = nullptr;
    const float* gPrev = nullptr;
    const float* bPrev = nullptr;
    for (int l = 0; l < 3; ++l) {
        float* accL = acc + l * 768;
        const float* pz = (l == 0) ? poses : nullptr;
        k1_s1<<<10752, 256, SM1>>>(Ah, accPrev, gPrev, bPrev, inv1,
                                   Bb, Ch, accL,
                                   wT + l*16384, PPj[1] + l*128, PPj[3] + l*384, PPj[5] + l*128,
                                   wf + l*32768, wf + l*32768 + 12288,
                                   pz, emb_w, emb_b);
        k2_s1<<<5376, 256, SM2>>>(Ah, Bb, Ch, accPrev, gPrev, bPrev, inv1,
                                  accL, PPj[6] + l*384, PPj[7] + l*384, inv1,
                                  Ah, accL + 512,
                                  wf + l*32768 + 16384, PPj[9] + l*256,
                                  wf + l*32768 + 24576, PPj[11] + l*128,
                                  pz, emb_w, emb_b, (l == 2) ? A2 : nullptr);
        accPrev = accL + 512;
        gPrev = PPj[6] + l*384 + 256;
        bPrev = PPj[7] + l*384 + 256;
    }

    // stage 2 (A2 fp32)
    float invNIn = inv1;
    for (int l = 0; l < 3; ++l) {
        float* accL = acc + 2304 + l * 768;
        k1_s2<<<448, 256, SM1B>>>(A2, accPrev, gPrev, bPrev, invNIn,
                                  B2, C2h, accL,
                                  wT + 49152 + l*16384, PPi[1] + l*128, PPi[3] + l*384, PPi[5] + l*128,
                                  wf2 + l*32768, wf2 + l*32768 + 12288);
        k2_s2<<<448, 256, SM2B>>>(A2, B2, C2h, accPrev, gPrev, bPrev, invNIn,
                                  accL, PPi[6] + l*384, PPi[7] + l*384, inv2,
                                  A2, accL + 512,
                                  wf2 + l*32768 + 16384, PPi[9] + l*256,
                                  wf2 + l*32768 + 24576, PPi[11] + l*128);
        accPrev = accL + 512;
        gPrev = PPi[6] + l*384 + 256;
        bPrev = PPi[7] + l*384 + 256;
        invNIn = inv2;
    }

    pool2_cls_kernel<<<256, 128>>>(A2, accPrev, gPrev, bPrev, inv2,
                                   cls_w, cls_b, (float*)d_out);
}

// round 17
// speedup vs baseline: 1.7200x; 1.1956x over previous
#include <cuda_runtime.h>
#include <cuda_fp16.h>
#include <stdint.h>

#define D 128

static __device__ float g_A [46792704];
static __device__ float g_B [46792704];
static __device__ float g_C [46792704];
static __device__ float g_A2[ 2752512];
static __device__ float g_B2[ 2752512];
static __device__ float g_C2[ 2752512];
static __device__ float g_acc [18*256];
static __device__ float g_wT  [98304];
static __device__ uint2 g_wf  [196608];

__global__ void init_kernel(float* acc) {
    int t = blockIdx.x * blockDim.x + threadIdx.x;
    if (t < 18*256) acc[t] = 0.f;
}

__global__ void transpose_kernel(const float* __restrict__ src, float* __restrict__ dst,
                                 int R, int C, int total) {
    int idx = blockIdx.x * blockDim.x + threadIdx.x;
    if (idx >= total) return;
    int m = idx / (R * C), rc = idx - m * (R * C), cc = rc / R, r = rc - cc * R;
    dst[idx] = src[m * R * C + r * C + cc];
}

__global__ void prep_frag(const float* __restrict__ W, uint2* __restrict__ out,
                          int NT, int K, int total) {
    int idx = blockIdx.x * blockDim.x + threadIdx.x;
    if (idx >= total) return;
    int lane = idx & 31, tile = idx >> 5;
    int nt = tile % NT, kt = tile / NT;
    int g = lane >> 2, t = lane & 3;
    const float* w = W + (size_t)(nt * 8 + g) * K + kt * 16 + 2 * t;
    __half2 b0 = __floats2half2_rn(w[0], w[1]);
    __half2 b1 = __floats2half2_rn(w[8], w[9]);
    uint2 o; o.x = *(uint32_t*)&b0; o.y = *(uint32_t*)&b1;
    out[idx] = o;
}

// inline BN fold from raw sums
__device__ __forceinline__ float2 mkfold(const float* __restrict__ a, float invN,
                                         const float* __restrict__ gg,
                                         const float* __restrict__ bb, int c) {
    float m = a[c] * invN;
    float v = fmaxf(a[128 + c] * invN - m * m, 0.f);
    float s = rsqrtf(v + 1e-5f) * gg[c];
    return make_float2(s, fmaf(-m, s, bb[c]));
}

__global__ void pool2_cls_kernel(const float* __restrict__ hin,
                                 const float* __restrict__ accIn, const float* __restrict__ gIn,
                                 const float* __restrict__ bIn, float invN,
                                 const float* __restrict__ cw, const float* __restrict__ cb,
                                 float* __restrict__ out) {
    __shared__ float p_s[D];
    int b = blockIdx.x, c = threadIdx.x;
    float2 f = mkfold(accIn, invN, gIn, bIn, c);
    const float* base = hin + (size_t)b * 84 * D + c;
    float s = 0.f;
    #pragma unroll 4
    for (int r = 0; r < 84; ++r) s += base[r * D];
    p_s[c] = fmaf(s * (1.f / 84.f), f.x, f.y);
    __syncthreads();
    if (c < 8) {
        float acc = cb[c];
        #pragma unroll 4
        for (int k = 0; k < D; ++k) acc = fmaf(p_s[k], cw[c * D + k], acc);
        out[b * 8 + c] = acc;
    }
}

__device__ __forceinline__ void mma16816(float* c, uint32_t a0, uint32_t a1,
                                         uint32_t a2, uint32_t a3, uint32_t b0, uint32_t b1) {
    asm("mma.sync.aligned.m16n8k16.row.col.f32.f16.f16.f32 "
        "{%0,%1,%2,%3},{%4,%5,%6,%7},{%8,%9},{%0,%1,%2,%3};"
        : "+f"(c[0]), "+f"(c[1]), "+f"(c[2]), "+f"(c[3])
        : "r"(a0), "r"(a1), "r"(a2), "r"(a3), "r"(b0), "r"(b1));
}

// multi-M-tile GEMM: loads each B fragment ONCE, applies to MT m-tiles
template<int KT, int NT, int MT>
__device__ __forceinline__ void mtileM(const __half* a_base, int lda, const uint2* __restrict__ wf,
                                       int ng, int lane, float acc[MT][4][4]) {
    #pragma unroll
    for (int kt = 0; kt < KT; ++kt) {
        uint2 b0 = wf[(kt*NT + ng*4 + 0)*32 + lane];
        uint2 b1 = wf[(kt*NT + ng*4 + 1)*32 + lane];
        uint2 b2 = wf[(kt*NT + ng*4 + 2)*32 + lane];
        uint2 b3 = wf[(kt*NT + ng*4 + 3)*32 + lane];
        #pragma unroll
        for (int m = 0; m < MT; ++m) {
            const __half* a0p = a_base + m*16*lda + kt*16;
            const __half* a1p = a0p + 8*lda;
            uint32_t a0 = *(const uint32_t*)a0p;
            uint32_t a1 = *(const uint32_t*)a1p;
            uint32_t a2 = *(const uint32_t*)(a0p + 8);
            uint32_t a3 = *(const uint32_t*)(a1p + 8);
            mma16816(acc[m][0], a0, a1, a2, a3, b0.x, b0.y);
            mma16816(acc[m][1], a0, a1, a2, a3, b1.x, b1.y);
            mma16816(acc[m][2], a0, a1, a2, a3, b2.x, b2.y);
            mma16816(acc[m][3], a0, a1, a2, a3, b3.x, b3.y);
        }
    }
}

// ---------------- stage-1 tensor kernels: 2 graphs (34 rows), 2 CTAs/SM ----
#define O_H16 0
#define O_Q16 13056
#define O_K16 26112
#define O_VT  39168
#define O_P   56576
#define O_SC  73984
#define O_MB  87584
#define O_H32 91680
#define SM1   109632

__global__ __launch_bounds__(256, 2)
void k1_s1(const __half* __restrict__ hin,
           const float* __restrict__ accIn, const float* __restrict__ gIn,
           const float* __restrict__ bIn, float invNIn,
           float* __restrict__ gcnb, __half* __restrict__ t2, float* __restrict__ accL,
           const float* __restrict__ gwT, const float* __restrict__ gb,
           const float* __restrict__ qb, const float* __restrict__ ob,
           const uint2* __restrict__ qkvf, const uint2* __restrict__ owf,
           const float* __restrict__ poses, const float* __restrict__ ew,
           const float* __restrict__ eb) {
    extern __shared__ char sm[];
    __half (*h16)[136] = (__half(*)[136])(sm + O_H16);
    __half (*q16)[136] = (__half(*)[136])(sm + O_Q16);
    __half (*k16)[136] = (__half(*)[136])(sm + O_K16);
    __half (*vT )[34]  = (__half(*)[34]) (sm + O_VT);
    __half (*pp )[34]  = (__half(*)[34]) (sm + O_P);
    float  (*sc )[25]  = (float(*)[25])  (sm + O_SC);
    float*  mbuf       = (float*)(sm + O_MB);
    float  (*h32)[132] = (float(*)[132]) (sm + O_H32);

    const int tid = threadIdx.x, warp = tid >> 5, lane = tid & 31;
    const int g = lane >> 2, t = lane & 3;
    const int colj = tid & 127;
    const int col0 = (2 * tid) & 127;
    const __half* hg = hin + (size_t)blockIdx.x * 4352;
    __half* t2g = t2 + (size_t)blockIdx.x * 4352;

    {
        uint4 zz = make_uint4(0,0,0,0);
        uint4* z = (uint4*)(sm + O_VT);
        for (int i = tid; i < 2176; i += 256) z[i] = zz;
        uint4* zh = (uint4*)&h16[34][0];
        for (int i = tid; i < 238; i += 256) zh[i] = zz;
        if (poses) { // layer 0: fused embed (2 cols/thread)
            float ewx0 = ew[2*col0], ewy0 = ew[2*col0+1], eb0 = eb[col0];
            float ewx1 = ew[2*col0+2], ewy1 = ew[2*col0+3], eb1 = eb[col0+1];
            const float2* pz2 = (const float2*)poses;
            for (int i2 = tid; i2 < 2176; i2 += 256) {
                int rr = i2 >> 6;
                float2 p = pz2[blockIdx.x * 34 + rr];
                float v0 = fmaf(p.x, ewx0, fmaf(p.y, ewy0, eb0));
                float v1 = fmaf(p.x, ewx1, fmaf(p.y, ewy1, eb1));
                v0 = v0 > 0.f ? v0 : 0.01f * v0;
                v1 = v1 > 0.f ? v1 : 0.01f * v1;
                h32[rr][col0] = v0; h32[rr][col0+1] = v1;
                *(__half2*)&h16[rr][col0] = __floats2half2_rn(v0, v1);
            }
        } else {
            float2 f0 = mkfold(accIn, invNIn, gIn, bIn, col0);
            float2 f1 = mkfold(accIn, invNIn, gIn, bIn, col0 + 1);
            const __half2* hg2 = (const __half2*)hg;
            for (int i2 = tid; i2 < 2176; i2 += 256) {
                int rr = i2 >> 6;
                float2 hv = __half22float2(hg2[i2]);
                float v0 = fmaf(hv.x, f0.x, f0.y);
                float v1 = fmaf(hv.y, f1.x, f1.y);
                h32[rr][col0] = v0; h32[rr][col0+1] = v1;
                *(__half2*)&h16[rr][col0] = __floats2half2_rn(v0, v1);
            }
        }
    }
    __syncthreads();
    {
        int gi = tid >> 7, cc = tid & 127;
        float s = 0.f, q = 0.f;
        #pragma unroll
        for (int r = 0; r < 17; ++r) {
            float v = h32[gi*17 + r][cc];
            s += v; q = fmaf(v, v, q);
        }
        mbuf[tid] = s * (1.f / 17.f);
        float* scr = (float*)sc;
        scr[tid] = q;
        scr[256 + tid] = s;
    }
    __syncthreads();
    {
        int gi = tid >> 7, cc = tid & 127;
        float a = gb[cc];
        const float* mrow = mbuf + gi * 128;
        #pragma unroll 4
        for (int k = 0; k < 128; ++k) a = fmaf(mrow[k], gwT[k*128 + cc], a);
        gcnb[(size_t)blockIdx.x * 256 + tid] = a;
        float* scr = (float*)sc;
        float Sh = scr[256 + tid], Sq = scr[tid];
        scr[256 + tid] = fmaf(17.f, a, Sh);
        scr[tid] = fmaf(17.f * a, a, fmaf(2.f * a, Sh, Sq));
    }
    __syncthreads();
    if (tid < 128) {
        float* scr = (float*)sc;
        atomicAdd(&accL[tid],       scr[256 + tid] + scr[384 + tid]);
        atomicAdd(&accL[128 + tid], scr[tid] + scr[tid + 128]);
    }
    // qkv: M=48, N=384, K=128 — B loaded once per 3 m-tiles
    for (int item = warp; item < 12; item += 8) {
        int ng = item;
        float acc[3][4][4] = {};
        mtileM<8,48,3>(&h16[g][2*t], 136, qkvf, ng, lane, acc);
        #pragma unroll
        for (int mt = 0; mt < 3; ++mt) {
            int r0 = mt*16 + g, r1 = r0 + 8;
            #pragma unroll
            for (int j = 0; j < 4; ++j) {
                int nc = ng*32 + j*8 + 2*t;
                float b0 = qb[nc], b1 = qb[nc+1];
                float v00 = acc[mt][j][0]+b0, v01 = acc[mt][j][1]+b1;
                float v10 = acc[mt][j][2]+b0, v11 = acc[mt][j][3]+b1;
                if (nc < 128) {
                    *(__half2*)&q16[r0][nc] = __floats2half2_rn(v00, v01);
                    *(__half2*)&q16[r1][nc] = __floats2half2_rn(v10, v11);
                } else if (nc < 256) {
                    *(__half2*)&k16[r0][nc-128] = __floats2half2_rn(v00, v01);
                    *(__half2*)&k16[r1][nc-128] = __floats2half2_rn(v10, v11);
                } else {
                    int d = nc - 256;
                    if (r0 < 34) { int gi = r0/17, sl = r0 - gi*17;
                        vT[gi*128+d][sl] = __float2half_rn(v00); vT[gi*128+d+1][sl] = __float2half_rn(v01); }
                    if (r1 < 34) { int gi = r1/17, sl = r1 - gi*17;
                        vT[gi*128+d][sl] = __float2half_rn(v10); vT[gi*128+d+1][sl] = __float2half_rn(v11); }
                }
            }
        }
    }
    __syncthreads();
    // scores
    for (int item = warp; item < 48; item += 8) {
        int gi = item / 24, r = item % 24, hh = r / 6, r2 = r % 6, mt = r2 / 3, nt = r2 % 3;
        int base = gi * 17;
        float acc[4] = {};
        const __half* a0p = &q16[base + mt*16 + g][hh*32 + 2*t];
        const __half* a1p = a0p + 8*136;
        const __half* br  = &k16[base + nt*8 + g][hh*32 + 2*t];
        #pragma unroll
        for (int kt = 0; kt < 2; ++kt) {
            mma16816(acc, *(const uint32_t*)(a0p+kt*16), *(const uint32_t*)(a1p+kt*16),
                     *(const uint32_t*)(a0p+kt*16+8), *(const uint32_t*)(a1p+kt*16+8),
                     *(const uint32_t*)(br+kt*16), *(const uint32_t*)(br+kt*16+8));
        }
        const float invs = 0.17677669529663687f;
        int q0 = mt*16 + g, ss = nt*8 + 2*t, row = (gi*4 + hh)*17;
        if (q0 < 17)     { sc[row+q0][ss]   = acc[0]*invs; sc[row+q0][ss+1]   = acc[1]*invs; }
        if (q0 + 8 < 17) { sc[row+q0+8][ss] = acc[2]*invs; sc[row+q0+8][ss+1] = acc[3]*invs; }
    }
    __syncthreads();
    for (int idx = tid; idx < 136; idx += 256) {
        int gh = idx / 17, q = idx - gh*17;
        float e[17], mx = -1e30f;
        #pragma unroll
        for (int s = 0; s < 17; ++s) mx = fmaxf(mx, sc[gh*17+q][s]);
        float sum = 0.f;
        #pragma unroll
        for (int s = 0; s < 17; ++s) { e[s] = __expf(sc[gh*17+q][s] - mx); sum += e[s]; }
        float inv = 1.f / sum;
        #pragma unroll
        for (int s = 0; s < 17; ++s) pp[gh*32 + q][s] = __float2half_rn(e[s] * inv);
    }
    __syncthreads();
    // attn @ V -> q16
    for (int item = warp; item < 16; item += 8) {
        int gi = item / 8, r = item % 8, hh = r / 2, mt = r % 2;
        float acc[4][4] = {};
        const __half* a0p = &pp[(gi*4+hh)*32 + mt*16 + g][2*t];
        const __half* a1p = a0p + 8*34;
        #pragma unroll
        for (int kt = 0; kt < 2; ++kt) {
            uint32_t a0 = *(const uint32_t*)(a0p+kt*16), a1 = *(const uint32_t*)(a1p+kt*16);
            uint32_t a2 = *(const uint32_t*)(a0p+kt*16+8), a3 = *(const uint32_t*)(a1p+kt*16+8);
            #pragma unroll
            for (int j = 0; j < 4; ++j) {
                const __half* bp = &vT[gi*128 + hh*32 + j*8 + g][kt*16 + 2*t];
                mma16816(acc[j], a0, a1, a2, a3, *(const uint32_t*)bp, *(const uint32_t*)(bp+8));
            }
        }
        int q0 = mt*16 + g;
        #pragma unroll
        for (int j = 0; j < 4; ++j) {
            int col = hh*32 + j*8 + 2*t;
            if (q0 < 17)     *(__half2*)&q16[gi*17+q0][col]   = __floats2half2_rn(acc[j][0], acc[j][1]);
            if (q0 + 8 < 17) *(__half2*)&q16[gi*17+q0+8][col] = __floats2half2_rn(acc[j][2], acc[j][3]);
        }
    }
    __syncthreads();
    // out-proj + residual -> t2 (fp16) AND h32 — B loaded once per m-chunk (2+1)
    for (int item = warp; item < 8; item += 8) {
        int ch = item >> 2, ng = item & 3;
        if (ch == 0) {
            float acc[2][4][4] = {};
            mtileM<8,16,2>(&q16[g][2*t], 136, owf, ng, lane, acc);
            #pragma unroll
            for (int mt = 0; mt < 2; ++mt) {
                int r0 = mt*16 + g, r1 = r0 + 8;
                #pragma unroll
                for (int j = 0; j < 4; ++j) {
                    int nc = ng*32 + j*8 + 2*t;
                    float b0 = ob[nc], b1 = ob[nc+1];
                    if (r0 < 34) {
                        __half q0h = __float2half_rn(acc[mt][j][0] + b0 + h32[r0][nc]);
                        __half q1h = __float2half_rn(acc[mt][j][1] + b1 + h32[r0][nc+1]);
                        *(__half2*)&t2g[r0*128+nc] = __halves2half2(q0h, q1h);
                        h32[r0][nc] = __half2float(q0h); h32[r0][nc+1] = __half2float(q1h);
                    }
                    if (r1 < 34) {
                        __half q0h = __float2half_rn(acc[mt][j][2] + b0 + h32[r1][nc]);
                        __half q1h = __float2half_rn(acc[mt][j][3] + b1 + h32[r1][nc+1]);
                        *(__half2*)&t2g[r1*128+nc] = __halves2half2(q0h, q1h);
                        h32[r1][nc] = __half2float(q0h); h32[r1][nc+1] = __half2float(q1h);
                    }
                }
            }
        } else {
            float acc[1][4][4] = {};
            mtileM<8,16,1>(&q16[32 + g][2*t], 136, owf, ng, lane, acc);
            int r0 = 32 + g, r1 = r0 + 8;
            #pragma unroll
            for (int j = 0; j < 4; ++j) {
                int nc = ng*32 + j*8 + 2*t;
                float b0 = ob[nc], b1 = ob[nc+1];
                if (r0 < 34) {
                    __half q0h = __float2half_rn(acc[0][j][0] + b0 + h32[r0][nc]);
                    __half q1h = __float2half_rn(acc[0][j][1] + b1 + h32[r0][nc+1]);
                    *(__half2*)&t2g[r0*128+nc] = __halves2half2(q0h, q1h);
                    h32[r0][nc] = __half2float(q0h); h32[r0][nc+1] = __half2float(q1h);
                }
                if (r1 < 34) {
                    __half q0h = __float2half_rn(acc[0][j][2] + b0 + h32[r1][nc]);
                    __half q1h = __float2half_rn(acc[0][j][3] + b1 + h32[r1][nc+1]);
                    *(__half2*)&t2g[r1*128+nc] = __halves2half2(q0h, q1h);
                    h32[r1][nc] = __half2float(q0h); h32[r1][nc+1] = __half2float(q1h);
                }
            }
        }
    }
    __syncthreads();
    {
        float s2 = 0.f, q2 = 0.f;
        for (int i = tid; i < 4352; i += 256) {
            float v = h32[i >> 7][colj];
            s2 += v; q2 = fmaf(v, v, q2);
        }
        mbuf[tid] = s2; mbuf[256 + tid] = q2;
        __syncthreads();
        if (tid < 128) {
            atomicAdd(&accL[256 + tid], mbuf[tid] + mbuf[tid + 128]);
            atomicAdd(&accL[384 + tid], mbuf[256 + tid] + mbuf[384 + tid]);
        }
    }
}

// 4 graphs (68 rows) per block, 2 CTAs/SM
#define P_O16 0
#define P_U16 21760
#define P_O32 64000
#define P_GB  99904
#define SM2   101952

__global__ __launch_bounds__(256, 2)
void k2_s1(const __half* __restrict__ hg0, const float* __restrict__ gcnb,
           const __half* __restrict__ t2,
           const float* __restrict__ accIn, const float* __restrict__ gIn,
           const float* __restrict__ bIn, float invNIn,
           const float* __restrict__ accL, const float* __restrict__ bngL,
           const float* __restrict__ bnbL, float invNC,
           __half* __restrict__ hout, float* __restrict__ accO,
           const uint2* __restrict__ w1f, const float* __restrict__ b1v,
           const uint2* __restrict__ w2f, const float* __restrict__ b2v,
           const float* __restrict__ poses, const float* __restrict__ ew,
           const float* __restrict__ eb, float* __restrict__ pool_out) {
    extern __shared__ char sm[];
    __half (*o16)[136] = (__half(*)[136])(sm + P_O16);
    __half (*u16)[264] = (__half(*)[264])(sm + P_U16);
    float  (*o32)[132] = (float(*)[132]) (sm + P_O32);
    float*  gbuf       = (float*)(sm + P_GB);
    const int tid = threadIdx.x, warp = tid >> 5, lane = tid & 31;
    const int g = lane >> 2, t = lane & 3;
    const int colj = tid & 127;
    const int col0 = (2 * tid) & 127;
    const __half* hgA = hg0 + (size_t)blockIdx.x * 8704;
    const __half* t2g = t2 + (size_t)blockIdx.x * 8704;
    __half* og = hout + (size_t)blockIdx.x * 8704;
    float2 f1a = mkfold(accL, invNC, bngL, bnbL, col0);
    float2 f1b = mkfold(accL, invNC, bngL, bnbL, col0 + 1);
    float2 f2a = mkfold(accL + 256, invNC, bngL + 128, bnbL + 128, col0);
    float2 f2b = mkfold(accL + 256, invNC, bngL + 128, bnbL + 128, col0 + 1);

    for (int j = tid; j < 512; j += 256)
        gbuf[j] = gcnb[(size_t)blockIdx.x * 512 + j];
    {
        uint4 zz = make_uint4(0,0,0,0);
        uint4* z = (uint4*)&o16[68][0];
        for (int i = tid; i < 204; i += 256) z[i] = zz;
    }
    __syncthreads();
    const __half2* t2g2 = (const __half2*)t2g;
    if (poses) { // layer 0: recompute embed (2 cols/thread)
        float ewx0 = ew[2*col0], ewy0 = ew[2*col0+1], eb0 = eb[col0];
        float ewx1 = ew[2*col0+2], ewy1 = ew[2*col0+3], eb1 = eb[col0+1];
        const float2* pz2 = (const float2*)poses;
        for (int i2 = tid; i2 < 4352; i2 += 256) {
            int rr = i2 >> 6;
            float2 p = pz2[blockIdx.x * 68 + rr];
            float h0 = fmaf(p.x, ewx0, fmaf(p.y, ewy0, eb0));
            float h1 = fmaf(p.x, ewx1, fmaf(p.y, ewy1, eb1));
            h0 = h0 > 0.f ? h0 : 0.01f * h0;
            h1 = h1 > 0.f ? h1 : 0.01f * h1;
            float gc = gbuf[(rr/17)*128 + col0], gc1 = gbuf[(rr/17)*128 + col0 + 1];
            float2 tv = __half22float2(t2g2[i2]);
            float o0 = fmaf(gc + h0, f1a.x, f1a.y) + fmaf(tv.x, f2a.x, f2a.y);
            float o1 = fmaf(gc1 + h1, f1b.x, f1b.y) + fmaf(tv.y, f2b.x, f2b.y);
            o32[rr][col0] = o0; o32[rr][col0+1] = o1;
            *(__half2*)&o16[rr][col0] = __floats2half2_rn(o0, o1);
        }
    } else {
        float2 fia = mkfold(accIn, invNIn, gIn, bIn, col0);
        float2 fib = mkfold(accIn, invNIn, gIn, bIn, col0 + 1);
        const __half2* hg2 = (const __half2*)hgA;
        for (int i2 = tid; i2 < 4352; i2 += 256) {
            int rr = i2 >> 6;
            float2 hv = __half22float2(hg2[i2]);
            float gc = gbuf[(rr/17)*128 + col0], gc1 = gbuf[(rr/17)*128 + col0 + 1];
            float t10 = gc + fmaf(hv.x, fia.x, fia.y);
            float t11 = gc1 + fmaf(hv.y, fib.x, fib.y);
            float2 tv = __half22float2(t2g2[i2]);
            float o0 = fmaf(t10, f1a.x, f1a.y) + fmaf(tv.x, f2a.x, f2a.y);
            float o1 = fmaf(t11, f1b.x, f1b.y) + fmaf(tv.y, f2b.x, f2b.y);
            o32[rr][col0] = o0; o32[rr][col0+1] = o1;
            *(__half2*)&o16[rr][col0] = __floats2half2_rn(o0, o1);
        }
    }
    __syncthreads();
    // mlp1: M=80 (chunks 3+2), N=256, K=128
    for (int item = warp; item < 16; item += 8) {
        int ch = item >> 3, ng = item & 7;
        if (ch == 0) {
            float acc[3][4][4] = {};
            mtileM<8,32,3>(&o16[g][2*t], 136, w1f, ng, lane, acc);
            #pragma unroll
            for (int mt = 0; mt < 3; ++mt) {
                int r0 = mt*16 + g, r1 = r0 + 8;
                #pragma unroll
                for (int j = 0; j < 4; ++j) {
                    int nc = ng*32 + j*8 + 2*t;
                    float b0 = b1v[nc], b1 = b1v[nc+1];
                    *(__half2*)&u16[r0][nc] = __floats2half2_rn(fmaxf(acc[mt][j][0]+b0, 0.f), fmaxf(acc[mt][j][1]+b1, 0.f));
                    *(__half2*)&u16[r1][nc] = __floats2half2_rn(fmaxf(acc[mt][j][2]+b0, 0.f), fmaxf(acc[mt][j][3]+b1, 0.f));
                }
            }
        } else {
            float acc[2][4][4] = {};
            mtileM<8,32,2>(&o16[48 + g][2*t], 136, w1f, ng, lane, acc);
            #pragma unroll
            for (int mt = 0; mt < 2; ++mt) {
                int r0 = 48 + mt*16 + g, r1 = r0 + 8;
                #pragma unroll
                for (int j = 0; j < 4; ++j) {
                    int nc = ng*32 + j*8 + 2*t;
                    float b0 = b1v[nc], b1 = b1v[nc+1];
                    *(__half2*)&u16[r0][nc] = __floats2half2_rn(fmaxf(acc[mt][j][0]+b0, 0.f), fmaxf(acc[mt][j][1]+b1, 0.f));
                    *(__half2*)&u16[r1][nc] = __floats2half2_rn(fmaxf(acc[mt][j][2]+b0, 0.f), fmaxf(acc[mt][j][3]+b1, 0.f));
                }
            }
        }
    }
    __syncthreads();
    // mlp2: M=80 (chunks 3+2), N=128, K=256 + residual -> og (fp16) AND o32
    for (int item = warp; item < 8; item += 8) {
        int ch = item >> 2, ng = item & 3;
        if (ch == 0) {
            float acc[3][4][4] = {};
            mtileM<16,16,3>(&u16[g][2*t], 264, w2f, ng, lane, acc);
            #pragma unroll
            for (int mt = 0; mt < 3; ++mt) {
                int r0 = mt*16 + g, r1 = r0 + 8;
                #pragma unroll
                for (int j = 0; j < 4; ++j) {
                    int nc = ng*32 + j*8 + 2*t;
                    float b0 = b2v[nc], b1 = b2v[nc+1];
                    {
                        __half q0h = __float2half_rn(acc[mt][j][0] + b0 + o32[r0][nc]);
                        __half q1h = __float2half_rn(acc[mt][j][1] + b1 + o32[r0][nc+1]);
                        *(__half2*)&og[r0*128+nc] = __halves2half2(q0h, q1h);
                        o32[r0][nc] = __half2float(q0h); o32[r0][nc+1] = __half2float(q1h);
                    }
                    {
                        __half q0h = __float2half_rn(acc[mt][j][2] + b0 + o32[r1][nc]);
                        __half q1h = __float2half_rn(acc[mt][j][3] + b1 + o32[r1][nc+1]);
                        *(__half2*)&og[r1*128+nc] = __halves2half2(q0h, q1h);
                        o32[r1][nc] = __half2float(q0h); o32[r1][nc+1] = __half2float(q1h);
                    }
                }
            }
        } else {
            float acc[2][4][4] = {};
            mtileM<16,16,2>(&u16[48 + g][2*t], 264, w2f, ng, lane, acc);
            #pragma unroll
            for (int mt = 0; mt < 2; ++mt) {
                int r0 = 48 + mt*16 + g, r1 = r0 + 8;
                #pragma unroll
                for (int j = 0; j < 4; ++j) {
                    int nc = ng*32 + j*8 + 2*t;
                    float b0 = b2v[nc], b1 = b2v[nc+1];
                    if (r0 < 68) {
                        __half q0h = __float2half_rn(acc[mt][j][0] + b0 + o32[r0][nc]);
                        __half q1h = __float2half_rn(acc[mt][j][1] + b1 + o32[r0][nc+1]);
                        *(__half2*)&og[r0*128+nc] = __halves2half2(q0h, q1h);
                        o32[r0][nc] = __half2float(q0h); o32[r0][nc+1] = __half2float(q1h);
                    }
                    if (r1 < 68) {
                        __half q0h = __float2half_rn(acc[mt][j][2] + b0 + o32[r1][nc]);
                        __half q1h = __float2half_rn(acc[mt][j][3] + b1 + o32[r1][nc+1]);
                        *(__half2*)&og[r1*128+nc] = __halves2half2(q0h, q1h);
                        o32[r1][nc] = __half2float(q0h); o32[r1][nc+1] = __half2float(q1h);
                    }
                }
            }
        }
    }
    __syncthreads();
    if (pool_out) {
        for (int j = tid; j < 512; j += 256) {
            int gi = j >> 7, cc = j & 127;
            float s = 0.f;
            #pragma unroll
            for (int r = 0; r < 17; ++r) s += o32[gi*17 + r][cc];
            pool_out[(size_t)blockIdx.x * 512 + j] = s * (1.f / 17.f);
        }
    }
    {
        float s3 = 0.f, q3 = 0.f;
        for (int i = tid; i < 8704; i += 256) {
            float v = o32[i >> 7][colj];
            s3 += v; q3 = fmaf(v, v, q3);
        }
        float* red = (float*)u16;
        red[tid] = s3; red[256 + tid] = q3;
        __syncthreads();
        if (tid < 128) {
            atomicAdd((float*)&accO[tid],       red[tid] + red[tid + 128]);
            atomicAdd((float*)&accO[128 + tid], red[256 + tid] + red[384 + tid]);
        }
    }
}

// ========== stage-2 tensor kernels: 4 graphs x 12 nodes = 48 rows ==========
#define B_H16 0
#define B_Q16 13056
#define B_K16 27200
#define B_VT  41344
#define B_P   57728
#define B_SC  65920
#define B_MB  78976
#define B_H32 83072
#define SM1B  108416

__global__ __launch_bounds__(256, 2)
void k1_s2(const float* __restrict__ hin,
           const float* __restrict__ accIn, const float* __restrict__ gIn,
           const float* __restrict__ bIn, float invNIn,
           float* __restrict__ gcnb, __half* __restrict__ t2, float* __restrict__ accL,
           const float* __restrict__ gwT, const float* __restrict__ gb,
           const float* __restrict__ qb, const float* __restrict__ ob,
           const uint2* __restrict__ qkvf, const uint2* __restrict__ owf) {
    extern __shared__ char sm[];
    __half (*h16)[136] = (__half(*)[136])(sm + B_H16);
    __half (*q16)[136] = (__half(*)[136])(sm + B_Q16);
    __half (*k16)[136] = (__half(*)[136])(sm + B_K16);
    __half (*vT )[16]  = (__half(*)[16]) (sm + B_VT);
    __half (*pp )[16]  = (__half(*)[16]) (sm + B_P);
    float  (*sc )[17]  = (float(*)[17])  (sm + B_SC);
    float*  mbuf       = (float*)(sm + B_MB);
    float  (*h32)[132] = (float(*)[132]) (sm + B_H32);

    const int tid = threadIdx.x, warp = tid >> 5, lane = tid & 31;
    const int g = lane >> 2, t = lane & 3;
    const int colj = tid & 127;
    const float* hg = hin + (size_t)blockIdx.x * 6144;
    __half* t2g = t2 + (size_t)blockIdx.x * 6144;

    {
        uint4 zz = make_uint4(0,0,0,0);
        uint4* z = (uint4*)(sm + B_VT);
        for (int i = tid; i < 1536; i += 256) z[i] = zz;
        uint4* zq = (uint4*)&q16[48][0];
        for (int i = tid; i < 68; i += 256) zq[i] = zz;
        uint4* zk = (uint4*)&k16[48][0];
        for (int i = tid; i < 68; i += 256) zk[i] = zz;
        float2 f = mkfold(accIn, invNIn, gIn, bIn, colj);
        for (int i = tid; i < 6144; i += 256) {
            int rr = i >> 7;
            float v = fmaf(hg[i], f.x, f.y);
            h32[rr][colj] = v;
            h16[rr][colj] = __float2half_rn(v);
        }
    }
    __syncthreads();
    {
        float* scr = (float*)sc;
        for (int j = tid; j < 512; j += 256) {
            int gi = j >> 7, cc = j & 127;
            float s = 0.f, q = 0.f;
            #pragma unroll
            for (int r = 0; r < 12; ++r) {
                float v = h32[gi*12 + r][cc];
                s += v; q = fmaf(v, v, q);
            }
            mbuf[j] = s * (1.f / 12.f);
            scr[j] = q; scr[512 + j] = s;
        }
    }
    __syncthreads();
    {
        float* scr = (float*)sc;
        for (int j = tid; j < 512; j += 256) {
            int gi = j >> 7, cc = j & 127;
            float a = gb[cc];
            const float* mrow = mbuf + gi * 128;
            #pragma unroll 4
            for (int k = 0; k < 128; ++k) a = fmaf(mrow[k], gwT[k*128 + cc], a);
            gcnb[(size_t)blockIdx.x * 512 + j] = a;
            float Sh = scr[512 + j], Sq = scr[j];
            scr[512 + j] = fmaf(12.f, a, Sh);
            scr[j] = fmaf(12.f * a, a, fmaf(2.f * a, Sh, Sq));
        }
    }
    __syncthreads();
    if (tid < 128) {
        float* scr = (float*)sc;
        atomicAdd(&accL[tid],       scr[512+tid] + scr[640+tid] + scr[768+tid] + scr[896+tid]);
        atomicAdd(&accL[128 + tid], scr[tid] + scr[128+tid] + scr[256+tid] + scr[384+tid]);
    }
    // qkv: M=48, MT=3
    for (int item = warp; item < 12; item += 8) {
        int ng = item;
        float acc[3][4][4] = {};
        mtileM<8,48,3>(&h16[g][2*t], 136, qkvf, ng, lane, acc);
        #pragma unroll
        for (int mt = 0; mt < 3; ++mt) {
            int r0 = mt*16 + g, r1 = r0 + 8;
            #pragma unroll
            for (int j = 0; j < 4; ++j) {
                int nc = ng*32 + j*8 + 2*t;
                float b0 = qb[nc], b1 = qb[nc+1];
                float v00 = acc[mt][j][0]+b0, v01 = acc[mt][j][1]+b1;
                float v10 = acc[mt][j][2]+b0, v11 = acc[mt][j][3]+b1;
                if (nc < 128) {
                    *(__half2*)&q16[r0][nc] = __floats2half2_rn(v00, v01);
                    *(__half2*)&q16[r1][nc] = __floats2half2_rn(v10, v11);
                } else if (nc < 256) {
                    *(__half2*)&k16[r0][nc-128] = __floats2half2_rn(v00, v01);
                    *(__half2*)&k16[r1][nc-128] = __floats2half2_rn(v10, v11);
                } else {
                    int d = nc - 256;
                    { int gi = r0/12, sl = r0 - gi*12;
                      vT[gi*128+d][sl] = __float2half_rn(v00); vT[gi*128+d+1][sl] = __float2half_rn(v01); }
                    { int gi = r1/12, sl = r1 - gi*12;
                      vT[gi*128+d][sl] = __float2half_rn(v10); vT[gi*128+d+1][sl] = __float2half_rn(v11); }
                }
            }
        }
    }
    __syncthreads();
    for (int item = warp; item < 32; item += 8) {
        int gi = item / 8, r = item % 8, hh = r / 2, nt = r % 2;
        int base = gi * 12;
        float acc[4] = {};
        const __half* a0p = &q16[base + g][hh*32 + 2*t];
        const __half* a1p = a0p + 8*136;
        const __half* br  = &k16[base + nt*8 + g][hh*32 + 2*t];
        #pragma unroll
        for (int kt = 0; kt < 2; ++kt) {
            mma16816(acc, *(const uint32_t*)(a0p+kt*16), *(const uint32_t*)(a1p+kt*16),
                     *(const uint32_t*)(a0p+kt*16+8), *(const uint32_t*)(a1p+kt*16+8),
                     *(const uint32_t*)(br+kt*16), *(const uint32_t*)(br+kt*16+8));
        }
        const float invs = 0.17677669529663687f;
        int ss = nt*8 + 2*t, row = (gi*4 + hh)*12;
        { sc[row+g][ss] = acc[0]*invs; sc[row+g][ss+1] = acc[1]*invs; }
        if (g + 8 < 12) { sc[row+g+8][ss] = acc[2]*invs; sc[row+g+8][ss+1] = acc[3]*invs; }
    }
    __syncthreads();
    if (tid < 192) {
        int gh = tid / 12, q = tid - gh*12;
        float e[12], mx = -1e30f;
        #pragma unroll
        for (int s = 0; s < 12; ++s) mx = fmaxf(mx, sc[gh*12+q][s]);
        float sum = 0.f;
        #pragma unroll
        for (int s = 0; s < 12; ++s) { e[s] = __expf(sc[gh*12+q][s] - mx); sum += e[s]; }
        float inv = 1.f / sum;
        #pragma unroll
        for (int s = 0; s < 12; ++s) pp[gh*16 + q][s] = __float2half_rn(e[s] * inv);
    }
    __syncthreads();
    for (int item = warp; item < 16; item += 8) {
        int gi = item / 4, hh = item % 4;
        float acc[4][4] = {};
        const __half* a0p = &pp[(gi*4+hh)*16 + g][2*t];
        const __half* a1p = a0p + 8*16;
        uint32_t a0 = *(const uint32_t*)a0p,       a1 = *(const uint32_t*)a1p;
        uint32_t a2 = *(const uint32_t*)(a0p + 8), a3 = *(const uint32_t*)(a1p + 8);
        #pragma unroll
        for (int j = 0; j < 4; ++j) {
            const __half* bp = &vT[gi*128 + hh*32 + j*8 + g][2*t];
            mma16816(acc[j], a0, a1, a2, a3, *(const uint32_t*)bp, *(const uint32_t*)(bp+8));
        }
        #pragma unroll
        for (int j = 0; j < 4; ++j) {
            int col = hh*32 + j*8 + 2*t;
            *(__half2*)&q16[gi*12+g][col] = __floats2half2_rn(acc[j][0], acc[j][1]);
            if (g + 8 < 12) *(__half2*)&q16[gi*12+g+8][col] = __floats2half2_rn(acc[j][2], acc[j][3]);
        }
    }
    __syncthreads();
    // out-proj: M=48 (chunks 2+1)
    for (int item = warp; item < 8; item += 8) {
        int ch = item >> 2, ng = item & 3;
        if (ch == 0) {
            float acc[2][4][4] = {};
            mtileM<8,16,2>(&q16[g][2*t], 136, owf, ng, lane, acc);
            #pragma unroll
            for (int mt = 0; mt < 2; ++mt) {
                int r0 = mt*16 + g, r1 = r0 + 8;
                #pragma unroll
                for (int j = 0; j < 4; ++j) {
                    int nc = ng*32 + j*8 + 2*t;
                    float b0 = ob[nc], b1 = ob[nc+1];
                    {
                        __half q0h = __float2half_rn(acc[mt][j][0] + b0 + h32[r0][nc]);
                        __half q1h = __float2half_rn(acc[mt][j][1] + b1 + h32[r0][nc+1]);
                        *(__half2*)&t2g[r0*128+nc] = __halves2half2(q0h, q1h);
                        h32[r0][nc] = __half2float(q0h); h32[r0][nc+1] = __half2float(q1h);
                    }
                    {
                        __half q0h = __float2half_rn(acc[mt][j][2] + b0 + h32[r1][nc]);
                        __half q1h = __float2half_rn(acc[mt][j][3] + b1 + h32[r1][nc+1]);
                        *(__half2*)&t2g[r1*128+nc] = __halves2half2(q0h, q1h);
                        h32[r1][nc] = __half2float(q0h); h32[r1][nc+1] = __half2float(q1h);
                    }
                }
            }
        } else {
            float acc[1][4][4] = {};
            mtileM<8,16,1>(&q16[32 + g][2*t], 136, owf, ng, lane, acc);
            int r0 = 32 + g, r1 = r0 + 8;
            #pragma unroll
            for (int j = 0; j < 4; ++j) {
                int nc = ng*32 + j*8 + 2*t;
                float b0 = ob[nc], b1 = ob[nc+1];
                {
                    __half q0h = __float2half_rn(acc[0][j][0] + b0 + h32[r0][nc]);
                    __half q1h = __float2half_rn(acc[0][j][1] + b1 + h32[r0][nc+1]);
                    *(__half2*)&t2g[r0*128+nc] = __halves2half2(q0h, q1h);
                    h32[r0][nc] = __half2float(q0h); h32[r0][nc+1] = __half2float(q1h);
                }
                {
                    __half q0h = __float2half_rn(acc[0][j][2] + b0 + h32[r1][nc]);
                    __half q1h = __float2half_rn(acc[0][j][3] + b1 + h32[r1][nc+1]);
                    *(__half2*)&t2g[r1*128+nc] = __halves2half2(q0h, q1h);
                    h32[r1][nc] = __half2float(q0h); h32[r1][nc+1] = __half2float(q1h);
                }
            }
        }
    }
    __syncthreads();
    {
        float s2 = 0.f, q2 = 0.f;
        for (int i = tid; i < 6144; i += 256) {
            float v = h32[i >> 7][colj];
            s2 += v; q2 = fmaf(v, v, q2);
        }
        mbuf[tid] = s2; mbuf[256 + tid] = q2;
        __syncthreads();
        if (tid < 128) {
            atomicAdd(&accL[256 + tid], mbuf[tid] + mbuf[tid + 128]);
            atomicAdd(&accL[384 + tid], mbuf[256 + tid] + mbuf[384 + tid]);
        }
    }
}

#define C_O16 0
#define C_U16 13056
#define C_O32 38400
#define C_GB  63744
#define SM2B  65792

__global__ __launch_bounds__(256, 2)
void k2_s2(const float* __restrict__ hg0, const float* __restrict__ gcnb,
           const __half* __restrict__ t2,
           const float* __restrict__ accIn, const float* __restrict__ gIn,
           const float* __restrict__ bIn, float invNIn,
           const float* __restrict__ accL, const float* __restrict__ bngL,
           const float* __restrict__ bnbL, float invNC,
           float* __restrict__ hout, float* __restrict__ accO,
           const uint2* __restrict__ w1f, const float* __restrict__ b1v,
           const uint2* __restrict__ w2f, const float* __restrict__ b2v) {
    extern __shared__ char sm[];
    __half (*o16)[136] = (__half(*)[136])(sm + C_O16);
    __half (*u16)[264] = (__half(*)[264])(sm + C_U16);
    float  (*o32)[132] = (float(*)[132]) (sm + C_O32);
    float*  gbuf       = (float*)(sm + C_GB);
    const int tid = threadIdx.x, warp = tid >> 5, lane = tid & 31;
    const int g = lane >> 2, t = lane & 3;
    const int colj = tid & 127;
    const float* hgA = hg0 + (size_t)blockIdx.x * 6144;
    const __half* t2g = t2 + (size_t)blockIdx.x * 6144;
    float* og = hout + (size_t)blockIdx.x * 6144;
    float2 fi = mkfold(accIn, invNIn, gIn, bIn, colj);
    float2 f1 = mkfold(accL, invNC, bngL, bnbL, colj);
    float2 f2 = mkfold(accL + 256, invNC, bngL + 128, bnbL + 128, colj);

    if (tid < 256) gbuf[tid] = gcnb[(size_t)blockIdx.x * 512 + tid];
    if (tid < 256) gbuf[256 + tid] = gcnb[(size_t)blockIdx.x * 512 + 256 + tid];
    __syncthreads();
    for (int i = tid; i < 6144; i += 256) {
        int rr = i >> 7;
        float t1v = gbuf[(rr/12)*128 + colj] + fmaf(hgA[i], fi.x, fi.y);
        float o = fmaf(t1v, f1.x, f1.y) + fmaf(__half2float(t2g[i]), f2.x, f2.y);
        o32[rr][colj] = o;
        o16[rr][colj] = __float2half_rn(o);
    }
    __syncthreads();
    // mlp1: M=48, MT=3, 8 items
    for (int item = warp; item < 8; item += 8) {
        int ng = item;
        float acc[3][4][4] = {};
        mtileM<8,32,3>(&o16[g][2*t], 136, w1f, ng, lane, acc);
        #pragma unroll
        for (int mt = 0; mt < 3; ++mt) {
            int r0 = mt*16 + g, r1 = r0 + 8;
            #pragma unroll
            for (int j = 0; j < 4; ++j) {
                int nc = ng*32 + j*8 + 2*t;
                float b0 = b1v[nc], b1 = b1v[nc+1];
                *(__half2*)&u16[r0][nc] = __floats2half2_rn(fmaxf(acc[mt][j][0]+b0, 0.f), fmaxf(acc[mt][j][1]+b1, 0.f));
                *(__half2*)&u16[r1][nc] = __floats2half2_rn(fmaxf(acc[mt][j][2]+b0, 0.f), fmaxf(acc[mt][j][3]+b1, 0.f));
            }
        }
    }
    __syncthreads();
    // mlp2: M=48 (chunks 2+1), K=256
    for (int item = warp; item < 8; item += 8) {
        int ch = item >> 2, ng = item & 3;
        if (ch == 0) {
            float acc[2][4][4] = {};
            mtileM<16,16,2>(&u16[g][2*t], 264, w2f, ng, lane, acc);
            #pragma unroll
            for (int mt = 0; mt < 2; ++mt) {
                int r0 = mt*16 + g, r1 = r0 + 8;
                #pragma unroll
                for (int j = 0; j < 4; ++j) {
                    int nc = ng*32 + j*8 + 2*t;
                    float b0 = b2v[nc], b1 = b2v[nc+1];
                    {
                        float v0 = acc[mt][j][0] + b0 + o32[r0][nc];
                        float v1 = acc[mt][j][1] + b1 + o32[r0][nc+1];
                        og[r0*128+nc] = v0; og[r0*128+nc+1] = v1;
                        o32[r0][nc] = v0; o32[r0][nc+1] = v1;
                    }
                    {
                        float v0 = acc[mt][j][2] + b0 + o32[r1][nc];
                        float v1 = acc[mt][j][3] + b1 + o32[r1][nc+1];
                        og[r1*128+nc] = v0; og[r1*128+nc+1] = v1;
                        o32[r1][nc] = v0; o32[r1][nc+1] = v1;
                    }
                }
            }
        } else {
            float acc[1][4][4] = {};
            mtileM<16,16,1>(&u16[32 + g][2*t], 264, w2f, ng, lane, acc);
            int r0 = 32 + g, r1 = r0 + 8;
            #pragma unroll
            for (int j = 0; j < 4; ++j) {
                int nc = ng*32 + j*8 + 2*t;
                float b0 = b2v[nc], b1 = b2v[nc+1];
                {
                    float v0 = acc[0][j][0] + b0 + o32[r0][nc];
                    float v1 = acc[0][j][1] + b1 + o32[r0][nc+1];
                    og[r0*128+nc] = v0; og[r0*128+nc+1] = v1;
                    o32[r0][nc] = v0; o32[r0][nc+1] = v1;
                }
                {
                    float v0 = acc[0][j][2] + b0 + o32[r1][nc];
                    float v1 = acc[0][j][3] + b1 + o32[r1][nc+1];
                    og[r1*128+nc] = v0; og[r1*128+nc+1] = v1;
                    o32[r1][nc] = v0; o32[r1][nc+1] = v1;
                }
            }
        }
    }
    __syncthreads();
    {
        float s3 = 0.f, q3 = 0.f;
        for (int i = tid; i < 6144; i += 256) {
            float v = o32[i >> 7][colj];
            s3 += v; q3 = fmaf(v, v, q3);
        }
        float* red = (float*)u16;
        red[tid] = s3; red[256 + tid] = q3;
        __syncthreads();
        if (tid < 128) {
            atomicAdd((float*)&accO[tid],       red[tid] + red[tid + 128]);
            atomicAdd((float*)&accO[128 + tid], red[256 + tid] + red[384 + tid]);
        }
    }
}

extern "C" void kernel_launch(void* const* d_in, const int* in_sizes, int n_in,
                              void* d_out, int out_size) {
    const float* poses = (const float*)d_in[0];
    const float* emb_w = (const float*)d_in[1];
    const float* emb_b = (const float*)d_in[2];
    const float* cls_w = (const float*)d_in[3];
    const float* cls_b = (const float*)d_in[4];
    const float* PPj[12]; const float* PPi[12];
    for (int i = 0; i < 12; ++i) { PPj[i] = (const float*)d_in[5+i]; PPi[i] = (const float*)d_in[17+i]; }

    float *A, *Bb, *Cc, *A2, *B2, *C2, *acc, *wT; uint2* wf;
    cudaGetSymbolAddress((void**)&A,    g_A);
    cudaGetSymbolAddress((void**)&Bb,   g_B);
    cudaGetSymbolAddress((void**)&Cc,   g_C);
    cudaGetSymbolAddress((void**)&A2,   g_A2);
    cudaGetSymbolAddress((void**)&B2,   g_B2);
    cudaGetSymbolAddress((void**)&C2,   g_C2);
    cudaGetSymbolAddress((void**)&acc,  g_acc);
    cudaGetSymbolAddress((void**)&wT,   g_wT);
    cudaGetSymbolAddress((void**)&wf,   g_wf);
    uint2* wf2 = wf + 98304;
    __half* Ah  = (__half*)A;
    __half* Ch  = (__half*)Cc;
    __half* C2h = (__half*)C2;
    const float inv1 = 1.f / 365568.f, inv2 = 1.f / 21504.f;

    cudaFuncSetAttribute(k1_s1, cudaFuncAttributeMaxDynamicSharedMemorySize, SM1);
    cudaFuncSetAttribute(k2_s1, cudaFuncAttributeMaxDynamicSharedMemorySize, SM2);
    cudaFuncSetAttribute(k1_s2, cudaFuncAttributeMaxDynamicSharedMemorySize, SM1B);
    cudaFuncSetAttribute(k2_s2, cudaFuncAttributeMaxDynamicSharedMemorySize, SM2B);

    init_kernel<<<18, 256>>>(acc);

    transpose_kernel<<<192, 256>>>(PPj[0], wT, 128, 128, 49152);
    transpose_kernel<<<192, 256>>>(PPi[0], wT + 49152, 128, 128, 49152);
    for (int l = 0; l < 3; ++l) {
        prep_frag<<<48, 256>>>(PPj[2]  + l*49152, wf + l*32768,          48, 128, 12288);
        prep_frag<<<16, 256>>>(PPj[4]  + l*16384, wf + l*32768 + 12288,  16, 128, 4096);
        prep_frag<<<32, 256>>>(PPj[8]  + l*32768, wf + l*32768 + 16384,  32, 128, 8192);
        prep_frag<<<32, 256>>>(PPj[10] + l*32768, wf + l*32768 + 24576,  16, 256, 8192);
        prep_frag<<<48, 256>>>(PPi[2]  + l*49152, wf2 + l*32768,         48, 128, 12288);
        prep_frag<<<16, 256>>>(PPi[4]  + l*16384, wf2 + l*32768 + 12288, 16, 128, 4096);
        prep_frag<<<32, 256>>>(PPi[8]  + l*32768, wf2 + l*32768 + 16384, 32, 128, 8192);
        prep_frag<<<32, 256>>>(PPi[10] + l*32768, wf2 + l*32768 + 24576, 16, 256, 8192);
    }

    // stage 1 (A/t2 fp16; folds inline; embed fused l0; pool fused l2)
    const float* accPrev = nullptr;
    const float* gPrev = nullptr;
    const float* bPrev = nullptr;
    for (int l = 0; l < 3; ++l) {
        float* accL = acc + l * 768;
        const float* pz = (l == 0) ? poses : nullptr;
        k1_s1<<<10752, 256, SM1>>>(Ah, accPrev, gPrev, bPrev, inv1,
                                   Bb, Ch, accL,
                                   wT + l*16384, PPj[1] + l*128, PPj[3] + l*384, PPj[5] + l*128,
                                   wf + l*32768, wf + l*32768 + 12288,
                                   pz, emb_w, emb_b);
        k2_s1<<<5376, 256, SM2>>>(Ah, Bb, Ch, accPrev, gPrev, bPrev, inv1,
                                  accL, PPj[6] + l*384, PPj[7] + l*384, inv1,
                                  Ah, accL + 512,
                                  wf + l*32768 + 16384, PPj[9] + l*256,
                                  wf + l*32768 + 24576, PPj[11] + l*128,
                                  pz, emb_w, emb_b, (l == 2) ? A2 : nullptr);
        accPrev = accL + 512;
        gPrev = PPj[6] + l*384 + 256;
        bPrev = PPj[7] + l*384 + 256;
    }

    // stage 2 (A2 fp32)
    float invNIn = inv1;
    for (int l = 0; l < 3; ++l) {
        float* accL = acc + 2304 + l * 768;
        k1_s2<<<448, 256, SM1B>>>(A2, accPrev, gPrev, bPrev, invNIn,
                                  B2, C2h, accL,
                                  wT + 49152 + l*16384, PPi[1] + l*128, PPi[3] + l*384, PPi[5] + l*128,
                                  wf2 + l*32768, wf2 + l*32768 + 12288);
        k2_s2<<<448, 256, SM2B>>>(A2, B2, C2h, accPrev, gPrev, bPrev, invNIn,
                                  accL, PPi[6] + l*384, PPi[7] + l*384, inv2,
                                  A2, accL + 512,
                                  wf2 + l*32768 + 16384, PPi[9] + l*256,
                                  wf2 + l*32768 + 24576, PPi[11] + l*128);
        accPrev = accL + 512;
        gPrev = PPi[6] + l*384 + 256;
        bPrev = PPi[7] + l*384 + 256;
        invNIn = inv2;
    }

    pool2_cls_kernel<<<256, 128>>>(A2, accPrev, gPrev, bPrev, inv2,
                                   cls_w, cls_b, (float*)d_out);
}